// round 1
// baseline (speedup 1.0000x reference)
#include <cuda_runtime.h>

// Problem constants
#define Bb   4
#define Tt   2048
#define Cc   512
#define Hh   8
#define Dd   64
#define CDRH 2

#define NEG_INF __int_as_float(0xff800000)

// Scratch (allocation-free: module-static device globals)
__device__ float g_q[Bb * Tt * Cc];
__device__ float g_k[Bb * Tt * Cc];
__device__ float g_v[Bb * Tt * Cc];
__device__ float g_ctx[Bb * Tt * Cc];
__device__ int   g_allm[Bb];

// ---------------------------------------------------------------------------
// Per-batch "all CDR tokens masked" flag: g_allm[b] = 1 iff all cdrs[b,:]==0
// ---------------------------------------------------------------------------
__global__ void allm_kernel(const int* __restrict__ cdrs) {
    __shared__ int any;
    int b = blockIdx.x;
    if (threadIdx.x == 0) any = 0;
    __syncthreads();
    int local = 0;
    for (int t = threadIdx.x; t < Tt; t += blockDim.x)
        local |= (cdrs[b * Tt + t] != 0);
    if (local) any = 1;   // benign race, all writers store 1
    __syncthreads();
    if (threadIdx.x == 0) g_allm[b] = (any == 0) ? 1 : 0;
}

// ---------------------------------------------------------------------------
// Generic tiled GEMM: out[M=8192, N=512] = A[8192, 512] @ W[512, 512] + bias
// BM=BN=64, BK=16, 256 threads, 4x4 register micro-tile per thread.
// ---------------------------------------------------------------------------
#define GP 68   // smem row pitch (floats): bank-safe + 16B-aligned rows

__device__ __forceinline__ void gemm_body(const float* __restrict__ A,
                                          const float* __restrict__ W,
                                          const float* __restrict__ bias,
                                          float* __restrict__ out) {
    __shared__ float As[16][GP];   // [k][m]
    __shared__ float Bs[16][GP];   // [k][n]
    const int tid = threadIdx.x;
    const int tx = tid & 15, ty = tid >> 4;
    const int m0 = blockIdx.x * 64, n0 = blockIdx.y * 64;

    const int kk_a = tid & 15, mm_a = tid >> 4;   // A loader coords
    const int nn_b = tid & 63, kk_b = tid >> 6;   // W loader coords

    float acc[4][4] = {};

    for (int k0 = 0; k0 < Cc; k0 += 16) {
#pragma unroll
        for (int p = 0; p < 4; p++)
            As[kk_a][mm_a + p * 16] = A[(m0 + mm_a + p * 16) * Cc + k0 + kk_a];
#pragma unroll
        for (int p = 0; p < 4; p++)
            Bs[kk_b + p * 4][nn_b] = W[(k0 + kk_b + p * 4) * Cc + n0 + nn_b];
        __syncthreads();

#pragma unroll
        for (int kk = 0; kk < 16; kk++) {
            float4 a4 = *(const float4*)&As[kk][ty * 4];
            float4 b4 = *(const float4*)&Bs[kk][tx * 4];
            float av[4] = {a4.x, a4.y, a4.z, a4.w};
            float bv[4] = {b4.x, b4.y, b4.z, b4.w};
#pragma unroll
            for (int i = 0; i < 4; i++)
#pragma unroll
                for (int j = 0; j < 4; j++)
                    acc[i][j] += av[i] * bv[j];
        }
        __syncthreads();
    }

    float4 bia = *(const float4*)&bias[n0 + tx * 4];
    float bv[4] = {bia.x, bia.y, bia.z, bia.w};
#pragma unroll
    for (int i = 0; i < 4; i++) {
        int m = m0 + ty * 4 + i;
        float4 o4;
        o4.x = acc[i][0] + bv[0];
        o4.y = acc[i][1] + bv[1];
        o4.z = acc[i][2] + bv[2];
        o4.w = acc[i][3] + bv[3];
        *(float4*)&out[m * Cc + n0 + tx * 4] = o4;
    }
}

// Fused Q/K/V projection: blockIdx.z selects which projection.
__global__ __launch_bounds__(256)
void gemm_qkv(const float* __restrict__ x,
              const float* __restrict__ Wq, const float* __restrict__ bq,
              const float* __restrict__ Wk, const float* __restrict__ bk,
              const float* __restrict__ Wv, const float* __restrict__ bv) {
    const float* W; const float* bi; float* out;
    if (blockIdx.z == 0)      { W = Wq; bi = bq; out = g_q; }
    else if (blockIdx.z == 1) { W = Wk; bi = bk; out = g_k; }
    else                      { W = Wv; bi = bv; out = g_v; }
    gemm_body(x, W, bi, out);
}

// Output projection: ctx @ Wo + bo
__global__ __launch_bounds__(256)
void gemm_out(const float* __restrict__ Wo, const float* __restrict__ bo,
              float* __restrict__ out) {
    gemm_body(g_ctx, Wo, bo, out);
}

// ---------------------------------------------------------------------------
// Flash-style masked attention.
// Block = (q-tile of 64, head, batch); 256 threads; online softmax.
// qs/ks/vs/ps tiles in dynamic smem (64 x 68 pitch each).
// ---------------------------------------------------------------------------
#define AP 68

__global__ __launch_bounds__(256)
void attn_kernel(const int* __restrict__ mask, const int* __restrict__ cdrs) {
    extern __shared__ float sh[];
    float* qs = sh;                 // [64][AP]
    float* ks = sh + 64 * AP;       // [64][AP]
    float* vs = sh + 2 * 64 * AP;   // [64][AP]
    float* ps = sh + 3 * 64 * AP;   // [64][AP]  scores -> probs

    __shared__ float m_sm[64], l_sm[64], al_sm[64], kneg[64];

    const int q0  = blockIdx.x * 64;
    const int h   = blockIdx.y;
    const int b   = blockIdx.z;
    const int tid = threadIdx.x;
    const int tx  = tid & 15, ty = tid >> 4;

    const bool iscdr = (h < CDRH) && (g_allm[b] == 0);

    // Load Q tile (float4 rows of 64 floats)
    const float* qbase = g_q + (b * Tt + q0) * Cc + h * Dd;
    for (int i = tid; i < 64 * 16; i += 256) {
        int r = i >> 4, c4 = i & 15;
        *(float4*)&qs[r * AP + c4 * 4] = *(const float4*)(qbase + r * Cc + c4 * 4);
    }
    if (tid < 64) { m_sm[tid] = NEG_INF; l_sm[tid] = 0.f; }

    float o[4][4] = {};   // rows q = ty*4+i, cols d = tx*4+j

    for (int kt = 0; kt < Tt / 64; kt++) {
        const int k0 = kt * 64;
        __syncthreads();   // previous tile's PV reads done before overwrite

        const float* kbase = g_k + (b * Tt + k0) * Cc + h * Dd;
        const float* vbase = g_v + (b * Tt + k0) * Cc + h * Dd;
        for (int i = tid; i < 64 * 16; i += 256) {
            int r = i >> 4, c4 = i & 15;
            *(float4*)&ks[r * AP + c4 * 4] = *(const float4*)(kbase + r * Cc + c4 * 4);
            *(float4*)&vs[r * AP + c4 * 4] = *(const float4*)(vbase + r * Cc + c4 * 4);
        }
        if (tid < 64) {
            int kg = k0 + tid;
            bool bad = (mask[b * Tt + kg] == 0) ||
                       (iscdr && (cdrs[b * Tt + kg] == 0));
            kneg[tid] = bad ? NEG_INF : 0.f;
        }
        __syncthreads();

        // S = (Q K^T) * scale + mask_bias
        float s[4][4] = {};
#pragma unroll
        for (int d4 = 0; d4 < 16; d4++) {
            float4 qv[4], kv[4];
#pragma unroll
            for (int i = 0; i < 4; i++) qv[i] = *(const float4*)&qs[(ty * 4 + i) * AP + d4 * 4];
#pragma unroll
            for (int j = 0; j < 4; j++) kv[j] = *(const float4*)&ks[(tx * 4 + j) * AP + d4 * 4];
#pragma unroll
            for (int i = 0; i < 4; i++)
#pragma unroll
                for (int j = 0; j < 4; j++)
                    s[i][j] += qv[i].x * kv[j].x + qv[i].y * kv[j].y +
                               qv[i].z * kv[j].z + qv[i].w * kv[j].w;
        }
#pragma unroll
        for (int i = 0; i < 4; i++) {
            float4 w;
            w.x = s[i][0] * 0.125f + kneg[tx * 4 + 0];
            w.y = s[i][1] * 0.125f + kneg[tx * 4 + 1];
            w.z = s[i][2] * 0.125f + kneg[tx * 4 + 2];
            w.w = s[i][3] * 0.125f + kneg[tx * 4 + 3];
            *(float4*)&ps[(ty * 4 + i) * AP + tx * 4] = w;
        }
        __syncthreads();

        // Online softmax row update (one thread per query row)
        if (tid < 64) {
            float mold = m_sm[tid];
            float mx = mold;
            float* row = &ps[tid * AP];
#pragma unroll 8
            for (int k = 0; k < 64; k++) mx = fmaxf(mx, row[k]);
            float alpha, sum = 0.f;
            if (mx == NEG_INF) {
                alpha = 1.f;
#pragma unroll 8
                for (int k = 0; k < 64; k++) row[k] = 0.f;
            } else {
                alpha = __expf(mold - mx);   // mold = -inf -> 0
#pragma unroll 8
                for (int k = 0; k < 64; k++) {
                    float p = __expf(row[k] - mx);
                    row[k] = p;
                    sum += p;
                }
            }
            m_sm[tid]  = mx;
            l_sm[tid]  = l_sm[tid] * alpha + sum;
            al_sm[tid] = alpha;
        }
        __syncthreads();

        // Rescale O, accumulate P @ V
#pragma unroll
        for (int i = 0; i < 4; i++) {
            float a = al_sm[ty * 4 + i];
#pragma unroll
            for (int j = 0; j < 4; j++) o[i][j] *= a;
        }
#pragma unroll
        for (int k4 = 0; k4 < 16; k4++) {
            float4 pv4[4], vv[4];
#pragma unroll
            for (int i = 0; i < 4; i++)  pv4[i] = *(const float4*)&ps[(ty * 4 + i) * AP + k4 * 4];
#pragma unroll
            for (int jj = 0; jj < 4; jj++) vv[jj] = *(const float4*)&vs[(k4 * 4 + jj) * AP + tx * 4];
#pragma unroll
            for (int i = 0; i < 4; i++) {
                o[i][0] += pv4[i].x * vv[0].x + pv4[i].y * vv[1].x + pv4[i].z * vv[2].x + pv4[i].w * vv[3].x;
                o[i][1] += pv4[i].x * vv[0].y + pv4[i].y * vv[1].y + pv4[i].z * vv[2].y + pv4[i].w * vv[3].y;
                o[i][2] += pv4[i].x * vv[0].z + pv4[i].y * vv[1].z + pv4[i].z * vv[2].z + pv4[i].w * vv[3].z;
                o[i][3] += pv4[i].x * vv[0].w + pv4[i].y * vv[1].w + pv4[i].z * vv[2].w + pv4[i].w * vv[3].w;
            }
        }
    }

    // Write ctx directly in [B, T, C] layout
    float* obase = g_ctx + (b * Tt + q0) * Cc + h * Dd;
#pragma unroll
    for (int i = 0; i < 4; i++) {
        int q = ty * 4 + i;
        float inv = 1.f / l_sm[q];
        float4 o4;
        o4.x = o[i][0] * inv;
        o4.y = o[i][1] * inv;
        o4.z = o[i][2] * inv;
        o4.w = o[i][3] * inv;
        *(float4*)&obase[q * Cc + tx * 4] = o4;
    }
}

// ---------------------------------------------------------------------------
// Launch
// ---------------------------------------------------------------------------
extern "C" void kernel_launch(void* const* d_in, const int* in_sizes, int n_in,
                              void* d_out, int out_size) {
    const float* x    = (const float*)d_in[0];
    const int*   mask = (const int*)d_in[1];
    const int*   cdrs = (const int*)d_in[2];
    const float* Wq   = (const float*)d_in[3];
    const float* bq   = (const float*)d_in[4];
    const float* Wk   = (const float*)d_in[5];
    const float* bk   = (const float*)d_in[6];
    const float* Wv   = (const float*)d_in[7];
    const float* bv   = (const float*)d_in[8];
    const float* Wo   = (const float*)d_in[9];
    const float* bo   = (const float*)d_in[10];
    float* out = (float*)d_out;

    // 1. per-batch CDR all-masked flag
    allm_kernel<<<Bb, 256>>>(cdrs);

    // 2. fused QKV projections
    dim3 gqkv(Bb * Tt / 64, Cc / 64, 3);
    gemm_qkv<<<gqkv, 256>>>(x, Wq, bq, Wk, bk, Wv, bv);

    // 3. attention
    size_t shbytes = (size_t)4 * 64 * AP * sizeof(float);   // 69632 B
    cudaFuncSetAttribute(attn_kernel, cudaFuncAttributeMaxDynamicSharedMemorySize,
                         (int)shbytes);
    dim3 gatt(Tt / 64, Hh, Bb);
    attn_kernel<<<gatt, 256, shbytes>>>(mask, cdrs);

    // 4. output projection
    dim3 gout(Bb * Tt / 64, Cc / 64, 1);
    gemm_out<<<gout, 256>>>(Wo, bo, out);
}

// round 2
// speedup vs baseline: 1.3181x; 1.3181x over previous
#include <cuda_runtime.h>

// Problem constants
#define Bb   4
#define Tt   2048
#define Cc   512
#define Hh   8
#define Dd   64
#define CDRH 2

#define NEG_INF __int_as_float(0xff800000)

// Scratch (allocation-free: module-static device globals)
__device__ float g_q[Bb * Tt * Cc];
__device__ float g_k[Bb * Tt * Cc];
__device__ float g_v[Bb * Tt * Cc];
__device__ float g_ctx[Bb * Tt * Cc];
__device__ int   g_allm[Bb];

// ---------------------------------------------------------------------------
// Per-batch "all CDR tokens masked" flag
// ---------------------------------------------------------------------------
__global__ void allm_kernel(const int* __restrict__ cdrs) {
    __shared__ int any;
    int b = blockIdx.x;
    if (threadIdx.x == 0) any = 0;
    __syncthreads();
    int local = 0;
    for (int t = threadIdx.x; t < Tt; t += blockDim.x)
        local |= (cdrs[b * Tt + t] != 0);
    if (local) any = 1;
    __syncthreads();
    if (threadIdx.x == 0) g_allm[b] = (any == 0) ? 1 : 0;
}

// ---------------------------------------------------------------------------
// Tiled GEMM: out[M, 512] = A[M, 512] @ W[512, 512] + bias
// BM=BN=128, BK=16, 256 threads, 8x8 register micro-tile (0.5 B/FLOP).
// ---------------------------------------------------------------------------
#define GP 132   // smem row pitch (floats), 16B-aligned rows

__device__ __forceinline__ void gemm_body(const float* __restrict__ A,
                                          const float* __restrict__ W,
                                          const float* __restrict__ bias,
                                          float* __restrict__ out) {
    __shared__ float As[16][GP];   // [k][m]
    __shared__ float Bs[16][GP];   // [k][n]
    const int tid = threadIdx.x;
    const int tx = tid & 15, ty = tid >> 4;
    const int m0 = blockIdx.x * 128, n0 = blockIdx.y * 128;

    float acc[8][8] = {};

    for (int k0 = 0; k0 < Cc; k0 += 16) {
        // load A tile: As[k][m] from A[m0+m][k0+k]
#pragma unroll
        for (int p = 0; p < 8; p++) {
            int m = p * 16 + (tid >> 4);
            int k = tid & 15;
            As[k][m] = A[(m0 + m) * Cc + k0 + k];
        }
        // load W tile: Bs[k][n] from W[k0+k][n0+n] (coalesced on n)
#pragma unroll
        for (int p = 0; p < 8; p++) {
            int k = p * 2 + (tid >> 7);
            int n = tid & 127;
            Bs[k][n] = W[(k0 + k) * Cc + n0 + n];
        }
        __syncthreads();

#pragma unroll
        for (int kk = 0; kk < 16; kk++) {
            float4 a_lo = *(const float4*)&As[kk][ty * 8];
            float4 a_hi = *(const float4*)&As[kk][ty * 8 + 4];
            float4 b_lo = *(const float4*)&Bs[kk][tx * 8];
            float4 b_hi = *(const float4*)&Bs[kk][tx * 8 + 4];
            float av[8] = {a_lo.x, a_lo.y, a_lo.z, a_lo.w,
                           a_hi.x, a_hi.y, a_hi.z, a_hi.w};
            float bv[8] = {b_lo.x, b_lo.y, b_lo.z, b_lo.w,
                           b_hi.x, b_hi.y, b_hi.z, b_hi.w};
#pragma unroll
            for (int i = 0; i < 8; i++)
#pragma unroll
                for (int j = 0; j < 8; j++)
                    acc[i][j] += av[i] * bv[j];
        }
        __syncthreads();
    }

    float4 bi_lo = *(const float4*)&bias[n0 + tx * 8];
    float4 bi_hi = *(const float4*)&bias[n0 + tx * 8 + 4];
    float bv[8] = {bi_lo.x, bi_lo.y, bi_lo.z, bi_lo.w,
                   bi_hi.x, bi_hi.y, bi_hi.z, bi_hi.w};
#pragma unroll
    for (int i = 0; i < 8; i++) {
        int m = m0 + ty * 8 + i;
        float4 lo, hi;
        lo.x = acc[i][0] + bv[0];  lo.y = acc[i][1] + bv[1];
        lo.z = acc[i][2] + bv[2];  lo.w = acc[i][3] + bv[3];
        hi.x = acc[i][4] + bv[4];  hi.y = acc[i][5] + bv[5];
        hi.z = acc[i][6] + bv[6];  hi.w = acc[i][7] + bv[7];
        *(float4*)&out[m * Cc + n0 + tx * 8]     = lo;
        *(float4*)&out[m * Cc + n0 + tx * 8 + 4] = hi;
    }
}

__global__ __launch_bounds__(256)
void gemm_qkv(const float* __restrict__ x,
              const float* __restrict__ Wq, const float* __restrict__ bq,
              const float* __restrict__ Wk, const float* __restrict__ bk,
              const float* __restrict__ Wv, const float* __restrict__ bv) {
    const float* W; const float* bi; float* out;
    if (blockIdx.z == 0)      { W = Wq; bi = bq; out = g_q; }
    else if (blockIdx.z == 1) { W = Wk; bi = bk; out = g_k; }
    else                      { W = Wv; bi = bv; out = g_v; }
    gemm_body(x, W, bi, out);
}

__global__ __launch_bounds__(256)
void gemm_out(const float* __restrict__ Wo, const float* __restrict__ bo,
              float* __restrict__ out) {
    gemm_body(g_ctx, Wo, bo, out);
}

// ---------------------------------------------------------------------------
// Flash attention: block = (128-query tile, head, batch), 256 threads.
// S kept in registers (8 rows x 4 cols per thread); softmax fully parallel
// via shfl_xor over the 16-lane column group. 8x4 micro for QK^T and PV.
// ---------------------------------------------------------------------------
#define AP 68

__global__ __launch_bounds__(256, 2)
void attn_kernel(const int* __restrict__ mask, const int* __restrict__ cdrs) {
    extern __shared__ float sh[];
    float* qs = sh;                   // [128][AP]
    float* ks = sh + 128 * AP;        // [64][AP]
    float* vs = ks + 64 * AP;         // [64][AP]
    float* ps = vs + 64 * AP;         // [128][AP]

    __shared__ __align__(16) float kneg[64];

    const int q0  = blockIdx.x * 128;
    const int h   = blockIdx.y;
    const int b   = blockIdx.z;
    const int tid = threadIdx.x;
    const int tx  = tid & 15, ty = tid >> 4;

    const bool iscdr = (h < CDRH) && (g_allm[b] == 0);

    // Load Q tile: 128 rows x 64 floats
    const float* qbase = g_q + (b * Tt + q0) * Cc + h * Dd;
    for (int i = tid; i < 128 * 16; i += 256) {
        int r = i >> 4, c4 = i & 15;
        *(float4*)&qs[r * AP + c4 * 4] = *(const float4*)(qbase + r * Cc + c4 * 4);
    }

    float m_run[8], l_run[8];
    float o[8][4] = {};
#pragma unroll
    for (int i = 0; i < 8; i++) { m_run[i] = NEG_INF; l_run[i] = 0.f; }

    for (int kt = 0; kt < Tt / 64; kt++) {
        const int k0 = kt * 64;
        __syncthreads();   // protect ks/vs/ps from previous iteration's readers

        const float* kbase = g_k + (b * Tt + k0) * Cc + h * Dd;
        const float* vbase = g_v + (b * Tt + k0) * Cc + h * Dd;
        for (int i = tid; i < 64 * 16; i += 256) {
            int r = i >> 4, c4 = i & 15;
            *(float4*)&ks[r * AP + c4 * 4] = *(const float4*)(kbase + r * Cc + c4 * 4);
            *(float4*)&vs[r * AP + c4 * 4] = *(const float4*)(vbase + r * Cc + c4 * 4);
        }
        if (tid < 64) {
            int kg = k0 + tid;
            bool bad = (mask[b * Tt + kg] == 0) ||
                       (iscdr && (cdrs[b * Tt + kg] == 0));
            kneg[tid] = bad ? NEG_INF : 0.f;
        }
        __syncthreads();

        // ---- S = Q K^T (8 rows x 4 cols per thread, in registers) ----
        float s[8][4] = {};
#pragma unroll
        for (int d4 = 0; d4 < 16; d4++) {
            float4 kv[4];
#pragma unroll
            for (int j = 0; j < 4; j++)
                kv[j] = *(const float4*)&ks[(tx * 4 + j) * AP + d4 * 4];
#pragma unroll
            for (int i = 0; i < 8; i++) {
                float4 qv = *(const float4*)&qs[(ty * 8 + i) * AP + d4 * 4];
#pragma unroll
                for (int j = 0; j < 4; j++)
                    s[i][j] += qv.x * kv[j].x + qv.y * kv[j].y +
                               qv.z * kv[j].z + qv.w * kv[j].w;
            }
        }

        // scale + key mask bias
        float4 kn4 = *(const float4*)&kneg[tx * 4];
        float kn[4] = {kn4.x, kn4.y, kn4.z, kn4.w};
#pragma unroll
        for (int i = 0; i < 8; i++)
#pragma unroll
            for (int j = 0; j < 4; j++)
                s[i][j] = s[i][j] * 0.125f + kn[j];

        // ---- Online softmax, fully parallel ----
#pragma unroll
        for (int i = 0; i < 8; i++) {
            float mt = fmaxf(fmaxf(s[i][0], s[i][1]), fmaxf(s[i][2], s[i][3]));
#pragma unroll
            for (int off = 1; off < 16; off <<= 1)
                mt = fmaxf(mt, __shfl_xor_sync(0xffffffffu, mt, off));
            float mn = fmaxf(m_run[i], mt);
            float alpha, rsum = 0.f;
            if (mn == NEG_INF) {
                alpha = 1.f;
#pragma unroll
                for (int j = 0; j < 4; j++) s[i][j] = 0.f;
            } else {
                alpha = __expf(m_run[i] - mn);   // m_run=-inf -> 0
#pragma unroll
                for (int j = 0; j < 4; j++) {
                    float p = __expf(s[i][j] - mn);   // s=-inf -> 0
                    s[i][j] = p;
                    rsum += p;
                }
            }
#pragma unroll
            for (int off = 1; off < 16; off <<= 1)
                rsum += __shfl_xor_sync(0xffffffffu, rsum, off);
            m_run[i] = mn;
            l_run[i] = l_run[i] * alpha + rsum;
#pragma unroll
            for (int j = 0; j < 4; j++) o[i][j] *= alpha;
            // stash probabilities for the PV GEMM
            float4 w = {s[i][0], s[i][1], s[i][2], s[i][3]};
            *(float4*)&ps[(ty * 8 + i) * AP + tx * 4] = w;
        }
        __syncthreads();

        // ---- O += P @ V (8 rows x 4 dims per thread) ----
#pragma unroll
        for (int k4 = 0; k4 < 16; k4++) {
            float4 vv[4];
#pragma unroll
            for (int jj = 0; jj < 4; jj++)
                vv[jj] = *(const float4*)&vs[(k4 * 4 + jj) * AP + tx * 4];
#pragma unroll
            for (int i = 0; i < 8; i++) {
                float4 pv = *(const float4*)&ps[(ty * 8 + i) * AP + k4 * 4];
                o[i][0] += pv.x * vv[0].x + pv.y * vv[1].x + pv.z * vv[2].x + pv.w * vv[3].x;
                o[i][1] += pv.x * vv[0].y + pv.y * vv[1].y + pv.z * vv[2].y + pv.w * vv[3].y;
                o[i][2] += pv.x * vv[0].z + pv.y * vv[1].z + pv.z * vv[2].z + pv.w * vv[3].z;
                o[i][3] += pv.x * vv[0].w + pv.y * vv[1].w + pv.z * vv[2].w + pv.w * vv[3].w;
            }
        }
    }

    // Epilogue: normalize and write ctx in [B, T, C] layout
    float* obase = g_ctx + (b * Tt + q0) * Cc + h * Dd;
#pragma unroll
    for (int i = 0; i < 8; i++) {
        int q = ty * 8 + i;
        float inv = 1.f / l_run[i];
        float4 o4;
        o4.x = o[i][0] * inv;
        o4.y = o[i][1] * inv;
        o4.z = o[i][2] * inv;
        o4.w = o[i][3] * inv;
        *(float4*)&obase[q * Cc + tx * 4] = o4;
    }
}

// ---------------------------------------------------------------------------
// Launch
// ---------------------------------------------------------------------------
extern "C" void kernel_launch(void* const* d_in, const int* in_sizes, int n_in,
                              void* d_out, int out_size) {
    const float* x    = (const float*)d_in[0];
    const int*   mask = (const int*)d_in[1];
    const int*   cdrs = (const int*)d_in[2];
    const float* Wq   = (const float*)d_in[3];
    const float* bq   = (const float*)d_in[4];
    const float* Wk   = (const float*)d_in[5];
    const float* bk   = (const float*)d_in[6];
    const float* Wv   = (const float*)d_in[7];
    const float* bv   = (const float*)d_in[8];
    const float* Wo   = (const float*)d_in[9];
    const float* bo   = (const float*)d_in[10];
    float* out = (float*)d_out;

    allm_kernel<<<Bb, 256>>>(cdrs);

    dim3 gqkv(Bb * Tt / 128, Cc / 128, 3);
    gemm_qkv<<<gqkv, 256>>>(x, Wq, bq, Wk, bk, Wv, bv);

    size_t shbytes = (size_t)(128 * AP + 64 * AP + 64 * AP + 128 * AP) * sizeof(float);
    cudaFuncSetAttribute(attn_kernel, cudaFuncAttributeMaxDynamicSharedMemorySize,
                         (int)shbytes);
    dim3 gatt(Tt / 128, Hh, Bb);
    attn_kernel<<<gatt, 256, shbytes>>>(mask, cdrs);

    dim3 gout(Bb * Tt / 128, Cc / 128, 1);
    gemm_out<<<gout, 256>>>(Wo, bo, out);
}

// round 3
// speedup vs baseline: 2.1894x; 1.6610x over previous
#include <cuda_runtime.h>
#include <cstdint>

// Problem constants
#define Bb   4
#define Tt   2048
#define Cc   512
#define Hh   8
#define Dd   64
#define CDRH 2

#define NEG_INF __int_as_float(0xff800000)

// Scratch (allocation-free: module-static device globals)
__device__ float g_q[Bb * Tt * Cc];
__device__ float g_k[Bb * Tt * Cc];
__device__ float g_v[Bb * Tt * Cc];
__device__ float g_ctx[Bb * Tt * Cc];
__device__ int   g_allm[Bb];

// ---------------------------------------------------------------------------
// tf32 helpers
// ---------------------------------------------------------------------------
__device__ __forceinline__ uint32_t f2tf32(float x) {
    uint32_t r;
    asm("cvt.rna.tf32.f32 %0, %1;" : "=r"(r) : "f"(x));
    return r;
}

__device__ __forceinline__ void mma_tf32(float c[4], const uint32_t a[4],
                                         uint32_t b0, uint32_t b1) {
    asm volatile(
        "mma.sync.aligned.m16n8k8.row.col.f32.tf32.tf32.f32 "
        "{%0,%1,%2,%3}, {%4,%5,%6,%7}, {%8,%9}, {%0,%1,%2,%3};"
        : "+f"(c[0]), "+f"(c[1]), "+f"(c[2]), "+f"(c[3])
        : "r"(a[0]), "r"(a[1]), "r"(a[2]), "r"(a[3]), "r"(b0), "r"(b1));
}

// ---------------------------------------------------------------------------
// Per-batch "all CDR tokens masked" flag
// ---------------------------------------------------------------------------
__global__ void allm_kernel(const int* __restrict__ cdrs) {
    __shared__ int any;
    int b = blockIdx.x;
    if (threadIdx.x == 0) any = 0;
    __syncthreads();
    int local = 0;
    for (int t = threadIdx.x; t < Tt; t += blockDim.x)
        local |= (cdrs[b * Tt + t] != 0);
    if (local) any = 1;
    __syncthreads();
    if (threadIdx.x == 0) g_allm[b] = (any == 0) ? 1 : 0;
}

// ---------------------------------------------------------------------------
// fp32 tiled GEMM for projections (unchanged from round 2)
// ---------------------------------------------------------------------------
#define GP 132

__device__ __forceinline__ void gemm_body(const float* __restrict__ A,
                                          const float* __restrict__ W,
                                          const float* __restrict__ bias,
                                          float* __restrict__ out) {
    __shared__ float As[16][GP];
    __shared__ float Bs[16][GP];
    const int tid = threadIdx.x;
    const int tx = tid & 15, ty = tid >> 4;
    const int m0 = blockIdx.x * 128, n0 = blockIdx.y * 128;

    float acc[8][8] = {};

    for (int k0 = 0; k0 < Cc; k0 += 16) {
#pragma unroll
        for (int p = 0; p < 8; p++) {
            int m = p * 16 + (tid >> 4);
            int k = tid & 15;
            As[k][m] = A[(m0 + m) * Cc + k0 + k];
        }
#pragma unroll
        for (int p = 0; p < 8; p++) {
            int k = p * 2 + (tid >> 7);
            int n = tid & 127;
            Bs[k][n] = W[(k0 + k) * Cc + n0 + n];
        }
        __syncthreads();

#pragma unroll
        for (int kk = 0; kk < 16; kk++) {
            float4 a_lo = *(const float4*)&As[kk][ty * 8];
            float4 a_hi = *(const float4*)&As[kk][ty * 8 + 4];
            float4 b_lo = *(const float4*)&Bs[kk][tx * 8];
            float4 b_hi = *(const float4*)&Bs[kk][tx * 8 + 4];
            float av[8] = {a_lo.x, a_lo.y, a_lo.z, a_lo.w,
                           a_hi.x, a_hi.y, a_hi.z, a_hi.w};
            float bv[8] = {b_lo.x, b_lo.y, b_lo.z, b_lo.w,
                           b_hi.x, b_hi.y, b_hi.z, b_hi.w};
#pragma unroll
            for (int i = 0; i < 8; i++)
#pragma unroll
                for (int j = 0; j < 8; j++)
                    acc[i][j] += av[i] * bv[j];
        }
        __syncthreads();
    }

    float4 bi_lo = *(const float4*)&bias[n0 + tx * 8];
    float4 bi_hi = *(const float4*)&bias[n0 + tx * 8 + 4];
    float bv[8] = {bi_lo.x, bi_lo.y, bi_lo.z, bi_lo.w,
                   bi_hi.x, bi_hi.y, bi_hi.z, bi_hi.w};
#pragma unroll
    for (int i = 0; i < 8; i++) {
        int m = m0 + ty * 8 + i;
        float4 lo, hi;
        lo.x = acc[i][0] + bv[0];  lo.y = acc[i][1] + bv[1];
        lo.z = acc[i][2] + bv[2];  lo.w = acc[i][3] + bv[3];
        hi.x = acc[i][4] + bv[4];  hi.y = acc[i][5] + bv[5];
        hi.z = acc[i][6] + bv[6];  hi.w = acc[i][7] + bv[7];
        *(float4*)&out[m * Cc + n0 + tx * 8]     = lo;
        *(float4*)&out[m * Cc + n0 + tx * 8 + 4] = hi;
    }
}

__global__ __launch_bounds__(256)
void gemm_qkv(const float* __restrict__ x,
              const float* __restrict__ Wq, const float* __restrict__ bq,
              const float* __restrict__ Wk, const float* __restrict__ bk,
              const float* __restrict__ Wv, const float* __restrict__ bv) {
    const float* W; const float* bi; float* out;
    if (blockIdx.z == 0)      { W = Wq; bi = bq; out = g_q; }
    else if (blockIdx.z == 1) { W = Wk; bi = bk; out = g_k; }
    else                      { W = Wv; bi = bv; out = g_v; }
    gemm_body(x, W, bi, out);
}

__global__ __launch_bounds__(256)
void gemm_out(const float* __restrict__ Wo, const float* __restrict__ bo,
              float* __restrict__ out) {
    gemm_body(g_ctx, Wo, bo, out);
}

// ---------------------------------------------------------------------------
// TF32 tensor-core flash attention.
// Block = (128-query tile, head, batch), 8 warps; warp w owns q rows
// [w*16, w*16+16). mma.m16n8k8 tf32 for QK^T and PV. Softmax reduced over
// lane quads (C-fragment layout keeps a row within 4 lanes).
// ---------------------------------------------------------------------------
#define AP 68   // smem pitch (floats) for 64-wide tiles

__global__ __launch_bounds__(256)
void attn_kernel(const int* __restrict__ mask, const int* __restrict__ cdrs) {
    extern __shared__ float sh[];
    float* ks = sh;                  // [64][AP]  K tile (tf32 bits)
    float* vs = sh + 64 * AP;        // [64][AP]  V tile (tf32 bits)
    float* ps = vs + 64 * AP;        // [128][AP] Q staging, then P per warp

    __shared__ __align__(16) float kneg[64];

    const int q0   = blockIdx.x * 128;
    const int h    = blockIdx.y;
    const int b    = blockIdx.z;
    const int tid  = threadIdx.x;
    const int warp = tid >> 5;
    const int lane = tid & 31;
    const int g    = lane >> 2;      // group id 0..7
    const int tig  = lane & 3;       // thread in group

    const bool iscdr = (h < CDRH) && (g_allm[b] == 0);

    // ---- Stage Q (tf32-rounded) into ps, then hoist fragments to regs ----
    const float* qbase = g_q + (b * Tt + q0) * Cc + h * Dd;
    for (int i = tid; i < 128 * 16; i += 256) {
        int r = i >> 4, c4 = i & 15;
        float4 v = *(const float4*)(qbase + r * Cc + c4 * 4);
        float* dst = &ps[r * AP + c4 * 4];
        dst[0] = __uint_as_float(f2tf32(v.x));
        dst[1] = __uint_as_float(f2tf32(v.y));
        dst[2] = __uint_as_float(f2tf32(v.z));
        dst[3] = __uint_as_float(f2tf32(v.w));
    }
    __syncthreads();

    const int r0 = warp * 16 + g;    // this thread's first q row (local)
    const int r1 = r0 + 8;           // second q row

    uint32_t qa[8][4];               // Q fragments: 8 k-chunks over D=64
#pragma unroll
    for (int kc = 0; kc < 8; kc++) {
        qa[kc][0] = __float_as_uint(ps[r0 * AP + kc * 8 + tig]);
        qa[kc][1] = __float_as_uint(ps[r1 * AP + kc * 8 + tig]);
        qa[kc][2] = __float_as_uint(ps[r0 * AP + kc * 8 + tig + 4]);
        qa[kc][3] = __float_as_uint(ps[r1 * AP + kc * 8 + tig + 4]);
    }

    float m_run[2] = {NEG_INF, NEG_INF};
    float l_run[2] = {0.f, 0.f};
    float o[8][4] = {};              // O accum: 8 d-tiles, C-layout each

    float* pw = ps + warp * 16 * AP; // warp-private P strip (16 rows)

    for (int kt = 0; kt < Tt / 64; kt++) {
        const int k0 = kt * 64;
        __syncthreads();   // ks/vs consumed by all warps in prev iter

        const float* kbase = g_k + (b * Tt + k0) * Cc + h * Dd;
        const float* vbase = g_v + (b * Tt + k0) * Cc + h * Dd;
        for (int i = tid; i < 64 * 16; i += 256) {
            int r = i >> 4, c4 = i & 15;
            float4 kv = *(const float4*)(kbase + r * Cc + c4 * 4);
            float4 vv = *(const float4*)(vbase + r * Cc + c4 * 4);
            float* kd = &ks[r * AP + c4 * 4];
            float* vd = &vs[r * AP + c4 * 4];
            kd[0] = __uint_as_float(f2tf32(kv.x));
            kd[1] = __uint_as_float(f2tf32(kv.y));
            kd[2] = __uint_as_float(f2tf32(kv.z));
            kd[3] = __uint_as_float(f2tf32(kv.w));
            vd[0] = __uint_as_float(f2tf32(vv.x));
            vd[1] = __uint_as_float(f2tf32(vv.y));
            vd[2] = __uint_as_float(f2tf32(vv.z));
            vd[3] = __uint_as_float(f2tf32(vv.w));
        }
        if (tid < 64) {
            int kg = k0 + tid;
            bool bad = (mask[b * Tt + kg] == 0) ||
                       (iscdr && (cdrs[b * Tt + kg] == 0));
            kneg[tid] = bad ? NEG_INF : 0.f;
        }
        __syncthreads();

        // ---- S = Q K^T : 8 n-tiles (keys) x 8 k-chunks (dims) ----
        float s[8][4] = {};
#pragma unroll
        for (int kc = 0; kc < 8; kc++) {
#pragma unroll
            for (int nt = 0; nt < 8; nt++) {
                uint32_t b0 = __float_as_uint(ks[(nt * 8 + g) * AP + kc * 8 + tig]);
                uint32_t b1 = __float_as_uint(ks[(nt * 8 + g) * AP + kc * 8 + tig + 4]);
                mma_tf32(s[nt], qa[kc], b0, b1);
            }
        }

        // ---- scale + key-mask bias ----
#pragma unroll
        for (int nt = 0; nt < 8; nt++) {
            float k0b = kneg[nt * 8 + 2 * tig];
            float k1b = kneg[nt * 8 + 2 * tig + 1];
            s[nt][0] = s[nt][0] * 0.125f + k0b;
            s[nt][1] = s[nt][1] * 0.125f + k1b;
            s[nt][2] = s[nt][2] * 0.125f + k0b;
            s[nt][3] = s[nt][3] * 0.125f + k1b;
        }

        // ---- online softmax (rows r0 and r1, reduced over lane quad) ----
        float mt0 = NEG_INF, mt1 = NEG_INF;
#pragma unroll
        for (int nt = 0; nt < 8; nt++) {
            mt0 = fmaxf(mt0, fmaxf(s[nt][0], s[nt][1]));
            mt1 = fmaxf(mt1, fmaxf(s[nt][2], s[nt][3]));
        }
#pragma unroll
        for (int off = 1; off < 4; off <<= 1) {
            mt0 = fmaxf(mt0, __shfl_xor_sync(0xffffffffu, mt0, off));
            mt1 = fmaxf(mt1, __shfl_xor_sync(0xffffffffu, mt1, off));
        }
        float mn0 = fmaxf(m_run[0], mt0);
        float mn1 = fmaxf(m_run[1], mt1);
        float alpha0, alpha1, sum0 = 0.f, sum1 = 0.f;
        if (mn0 == NEG_INF) {
            alpha0 = 1.f;
#pragma unroll
            for (int nt = 0; nt < 8; nt++) { s[nt][0] = 0.f; s[nt][1] = 0.f; }
        } else {
            alpha0 = __expf(m_run[0] - mn0);
#pragma unroll
            for (int nt = 0; nt < 8; nt++) {
                float p0 = __expf(s[nt][0] - mn0);
                float p1 = __expf(s[nt][1] - mn0);
                s[nt][0] = p0; s[nt][1] = p1;
                sum0 += p0 + p1;
            }
        }
        if (mn1 == NEG_INF) {
            alpha1 = 1.f;
#pragma unroll
            for (int nt = 0; nt < 8; nt++) { s[nt][2] = 0.f; s[nt][3] = 0.f; }
        } else {
            alpha1 = __expf(m_run[1] - mn1);
#pragma unroll
            for (int nt = 0; nt < 8; nt++) {
                float p0 = __expf(s[nt][2] - mn1);
                float p1 = __expf(s[nt][3] - mn1);
                s[nt][2] = p0; s[nt][3] = p1;
                sum1 += p0 + p1;
            }
        }
#pragma unroll
        for (int off = 1; off < 4; off <<= 1) {
            sum0 += __shfl_xor_sync(0xffffffffu, sum0, off);
            sum1 += __shfl_xor_sync(0xffffffffu, sum1, off);
        }
        m_run[0] = mn0;  l_run[0] = l_run[0] * alpha0 + sum0;
        m_run[1] = mn1;  l_run[1] = l_run[1] * alpha1 + sum1;

        // rescale O
#pragma unroll
        for (int nt = 0; nt < 8; nt++) {
            o[nt][0] *= alpha0; o[nt][1] *= alpha0;
            o[nt][2] *= alpha1; o[nt][3] *= alpha1;
        }

        // ---- stash P (tf32) in warp-private smem, re-layout as A frags ----
#pragma unroll
        for (int nt = 0; nt < 8; nt++) {
            float2 w0, w1;
            w0.x = __uint_as_float(f2tf32(s[nt][0]));
            w0.y = __uint_as_float(f2tf32(s[nt][1]));
            w1.x = __uint_as_float(f2tf32(s[nt][2]));
            w1.y = __uint_as_float(f2tf32(s[nt][3]));
            *(float2*)&pw[g * AP + nt * 8 + 2 * tig]       = w0;
            *(float2*)&pw[(g + 8) * AP + nt * 8 + 2 * tig] = w1;
        }
        __syncwarp();

        // ---- O += P @ V ----
#pragma unroll
        for (int kc = 0; kc < 8; kc++) {
            uint32_t pa[4];
            pa[0] = __float_as_uint(pw[g * AP + kc * 8 + tig]);
            pa[1] = __float_as_uint(pw[(g + 8) * AP + kc * 8 + tig]);
            pa[2] = __float_as_uint(pw[g * AP + kc * 8 + tig + 4]);
            pa[3] = __float_as_uint(pw[(g + 8) * AP + kc * 8 + tig + 4]);
#pragma unroll
            for (int nt = 0; nt < 8; nt++) {
                uint32_t b0 = __float_as_uint(vs[(kc * 8 + tig) * AP + nt * 8 + g]);
                uint32_t b1 = __float_as_uint(vs[(kc * 8 + tig + 4) * AP + nt * 8 + g]);
                mma_tf32(o[nt], pa, b0, b1);
            }
        }
        __syncwarp();   // pw reads done before next iteration's overwrite
    }

    // ---- epilogue: normalize, write ctx [B, T, C] ----
    float inv0 = 1.f / l_run[0];
    float inv1 = 1.f / l_run[1];
    float* ob0 = g_ctx + (b * Tt + q0 + r0) * Cc + h * Dd;
    float* ob1 = g_ctx + (b * Tt + q0 + r1) * Cc + h * Dd;
#pragma unroll
    for (int nt = 0; nt < 8; nt++) {
        float2 w0 = {o[nt][0] * inv0, o[nt][1] * inv0};
        float2 w1 = {o[nt][2] * inv1, o[nt][3] * inv1};
        *(float2*)&ob0[nt * 8 + 2 * tig] = w0;
        *(float2*)&ob1[nt * 8 + 2 * tig] = w1;
    }
}

// ---------------------------------------------------------------------------
// Launch
// ---------------------------------------------------------------------------
extern "C" void kernel_launch(void* const* d_in, const int* in_sizes, int n_in,
                              void* d_out, int out_size) {
    const float* x    = (const float*)d_in[0];
    const int*   mask = (const int*)d_in[1];
    const int*   cdrs = (const int*)d_in[2];
    const float* Wq   = (const float*)d_in[3];
    const float* bq   = (const float*)d_in[4];
    const float* Wk   = (const float*)d_in[5];
    const float* bk   = (const float*)d_in[6];
    const float* Wv   = (const float*)d_in[7];
    const float* bv   = (const float*)d_in[8];
    const float* Wo   = (const float*)d_in[9];
    const float* bo   = (const float*)d_in[10];
    float* out = (float*)d_out;

    allm_kernel<<<Bb, 256>>>(cdrs);

    dim3 gqkv(Bb * Tt / 128, Cc / 128, 3);
    gemm_qkv<<<gqkv, 256>>>(x, Wq, bq, Wk, bk, Wv, bv);

    size_t shbytes = (size_t)(64 * AP + 64 * AP + 128 * AP) * sizeof(float); // 69632
    cudaFuncSetAttribute(attn_kernel, cudaFuncAttributeMaxDynamicSharedMemorySize,
                         (int)shbytes);
    dim3 gatt(Tt / 128, Hh, Bb);
    attn_kernel<<<gatt, 256, shbytes>>>(mask, cdrs);

    dim3 gout(Bb * Tt / 128, Cc / 128, 1);
    gemm_out<<<gout, 256>>>(Wo, bo, out);
}

// round 4
// speedup vs baseline: 2.6703x; 1.2197x over previous
#include <cuda_runtime.h>
#include <cstdint>

// Problem constants
#define Bb   4
#define Tt   2048
#define Cc   512
#define Hh   8
#define Dd   64
#define CDRH 2

#define NEG_INF __int_as_float(0xff800000)

// Scratch (allocation-free: module-static device globals)
__device__ float g_q[Bb * Tt * Cc];
__device__ float g_k[Bb * Tt * Cc];
__device__ float g_v[Bb * Tt * Cc];
__device__ float g_ctx[Bb * Tt * Cc];
__device__ int   g_allm[Bb];

// ---------------------------------------------------------------------------
// tf32 helpers
// ---------------------------------------------------------------------------
__device__ __forceinline__ uint32_t f2tf32(float x) {
    uint32_t r;
    asm("cvt.rna.tf32.f32 %0, %1;" : "=r"(r) : "f"(x));
    return r;
}

__device__ __forceinline__ void mma_tf32(float c[4], const uint32_t a[4],
                                         uint32_t b0, uint32_t b1) {
    asm volatile(
        "mma.sync.aligned.m16n8k8.row.col.f32.tf32.tf32.f32 "
        "{%0,%1,%2,%3}, {%4,%5,%6,%7}, {%8,%9}, {%0,%1,%2,%3};"
        : "+f"(c[0]), "+f"(c[1]), "+f"(c[2]), "+f"(c[3])
        : "r"(a[0]), "r"(a[1]), "r"(a[2]), "r"(a[3]), "r"(b0), "r"(b1));
}

// ---------------------------------------------------------------------------
// Per-batch "all CDR tokens masked" flag
// ---------------------------------------------------------------------------
__global__ void allm_kernel(const int* __restrict__ cdrs) {
    __shared__ int any;
    int b = blockIdx.x;
    if (threadIdx.x == 0) any = 0;
    __syncthreads();
    int local = 0;
    for (int t = threadIdx.x; t < Tt; t += blockDim.x)
        local |= (cdrs[b * Tt + t] != 0);
    if (local) any = 1;
    __syncthreads();
    if (threadIdx.x == 0) g_allm[b] = (any == 0) ? 1 : 0;
}

// ---------------------------------------------------------------------------
// TF32 tensor-core GEMM: out[M,512] = A[M,512] @ W[512,512] + bias
// BM=BN=128, BK=16; 8 warps in 2(m) x 4(n); warp tile 64x32 via m16n8k8.
// ---------------------------------------------------------------------------
__device__ __forceinline__ void gemm_tf32_body(const float* __restrict__ A,
                                               const float* __restrict__ W,
                                               const float* __restrict__ bias,
                                               float* __restrict__ out) {
    __shared__ float As[16][132];   // [k][m], tf32 bits
    __shared__ float Bs[16][132];   // [k][n], tf32 bits
    const int tid  = threadIdx.x;
    const int warp = tid >> 5;
    const int lane = tid & 31;
    const int g    = lane >> 2;     // 0..7
    const int tig  = lane & 3;      // 0..3
    const int wm   = warp >> 2;     // 0..1  (m direction)
    const int wn   = warp & 3;      // 0..3  (n direction)
    const int m0 = blockIdx.x * 128, n0 = blockIdx.y * 128;

    float acc[4][4][4] = {};        // [m-tile][n-tile][frag]

    for (int k0 = 0; k0 < Cc; k0 += 16) {
        // load A tile: As[k][m]
#pragma unroll
        for (int p = 0; p < 8; p++) {
            int m = p * 16 + (tid >> 4);
            int k = tid & 15;
            As[k][m] = __uint_as_float(f2tf32(A[(m0 + m) * Cc + k0 + k]));
        }
        // load W tile: Bs[k][n] (coalesced on n)
#pragma unroll
        for (int p = 0; p < 8; p++) {
            int k = p * 2 + (tid >> 7);
            int n = tid & 127;
            Bs[k][n] = __uint_as_float(f2tf32(W[(k0 + k) * Cc + n0 + n]));
        }
        __syncthreads();

#pragma unroll
        for (int kc = 0; kc < 2; kc++) {
            uint32_t af[4][4];
#pragma unroll
            for (int mt = 0; mt < 4; mt++) {
                int r = wm * 64 + mt * 16 + g;
                af[mt][0] = __float_as_uint(As[kc * 8 + tig][r]);
                af[mt][1] = __float_as_uint(As[kc * 8 + tig][r + 8]);
                af[mt][2] = __float_as_uint(As[kc * 8 + tig + 4][r]);
                af[mt][3] = __float_as_uint(As[kc * 8 + tig + 4][r + 8]);
            }
            uint32_t bf[4][2];
#pragma unroll
            for (int nt = 0; nt < 4; nt++) {
                int n = wn * 32 + nt * 8 + g;
                bf[nt][0] = __float_as_uint(Bs[kc * 8 + tig][n]);
                bf[nt][1] = __float_as_uint(Bs[kc * 8 + tig + 4][n]);
            }
#pragma unroll
            for (int mt = 0; mt < 4; mt++)
#pragma unroll
                for (int nt = 0; nt < 4; nt++)
                    mma_tf32(acc[mt][nt], af[mt], bf[nt][0], bf[nt][1]);
        }
        __syncthreads();
    }

    // epilogue: add bias, store (C frag: rows g, g+8; cols 2*tig, 2*tig+1)
#pragma unroll
    for (int mt = 0; mt < 4; mt++) {
        int r0g = m0 + wm * 64 + mt * 16 + g;
        int r1g = r0g + 8;
#pragma unroll
        for (int nt = 0; nt < 4; nt++) {
            int n = n0 + wn * 32 + nt * 8 + 2 * tig;
            float b0 = bias[n], b1 = bias[n + 1];
            float2 w0 = {acc[mt][nt][0] + b0, acc[mt][nt][1] + b1};
            float2 w1 = {acc[mt][nt][2] + b0, acc[mt][nt][3] + b1};
            *(float2*)&out[r0g * Cc + n] = w0;
            *(float2*)&out[r1g * Cc + n] = w1;
        }
    }
}

__global__ __launch_bounds__(256)
void gemm_qkv(const float* __restrict__ x,
              const float* __restrict__ Wq, const float* __restrict__ bq,
              const float* __restrict__ Wk, const float* __restrict__ bk,
              const float* __restrict__ Wv, const float* __restrict__ bv) {
    const float* W; const float* bi; float* out;
    if (blockIdx.z == 0)      { W = Wq; bi = bq; out = g_q; }
    else if (blockIdx.z == 1) { W = Wk; bi = bk; out = g_k; }
    else                      { W = Wv; bi = bv; out = g_v; }
    gemm_tf32_body(x, W, bi, out);
}

// ---------------------------------------------------------------------------
// fp32 tiled GEMM for the output projection (error-critical; stays fp32)
// ---------------------------------------------------------------------------
__global__ __launch_bounds__(256)
void gemm_out(const float* __restrict__ Wo, const float* __restrict__ bo,
              float* __restrict__ out) {
    __shared__ float As[16][132];
    __shared__ float Bs[16][132];
    const float* A = g_ctx;
    const int tid = threadIdx.x;
    const int tx = tid & 15, ty = tid >> 4;
    const int m0 = blockIdx.x * 128, n0 = blockIdx.y * 128;

    float acc[8][8] = {};

    for (int k0 = 0; k0 < Cc; k0 += 16) {
#pragma unroll
        for (int p = 0; p < 8; p++) {
            int m = p * 16 + (tid >> 4);
            int k = tid & 15;
            As[k][m] = A[(m0 + m) * Cc + k0 + k];
        }
#pragma unroll
        for (int p = 0; p < 8; p++) {
            int k = p * 2 + (tid >> 7);
            int n = tid & 127;
            Bs[k][n] = Wo[(k0 + k) * Cc + n0 + n];
        }
        __syncthreads();

#pragma unroll
        for (int kk = 0; kk < 16; kk++) {
            float4 a_lo = *(const float4*)&As[kk][ty * 8];
            float4 a_hi = *(const float4*)&As[kk][ty * 8 + 4];
            float4 b_lo = *(const float4*)&Bs[kk][tx * 8];
            float4 b_hi = *(const float4*)&Bs[kk][tx * 8 + 4];
            float av[8] = {a_lo.x, a_lo.y, a_lo.z, a_lo.w,
                           a_hi.x, a_hi.y, a_hi.z, a_hi.w};
            float bv[8] = {b_lo.x, b_lo.y, b_lo.z, b_lo.w,
                           b_hi.x, b_hi.y, b_hi.z, b_hi.w};
#pragma unroll
            for (int i = 0; i < 8; i++)
#pragma unroll
                for (int j = 0; j < 8; j++)
                    acc[i][j] += av[i] * bv[j];
        }
        __syncthreads();
    }

    float4 bi_lo = *(const float4*)&bo[n0 + tx * 8];
    float4 bi_hi = *(const float4*)&bo[n0 + tx * 8 + 4];
    float bv[8] = {bi_lo.x, bi_lo.y, bi_lo.z, bi_lo.w,
                   bi_hi.x, bi_hi.y, bi_hi.z, bi_hi.w};
#pragma unroll
    for (int i = 0; i < 8; i++) {
        int m = m0 + ty * 8 + i;
        float4 lo, hi;
        lo.x = acc[i][0] + bv[0];  lo.y = acc[i][1] + bv[1];
        lo.z = acc[i][2] + bv[2];  lo.w = acc[i][3] + bv[3];
        hi.x = acc[i][4] + bv[4];  hi.y = acc[i][5] + bv[5];
        hi.z = acc[i][6] + bv[6];  hi.w = acc[i][7] + bv[7];
        *(float4*)&out[m * Cc + n0 + tx * 8]     = lo;
        *(float4*)&out[m * Cc + n0 + tx * 8 + 4] = hi;
    }
}

// ---------------------------------------------------------------------------
// TF32 tensor-core flash attention (unchanged from round 3).
// ---------------------------------------------------------------------------
#define AP 68

__global__ __launch_bounds__(256)
void attn_kernel(const int* __restrict__ mask, const int* __restrict__ cdrs) {
    extern __shared__ float sh[];
    float* ks = sh;                  // [64][AP]
    float* vs = sh + 64 * AP;        // [64][AP]
    float* ps = vs + 64 * AP;        // [128][AP]

    __shared__ __align__(16) float kneg[64];

    const int q0   = blockIdx.x * 128;
    const int h    = blockIdx.y;
    const int b    = blockIdx.z;
    const int tid  = threadIdx.x;
    const int warp = tid >> 5;
    const int lane = tid & 31;
    const int g    = lane >> 2;
    const int tig  = lane & 3;

    const bool iscdr = (h < CDRH) && (g_allm[b] == 0);

    const float* qbase = g_q + (b * Tt + q0) * Cc + h * Dd;
    for (int i = tid; i < 128 * 16; i += 256) {
        int r = i >> 4, c4 = i & 15;
        float4 v = *(const float4*)(qbase + r * Cc + c4 * 4);
        float* dst = &ps[r * AP + c4 * 4];
        dst[0] = __uint_as_float(f2tf32(v.x));
        dst[1] = __uint_as_float(f2tf32(v.y));
        dst[2] = __uint_as_float(f2tf32(v.z));
        dst[3] = __uint_as_float(f2tf32(v.w));
    }
    __syncthreads();

    const int r0 = warp * 16 + g;
    const int r1 = r0 + 8;

    uint32_t qa[8][4];
#pragma unroll
    for (int kc = 0; kc < 8; kc++) {
        qa[kc][0] = __float_as_uint(ps[r0 * AP + kc * 8 + tig]);
        qa[kc][1] = __float_as_uint(ps[r1 * AP + kc * 8 + tig]);
        qa[kc][2] = __float_as_uint(ps[r0 * AP + kc * 8 + tig + 4]);
        qa[kc][3] = __float_as_uint(ps[r1 * AP + kc * 8 + tig + 4]);
    }

    float m_run[2] = {NEG_INF, NEG_INF};
    float l_run[2] = {0.f, 0.f};
    float o[8][4] = {};

    float* pw = ps + warp * 16 * AP;

    for (int kt = 0; kt < Tt / 64; kt++) {
        const int k0 = kt * 64;
        __syncthreads();

        const float* kbase = g_k + (b * Tt + k0) * Cc + h * Dd;
        const float* vbase = g_v + (b * Tt + k0) * Cc + h * Dd;
        for (int i = tid; i < 64 * 16; i += 256) {
            int r = i >> 4, c4 = i & 15;
            float4 kv = *(const float4*)(kbase + r * Cc + c4 * 4);
            float4 vv = *(const float4*)(vbase + r * Cc + c4 * 4);
            float* kd = &ks[r * AP + c4 * 4];
            float* vd = &vs[r * AP + c4 * 4];
            kd[0] = __uint_as_float(f2tf32(kv.x));
            kd[1] = __uint_as_float(f2tf32(kv.y));
            kd[2] = __uint_as_float(f2tf32(kv.z));
            kd[3] = __uint_as_float(f2tf32(kv.w));
            vd[0] = __uint_as_float(f2tf32(vv.x));
            vd[1] = __uint_as_float(f2tf32(vv.y));
            vd[2] = __uint_as_float(f2tf32(vv.z));
            vd[3] = __uint_as_float(f2tf32(vv.w));
        }
        if (tid < 64) {
            int kg = k0 + tid;
            bool bad = (mask[b * Tt + kg] == 0) ||
                       (iscdr && (cdrs[b * Tt + kg] == 0));
            kneg[tid] = bad ? NEG_INF : 0.f;
        }
        __syncthreads();

        float s[8][4] = {};
#pragma unroll
        for (int kc = 0; kc < 8; kc++) {
#pragma unroll
            for (int nt = 0; nt < 8; nt++) {
                uint32_t b0 = __float_as_uint(ks[(nt * 8 + g) * AP + kc * 8 + tig]);
                uint32_t b1 = __float_as_uint(ks[(nt * 8 + g) * AP + kc * 8 + tig + 4]);
                mma_tf32(s[nt], qa[kc], b0, b1);
            }
        }

#pragma unroll
        for (int nt = 0; nt < 8; nt++) {
            float k0b = kneg[nt * 8 + 2 * tig];
            float k1b = kneg[nt * 8 + 2 * tig + 1];
            s[nt][0] = s[nt][0] * 0.125f + k0b;
            s[nt][1] = s[nt][1] * 0.125f + k1b;
            s[nt][2] = s[nt][2] * 0.125f + k0b;
            s[nt][3] = s[nt][3] * 0.125f + k1b;
        }

        float mt0 = NEG_INF, mt1 = NEG_INF;
#pragma unroll
        for (int nt = 0; nt < 8; nt++) {
            mt0 = fmaxf(mt0, fmaxf(s[nt][0], s[nt][1]));
            mt1 = fmaxf(mt1, fmaxf(s[nt][2], s[nt][3]));
        }
#pragma unroll
        for (int off = 1; off < 4; off <<= 1) {
            mt0 = fmaxf(mt0, __shfl_xor_sync(0xffffffffu, mt0, off));
            mt1 = fmaxf(mt1, __shfl_xor_sync(0xffffffffu, mt1, off));
        }
        float mn0 = fmaxf(m_run[0], mt0);
        float mn1 = fmaxf(m_run[1], mt1);
        float alpha0, alpha1, sum0 = 0.f, sum1 = 0.f;
        if (mn0 == NEG_INF) {
            alpha0 = 1.f;
#pragma unroll
            for (int nt = 0; nt < 8; nt++) { s[nt][0] = 0.f; s[nt][1] = 0.f; }
        } else {
            alpha0 = __expf(m_run[0] - mn0);
#pragma unroll
            for (int nt = 0; nt < 8; nt++) {
                float p0 = __expf(s[nt][0] - mn0);
                float p1 = __expf(s[nt][1] - mn0);
                s[nt][0] = p0; s[nt][1] = p1;
                sum0 += p0 + p1;
            }
        }
        if (mn1 == NEG_INF) {
            alpha1 = 1.f;
#pragma unroll
            for (int nt = 0; nt < 8; nt++) { s[nt][2] = 0.f; s[nt][3] = 0.f; }
        } else {
            alpha1 = __expf(m_run[1] - mn1);
#pragma unroll
            for (int nt = 0; nt < 8; nt++) {
                float p0 = __expf(s[nt][2] - mn1);
                float p1 = __expf(s[nt][3] - mn1);
                s[nt][2] = p0; s[nt][3] = p1;
                sum1 += p0 + p1;
            }
        }
#pragma unroll
        for (int off = 1; off < 4; off <<= 1) {
            sum0 += __shfl_xor_sync(0xffffffffu, sum0, off);
            sum1 += __shfl_xor_sync(0xffffffffu, sum1, off);
        }
        m_run[0] = mn0;  l_run[0] = l_run[0] * alpha0 + sum0;
        m_run[1] = mn1;  l_run[1] = l_run[1] * alpha1 + sum1;

#pragma unroll
        for (int nt = 0; nt < 8; nt++) {
            o[nt][0] *= alpha0; o[nt][1] *= alpha0;
            o[nt][2] *= alpha1; o[nt][3] *= alpha1;
        }

#pragma unroll
        for (int nt = 0; nt < 8; nt++) {
            float2 w0, w1;
            w0.x = __uint_as_float(f2tf32(s[nt][0]));
            w0.y = __uint_as_float(f2tf32(s[nt][1]));
            w1.x = __uint_as_float(f2tf32(s[nt][2]));
            w1.y = __uint_as_float(f2tf32(s[nt][3]));
            *(float2*)&pw[g * AP + nt * 8 + 2 * tig]       = w0;
            *(float2*)&pw[(g + 8) * AP + nt * 8 + 2 * tig] = w1;
        }
        __syncwarp();

#pragma unroll
        for (int kc = 0; kc < 8; kc++) {
            uint32_t pa[4];
            pa[0] = __float_as_uint(pw[g * AP + kc * 8 + tig]);
            pa[1] = __float_as_uint(pw[(g + 8) * AP + kc * 8 + tig]);
            pa[2] = __float_as_uint(pw[g * AP + kc * 8 + tig + 4]);
            pa[3] = __float_as_uint(pw[(g + 8) * AP + kc * 8 + tig + 4]);
#pragma unroll
            for (int nt = 0; nt < 8; nt++) {
                uint32_t b0 = __float_as_uint(vs[(kc * 8 + tig) * AP + nt * 8 + g]);
                uint32_t b1 = __float_as_uint(vs[(kc * 8 + tig + 4) * AP + nt * 8 + g]);
                mma_tf32(o[nt], pa, b0, b1);
            }
        }
        __syncwarp();
    }

    float inv0 = 1.f / l_run[0];
    float inv1 = 1.f / l_run[1];
    float* ob0 = g_ctx + (b * Tt + q0 + r0) * Cc + h * Dd;
    float* ob1 = g_ctx + (b * Tt + q0 + r1) * Cc + h * Dd;
#pragma unroll
    for (int nt = 0; nt < 8; nt++) {
        float2 w0 = {o[nt][0] * inv0, o[nt][1] * inv0};
        float2 w1 = {o[nt][2] * inv1, o[nt][3] * inv1};
        *(float2*)&ob0[nt * 8 + 2 * tig] = w0;
        *(float2*)&ob1[nt * 8 + 2 * tig] = w1;
    }
}

// ---------------------------------------------------------------------------
// Launch
// ---------------------------------------------------------------------------
extern "C" void kernel_launch(void* const* d_in, const int* in_sizes, int n_in,
                              void* d_out, int out_size) {
    const float* x    = (const float*)d_in[0];
    const int*   mask = (const int*)d_in[1];
    const int*   cdrs = (const int*)d_in[2];
    const float* Wq   = (const float*)d_in[3];
    const float* bq   = (const float*)d_in[4];
    const float* Wk   = (const float*)d_in[5];
    const float* bk   = (const float*)d_in[6];
    const float* Wv   = (const float*)d_in[7];
    const float* bv   = (const float*)d_in[8];
    const float* Wo   = (const float*)d_in[9];
    const float* bo   = (const float*)d_in[10];
    float* out = (float*)d_out;

    allm_kernel<<<Bb, 256>>>(cdrs);

    dim3 gqkv(Bb * Tt / 128, Cc / 128, 3);
    gemm_qkv<<<gqkv, 256>>>(x, Wq, bq, Wk, bk, Wv, bv);

    size_t shbytes = (size_t)(64 * AP + 64 * AP + 128 * AP) * sizeof(float);
    cudaFuncSetAttribute(attn_kernel, cudaFuncAttributeMaxDynamicSharedMemorySize,
                         (int)shbytes);
    dim3 gatt(Tt / 128, Hh, Bb);
    attn_kernel<<<gatt, 256, shbytes>>>(mask, cdrs);

    dim3 gout(Bb * Tt / 128, Cc / 128, 1);
    gemm_out<<<gout, 256>>>(Wo, bo, out);
}

// round 5
// speedup vs baseline: 5.6209x; 2.1050x over previous
#include <cuda_runtime.h>
#include <cuda_fp16.h>
#include <cstdint>

// Problem constants
#define Bb   4
#define Tt   2048
#define Cc   512
#define Hh   8
#define Dd   64
#define CDRH 2

#define NEG_INF __int_as_float(0xff800000)

// Scratch (allocation-free: module-static device globals)
__device__ __half g_qh[Bb * Tt * Cc];
__device__ __half g_kh[Bb * Tt * Cc];
__device__ __half g_vh[Bb * Tt * Cc];
__device__ float  g_ctx[Bb * Tt * Cc];
__device__ int    g_allm[Bb];

// ---------------------------------------------------------------------------
// helpers
// ---------------------------------------------------------------------------
__device__ __forceinline__ uint32_t f2tf32(float x) {
    uint32_t r;
    asm("cvt.rna.tf32.f32 %0, %1;" : "=r"(r) : "f"(x));
    return r;
}

__device__ __forceinline__ void mma_tf32(float c[4], const uint32_t a[4],
                                         uint32_t b0, uint32_t b1) {
    asm volatile(
        "mma.sync.aligned.m16n8k8.row.col.f32.tf32.tf32.f32 "
        "{%0,%1,%2,%3}, {%4,%5,%6,%7}, {%8,%9}, {%0,%1,%2,%3};"
        : "+f"(c[0]), "+f"(c[1]), "+f"(c[2]), "+f"(c[3])
        : "r"(a[0]), "r"(a[1]), "r"(a[2]), "r"(a[3]), "r"(b0), "r"(b1));
}

__device__ __forceinline__ void mma_f16(float c[4], const uint32_t a[4],
                                        uint32_t b0, uint32_t b1) {
    asm volatile(
        "mma.sync.aligned.m16n8k16.row.col.f32.f16.f16.f32 "
        "{%0,%1,%2,%3}, {%4,%5,%6,%7}, {%8,%9}, {%0,%1,%2,%3};"
        : "+f"(c[0]), "+f"(c[1]), "+f"(c[2]), "+f"(c[3])
        : "r"(a[0]), "r"(a[1]), "r"(a[2]), "r"(a[3]), "r"(b0), "r"(b1));
}

__device__ __forceinline__ void ldsm_x4(uint32_t r[4], uint32_t addr) {
    asm volatile("ldmatrix.sync.aligned.m8n8.x4.shared.b16 {%0,%1,%2,%3}, [%4];"
                 : "=r"(r[0]), "=r"(r[1]), "=r"(r[2]), "=r"(r[3]) : "r"(addr));
}

__device__ __forceinline__ void ldsm_x4_t(uint32_t r[4], uint32_t addr) {
    asm volatile("ldmatrix.sync.aligned.m8n8.x4.trans.shared.b16 {%0,%1,%2,%3}, [%4];"
                 : "=r"(r[0]), "=r"(r[1]), "=r"(r[2]), "=r"(r[3]) : "r"(addr));
}

__device__ __forceinline__ uint32_t h2u(__half2 h) {
    return *reinterpret_cast<uint32_t*>(&h);
}

// ---------------------------------------------------------------------------
// Per-batch "all CDR tokens masked" flag
// ---------------------------------------------------------------------------
__global__ void allm_kernel(const int* __restrict__ cdrs) {
    __shared__ int any;
    int b = blockIdx.x;
    if (threadIdx.x == 0) any = 0;
    __syncthreads();
    int local = 0;
    for (int t = threadIdx.x; t < Tt; t += blockDim.x)
        local |= (cdrs[b * Tt + t] != 0);
    if (local) any = 1;
    __syncthreads();
    if (threadIdx.x == 0) g_allm[b] = (any == 0) ? 1 : 0;
}

// ---------------------------------------------------------------------------
// TF32 tensor-core GEMM: out[M,512] = A[M,512] @ W[512,512] + bias
// BM=BN=128, BK=16; 8 warps (2m x 4n); warp tile 64x32 via m16n8k8.
// OutT = __half (QKV scratch) or float (final output).
// ---------------------------------------------------------------------------
template <typename OutT>
__device__ __forceinline__ void gemm_tf32_body(const float* __restrict__ A,
                                               const float* __restrict__ W,
                                               const float* __restrict__ bias,
                                               OutT* __restrict__ out) {
    __shared__ float As[16][132];   // [k][m], tf32 bits
    __shared__ float Bs[16][132];   // [k][n], tf32 bits
    const int tid  = threadIdx.x;
    const int warp = tid >> 5;
    const int lane = tid & 31;
    const int g    = lane >> 2;
    const int tig  = lane & 3;
    const int wm   = warp >> 2;
    const int wn   = warp & 3;
    const int m0 = blockIdx.x * 128, n0 = blockIdx.y * 128;

    float acc[4][4][4] = {};

    for (int k0 = 0; k0 < Cc; k0 += 16) {
#pragma unroll
        for (int p = 0; p < 8; p++) {
            int m = p * 16 + (tid >> 4);
            int k = tid & 15;
            As[k][m] = __uint_as_float(f2tf32(A[(m0 + m) * Cc + k0 + k]));
        }
#pragma unroll
        for (int p = 0; p < 8; p++) {
            int k = p * 2 + (tid >> 7);
            int n = tid & 127;
            Bs[k][n] = __uint_as_float(f2tf32(W[(k0 + k) * Cc + n0 + n]));
        }
        __syncthreads();

#pragma unroll
        for (int kc = 0; kc < 2; kc++) {
            uint32_t af[4][4];
#pragma unroll
            for (int mt = 0; mt < 4; mt++) {
                int r = wm * 64 + mt * 16 + g;
                af[mt][0] = __float_as_uint(As[kc * 8 + tig][r]);
                af[mt][1] = __float_as_uint(As[kc * 8 + tig][r + 8]);
                af[mt][2] = __float_as_uint(As[kc * 8 + tig + 4][r]);
                af[mt][3] = __float_as_uint(As[kc * 8 + tig + 4][r + 8]);
            }
            uint32_t bf[4][2];
#pragma unroll
            for (int nt = 0; nt < 4; nt++) {
                int n = wn * 32 + nt * 8 + g;
                bf[nt][0] = __float_as_uint(Bs[kc * 8 + tig][n]);
                bf[nt][1] = __float_as_uint(Bs[kc * 8 + tig + 4][n]);
            }
#pragma unroll
            for (int mt = 0; mt < 4; mt++)
#pragma unroll
                for (int nt = 0; nt < 4; nt++)
                    mma_tf32(acc[mt][nt], af[mt], bf[nt][0], bf[nt][1]);
        }
        __syncthreads();
    }

#pragma unroll
    for (int mt = 0; mt < 4; mt++) {
        int r0g = m0 + wm * 64 + mt * 16 + g;
        int r1g = r0g + 8;
#pragma unroll
        for (int nt = 0; nt < 4; nt++) {
            int n = n0 + wn * 32 + nt * 8 + 2 * tig;
            float b0 = bias[n], b1 = bias[n + 1];
            float v00 = acc[mt][nt][0] + b0, v01 = acc[mt][nt][1] + b1;
            float v10 = acc[mt][nt][2] + b0, v11 = acc[mt][nt][3] + b1;
            if constexpr (sizeof(OutT) == 2) {
                __half2 w0 = __floats2half2_rn(v00, v01);
                __half2 w1 = __floats2half2_rn(v10, v11);
                *(uint32_t*)&out[r0g * Cc + n] = h2u(w0);
                *(uint32_t*)&out[r1g * Cc + n] = h2u(w1);
            } else {
                float2 w0 = {v00, v01};
                float2 w1 = {v10, v11};
                *(float2*)&out[r0g * Cc + n] = w0;
                *(float2*)&out[r1g * Cc + n] = w1;
            }
        }
    }
}

__global__ __launch_bounds__(256)
void gemm_qkv(const float* __restrict__ x,
              const float* __restrict__ Wq, const float* __restrict__ bq,
              const float* __restrict__ Wk, const float* __restrict__ bk,
              const float* __restrict__ Wv, const float* __restrict__ bv) {
    const float* W; const float* bi; __half* out;
    if (blockIdx.z == 0)      { W = Wq; bi = bq; out = g_qh; }
    else if (blockIdx.z == 1) { W = Wk; bi = bk; out = g_kh; }
    else                      { W = Wv; bi = bv; out = g_vh; }
    gemm_tf32_body<__half>(x, W, bi, out);
}

__global__ __launch_bounds__(256)
void gemm_out(const float* __restrict__ Wo, const float* __restrict__ bo,
              float* __restrict__ out) {
    gemm_tf32_body<float>(g_ctx, Wo, bo, out);
}

// ---------------------------------------------------------------------------
// fp16 tensor-core flash attention with ldmatrix fragment feeds.
// Block = (128-query tile, head, batch), 8 warps; warp owns 16 q rows.
// m16n8k16: QK^T (K frags via ldmatrix), PV (V frags via ldmatrix.trans;
// P stays in registers — C-layout of S == A-layout of PV).
// ---------------------------------------------------------------------------
#define QP 72   // smem pitch in halves (144 B): LDSM phase-conflict-free

__global__ __launch_bounds__(256)
void attn_kernel(const int* __restrict__ mask, const int* __restrict__ cdrs) {
    extern __shared__ __align__(16) __half sh[];
    __half* qs = sh;                 // [128][QP]
    __half* ks = sh + 128 * QP;      // [64][QP]
    __half* vs = ks + 64 * QP;       // [64][QP]

    __shared__ __align__(16) float kneg[64];

    const int q0   = blockIdx.x * 128;
    const int h    = blockIdx.y;
    const int b    = blockIdx.z;
    const int tid  = threadIdx.x;
    const int warp = tid >> 5;
    const int lane = tid & 31;
    const int g    = lane >> 2;      // 0..7
    const int tig  = lane & 3;       // 0..3
    const int mf   = lane >> 3;      // ldmatrix matrix id 0..3
    const int rr   = lane & 7;       // ldmatrix row within matrix

    const bool iscdr = (h < CDRH) && (g_allm[b] == 0);

    // ---- stage Q tile (raw half copy) ----
    const __half* qbase = g_qh + (size_t)(b * Tt + q0) * Cc + h * Dd;
    for (int i = tid; i < 128 * 8; i += 256) {
        int r = i >> 3, c8 = i & 7;
        *(uint4*)&qs[r * QP + c8 * 8] = *(const uint4*)(qbase + r * Cc + c8 * 8);
    }
    __syncthreads();

    const uint32_t qs_u = (uint32_t)__cvta_generic_to_shared(qs);
    const uint32_t ks_u = (uint32_t)__cvta_generic_to_shared(ks);
    const uint32_t vs_u = (uint32_t)__cvta_generic_to_shared(vs);

    // ---- hoist Q A-fragments: 4 k-chunks of 16 over D=64 ----
    uint32_t qa[4][4];
#pragma unroll
    for (int kc = 0; kc < 4; kc++) {
        int row = warp * 16 + rr + (mf & 1) * 8;
        int col = kc * 16 + (mf >> 1) * 8;
        ldsm_x4(qa[kc], qs_u + (row * QP + col) * 2);
    }

    float m_run[2] = {NEG_INF, NEG_INF};
    float l_run[2] = {0.f, 0.f};
    float o[8][4] = {};

    for (int kt = 0; kt < Tt / 64; kt++) {
        const int k0 = kt * 64;
        __syncthreads();   // ks/vs consumed by all warps in prev iter

        const __half* kbase = g_kh + (size_t)(b * Tt + k0) * Cc + h * Dd;
        const __half* vbase = g_vh + (size_t)(b * Tt + k0) * Cc + h * Dd;
        for (int i = tid; i < 64 * 8; i += 256) {
            int r = i >> 3, c8 = i & 7;
            *(uint4*)&ks[r * QP + c8 * 8] = *(const uint4*)(kbase + r * Cc + c8 * 8);
            *(uint4*)&vs[r * QP + c8 * 8] = *(const uint4*)(vbase + r * Cc + c8 * 8);
        }
        if (tid < 64) {
            int kg = k0 + tid;
            bool bad = (mask[b * Tt + kg] == 0) ||
                       (iscdr && (cdrs[b * Tt + kg] == 0));
            kneg[tid] = bad ? NEG_INF : 0.f;
        }
        __syncthreads();

        // ---- S = Q K^T ----
        float s[8][4] = {};
#pragma unroll
        for (int kc = 0; kc < 4; kc++) {
#pragma unroll
            for (int p = 0; p < 4; p++) {
                // m0:(nt=2p,klo) m1:(2p,khi) m2:(2p+1,klo) m3:(2p+1,khi)
                int key = (2 * p + (mf >> 1)) * 8 + rr;
                int d   = kc * 16 + (mf & 1) * 8;
                uint32_t bk[4];
                ldsm_x4(bk, ks_u + (key * QP + d) * 2);
                mma_f16(s[2 * p],     qa[kc], bk[0], bk[1]);
                mma_f16(s[2 * p + 1], qa[kc], bk[2], bk[3]);
            }
        }

        // ---- scale + key-mask bias ----
#pragma unroll
        for (int nt = 0; nt < 8; nt++) {
            float k0b = kneg[nt * 8 + 2 * tig];
            float k1b = kneg[nt * 8 + 2 * tig + 1];
            s[nt][0] = s[nt][0] * 0.125f + k0b;
            s[nt][1] = s[nt][1] * 0.125f + k1b;
            s[nt][2] = s[nt][2] * 0.125f + k0b;
            s[nt][3] = s[nt][3] * 0.125f + k1b;
        }

        // ---- online softmax (rows r0 = warp*16+g, r1 = +8) ----
        float mt0 = NEG_INF, mt1 = NEG_INF;
#pragma unroll
        for (int nt = 0; nt < 8; nt++) {
            mt0 = fmaxf(mt0, fmaxf(s[nt][0], s[nt][1]));
            mt1 = fmaxf(mt1, fmaxf(s[nt][2], s[nt][3]));
        }
#pragma unroll
        for (int off = 1; off < 4; off <<= 1) {
            mt0 = fmaxf(mt0, __shfl_xor_sync(0xffffffffu, mt0, off));
            mt1 = fmaxf(mt1, __shfl_xor_sync(0xffffffffu, mt1, off));
        }
        float mn0 = fmaxf(m_run[0], mt0);
        float mn1 = fmaxf(m_run[1], mt1);
        float alpha0, alpha1, sum0 = 0.f, sum1 = 0.f;
        if (mn0 == NEG_INF) {
            alpha0 = 1.f;
#pragma unroll
            for (int nt = 0; nt < 8; nt++) { s[nt][0] = 0.f; s[nt][1] = 0.f; }
        } else {
            alpha0 = __expf(m_run[0] - mn0);
#pragma unroll
            for (int nt = 0; nt < 8; nt++) {
                float p0 = __expf(s[nt][0] - mn0);
                float p1 = __expf(s[nt][1] - mn0);
                s[nt][0] = p0; s[nt][1] = p1;
                sum0 += p0 + p1;
            }
        }
        if (mn1 == NEG_INF) {
            alpha1 = 1.f;
#pragma unroll
            for (int nt = 0; nt < 8; nt++) { s[nt][2] = 0.f; s[nt][3] = 0.f; }
        } else {
            alpha1 = __expf(m_run[1] - mn1);
#pragma unroll
            for (int nt = 0; nt < 8; nt++) {
                float p0 = __expf(s[nt][2] - mn1);
                float p1 = __expf(s[nt][3] - mn1);
                s[nt][2] = p0; s[nt][3] = p1;
                sum1 += p0 + p1;
            }
        }
#pragma unroll
        for (int off = 1; off < 4; off <<= 1) {
            sum0 += __shfl_xor_sync(0xffffffffu, sum0, off);
            sum1 += __shfl_xor_sync(0xffffffffu, sum1, off);
        }
        m_run[0] = mn0;  l_run[0] = l_run[0] * alpha0 + sum0;
        m_run[1] = mn1;  l_run[1] = l_run[1] * alpha1 + sum1;

#pragma unroll
        for (int nt = 0; nt < 8; nt++) {
            o[nt][0] *= alpha0; o[nt][1] *= alpha0;
            o[nt][2] *= alpha1; o[nt][3] *= alpha1;
        }

        // ---- O += P @ V : P converts reg->reg into A-fragments ----
#pragma unroll
        for (int kc = 0; kc < 4; kc++) {
            uint32_t pa[4];
            pa[0] = h2u(__floats2half2_rn(s[2 * kc][0],     s[2 * kc][1]));
            pa[1] = h2u(__floats2half2_rn(s[2 * kc][2],     s[2 * kc][3]));
            pa[2] = h2u(__floats2half2_rn(s[2 * kc + 1][0], s[2 * kc + 1][1]));
            pa[3] = h2u(__floats2half2_rn(s[2 * kc + 1][2], s[2 * kc + 1][3]));
#pragma unroll
            for (int p = 0; p < 4; p++) {
                // m0:b0(nt=2p) m1:b1(2p) m2:b0(2p+1) m3:b1(2p+1); k = key dim
                int key = kc * 16 + (mf & 1) * 8 + rr;
                int d   = (2 * p + (mf >> 1)) * 8;
                uint32_t bv[4];
                ldsm_x4_t(bv, vs_u + (key * QP + d) * 2);
                mma_f16(o[2 * p],     pa, bv[0], bv[1]);
                mma_f16(o[2 * p + 1], pa, bv[2], bv[3]);
            }
        }
    }

    // ---- epilogue: normalize, write ctx [B, T, C] (fp32) ----
    const int r0 = warp * 16 + g;
    const int r1 = r0 + 8;
    float inv0 = 1.f / l_run[0];
    float inv1 = 1.f / l_run[1];
    float* ob0 = g_ctx + (size_t)(b * Tt + q0 + r0) * Cc + h * Dd;
    float* ob1 = g_ctx + (size_t)(b * Tt + q0 + r1) * Cc + h * Dd;
#pragma unroll
    for (int nt = 0; nt < 8; nt++) {
        float2 w0 = {o[nt][0] * inv0, o[nt][1] * inv0};
        float2 w1 = {o[nt][2] * inv1, o[nt][3] * inv1};
        *(float2*)&ob0[nt * 8 + 2 * tig] = w0;
        *(float2*)&ob1[nt * 8 + 2 * tig] = w1;
    }
}

// ---------------------------------------------------------------------------
// Launch
// ---------------------------------------------------------------------------
extern "C" void kernel_launch(void* const* d_in, const int* in_sizes, int n_in,
                              void* d_out, int out_size) {
    const float* x    = (const float*)d_in[0];
    const int*   mask = (const int*)d_in[1];
    const int*   cdrs = (const int*)d_in[2];
    const float* Wq   = (const float*)d_in[3];
    const float* bq   = (const float*)d_in[4];
    const float* Wk   = (const float*)d_in[5];
    const float* bk   = (const float*)d_in[6];
    const float* Wv   = (const float*)d_in[7];
    const float* bv   = (const float*)d_in[8];
    const float* Wo   = (const float*)d_in[9];
    const float* bo   = (const float*)d_in[10];
    float* out = (float*)d_out;

    allm_kernel<<<Bb, 256>>>(cdrs);

    dim3 gqkv(Bb * Tt / 128, Cc / 128, 3);
    gemm_qkv<<<gqkv, 256>>>(x, Wq, bq, Wk, bk, Wv, bv);

    size_t shbytes = (size_t)(128 + 64 + 64) * QP * sizeof(__half);  // 36864
    cudaFuncSetAttribute(attn_kernel, cudaFuncAttributeMaxDynamicSharedMemorySize,
                         (int)shbytes);
    dim3 gatt(Tt / 128, Hh, Bb);
    attn_kernel<<<gatt, 256, shbytes>>>(mask, cdrs);

    dim3 gout(Bb * Tt / 128, Cc / 128, 1);
    gemm_out<<<gout, 256>>>(Wo, bo, out);
}

// round 6
// speedup vs baseline: 8.3367x; 1.4832x over previous
#include <cuda_runtime.h>
#include <cuda_fp16.h>
#include <cstdint>

// Problem constants
#define Bb   4
#define Tt   2048
#define Cc   512
#define Hh   8
#define Dd   64
#define CDRH 2

#define NEG_INF __int_as_float(0xff800000)

// Scratch (allocation-free: module-static device globals)
__device__ __half g_qh[Bb * Tt * Cc];
__device__ __half g_kh[Bb * Tt * Cc];
__device__ __half g_vh[Bb * Tt * Cc];
__device__ float  g_ctx[Bb * Tt * Cc];
__device__ int    g_allm[Bb];

// ---------------------------------------------------------------------------
// helpers
// ---------------------------------------------------------------------------
__device__ __forceinline__ void mma_f16(float c[4], const uint32_t a[4],
                                        uint32_t b0, uint32_t b1) {
    asm volatile(
        "mma.sync.aligned.m16n8k16.row.col.f32.f16.f16.f32 "
        "{%0,%1,%2,%3}, {%4,%5,%6,%7}, {%8,%9}, {%0,%1,%2,%3};"
        : "+f"(c[0]), "+f"(c[1]), "+f"(c[2]), "+f"(c[3])
        : "r"(a[0]), "r"(a[1]), "r"(a[2]), "r"(a[3]), "r"(b0), "r"(b1));
}

__device__ __forceinline__ void ldsm_x4(uint32_t r[4], uint32_t addr) {
    asm volatile("ldmatrix.sync.aligned.m8n8.x4.shared.b16 {%0,%1,%2,%3}, [%4];"
                 : "=r"(r[0]), "=r"(r[1]), "=r"(r[2]), "=r"(r[3]) : "r"(addr));
}

__device__ __forceinline__ void ldsm_x4_t(uint32_t r[4], uint32_t addr) {
    asm volatile("ldmatrix.sync.aligned.m8n8.x4.trans.shared.b16 {%0,%1,%2,%3}, [%4];"
                 : "=r"(r[0]), "=r"(r[1]), "=r"(r[2]), "=r"(r[3]) : "r"(addr));
}

__device__ __forceinline__ uint32_t h2u(__half2 h) {
    return *reinterpret_cast<uint32_t*>(&h);
}

// ---------------------------------------------------------------------------
// Per-batch "all CDR tokens masked" flag
// ---------------------------------------------------------------------------
__global__ void allm_kernel(const int* __restrict__ cdrs) {
    __shared__ int any;
    int b = blockIdx.x;
    if (threadIdx.x == 0) any = 0;
    __syncthreads();
    int local = 0;
    for (int t = threadIdx.x; t < Tt; t += blockDim.x)
        local |= (cdrs[b * Tt + t] != 0);
    if (local) any = 1;
    __syncthreads();
    if (threadIdx.x == 0) g_allm[b] = (any == 0) ? 1 : 0;
}

// ---------------------------------------------------------------------------
// fp16 tensor-core GEMM: out[M,512] = A[M,512] @ W[512,512] + bias
// BM=BN=128, BK=32; 8 warps (2m x 4n); warp tile 64x32 via m16n8k16 + LDSM.
// A-fragments: ldmatrix (As[m][k]); B-fragments: ldmatrix.trans (Bs[k][n]).
// OutT = __half (QKV scratch) or float (final output).
// ---------------------------------------------------------------------------
#define APIT 40    // As pitch in halves (80 B  -> LDSM rows distinct mod 128)
#define BPIT 136   // Bs pitch in halves (272 B -> LDSM rows distinct mod 128)

template <typename OutT>
__device__ __forceinline__ void gemm_f16_body(const float* __restrict__ A,
                                              const float* __restrict__ W,
                                              const float* __restrict__ bias,
                                              OutT* __restrict__ out) {
    __shared__ __align__(16) __half As[128][APIT];   // [m][k]
    __shared__ __align__(16) __half Bs[32][BPIT];    // [k][n]
    const int tid  = threadIdx.x;
    const int warp = tid >> 5;
    const int lane = tid & 31;
    const int g    = lane >> 2;
    const int tig  = lane & 3;
    const int mf   = lane >> 3;     // ldmatrix matrix id 0..3
    const int rr   = lane & 7;      // ldmatrix row within matrix
    const int wm   = warp >> 2;     // 0..1
    const int wn   = warp & 3;      // 0..3
    const int m0 = blockIdx.x * 128, n0 = blockIdx.y * 128;

    const uint32_t as_u = (uint32_t)__cvta_generic_to_shared(&As[0][0]);
    const uint32_t bs_u = (uint32_t)__cvta_generic_to_shared(&Bs[0][0]);

    float acc[4][4][4] = {};

    for (int k0 = 0; k0 < Cc; k0 += 32) {
        // load A tile: 128 x 32, convert fp32 -> half
#pragma unroll
        for (int p = 0; p < 4; p++) {
            int li = p * 256 + tid;
            int r  = li >> 3;
            int c  = (li & 7) * 4;
            float4 v = *(const float4*)&A[(m0 + r) * Cc + k0 + c];
            *(uint32_t*)&As[r][c]     = h2u(__floats2half2_rn(v.x, v.y));
            *(uint32_t*)&As[r][c + 2] = h2u(__floats2half2_rn(v.z, v.w));
        }
        // load W tile: 32 x 128 (coalesced on n), convert fp32 -> half
#pragma unroll
        for (int p = 0; p < 4; p++) {
            int li = p * 256 + tid;
            int r  = li >> 5;
            int c  = (li & 31) * 4;
            float4 v = *(const float4*)&W[(k0 + r) * Cc + n0 + c];
            *(uint32_t*)&Bs[r][c]     = h2u(__floats2half2_rn(v.x, v.y));
            *(uint32_t*)&Bs[r][c + 2] = h2u(__floats2half2_rn(v.z, v.w));
        }
        __syncthreads();

#pragma unroll
        for (int kc = 0; kc < 2; kc++) {
            uint32_t af[4][4];
#pragma unroll
            for (int mt = 0; mt < 4; mt++) {
                int row = wm * 64 + mt * 16 + rr + (mf & 1) * 8;
                int col = kc * 16 + (mf >> 1) * 8;
                ldsm_x4(af[mt], as_u + (row * APIT + col) * 2);
            }
            uint32_t bf[2][4];
#pragma unroll
            for (int p = 0; p < 2; p++) {
                int krow = kc * 16 + (mf & 1) * 8 + rr;
                int ncol = wn * 32 + (2 * p + (mf >> 1)) * 8;
                ldsm_x4_t(bf[p], bs_u + (krow * BPIT + ncol) * 2);
            }
#pragma unroll
            for (int mt = 0; mt < 4; mt++)
#pragma unroll
                for (int p = 0; p < 2; p++) {
                    mma_f16(acc[mt][2 * p],     af[mt], bf[p][0], bf[p][1]);
                    mma_f16(acc[mt][2 * p + 1], af[mt], bf[p][2], bf[p][3]);
                }
        }
        __syncthreads();
    }

    // epilogue: add bias, store (C frag: rows g, g+8; cols 2*tig, 2*tig+1)
#pragma unroll
    for (int mt = 0; mt < 4; mt++) {
        int r0g = m0 + wm * 64 + mt * 16 + g;
        int r1g = r0g + 8;
#pragma unroll
        for (int nt = 0; nt < 4; nt++) {
            int n = n0 + wn * 32 + nt * 8 + 2 * tig;
            float b0 = bias[n], b1 = bias[n + 1];
            float v00 = acc[mt][nt][0] + b0, v01 = acc[mt][nt][1] + b1;
            float v10 = acc[mt][nt][2] + b0, v11 = acc[mt][nt][3] + b1;
            if constexpr (sizeof(OutT) == 2) {
                *(uint32_t*)&out[r0g * Cc + n] = h2u(__floats2half2_rn(v00, v01));
                *(uint32_t*)&out[r1g * Cc + n] = h2u(__floats2half2_rn(v10, v11));
            } else {
                float2 w0 = {v00, v01};
                float2 w1 = {v10, v11};
                *(float2*)&out[r0g * Cc + n] = w0;
                *(float2*)&out[r1g * Cc + n] = w1;
            }
        }
    }
}

__global__ __launch_bounds__(256)
void gemm_qkv(const float* __restrict__ x,
              const float* __restrict__ Wq, const float* __restrict__ bq,
              const float* __restrict__ Wk, const float* __restrict__ bk,
              const float* __restrict__ Wv, const float* __restrict__ bv) {
    const float* W; const float* bi; __half* out;
    if (blockIdx.z == 0)      { W = Wq; bi = bq; out = g_qh; }
    else if (blockIdx.z == 1) { W = Wk; bi = bk; out = g_kh; }
    else                      { W = Wv; bi = bv; out = g_vh; }
    gemm_f16_body<__half>(x, W, bi, out);
}

__global__ __launch_bounds__(256)
void gemm_out(const float* __restrict__ Wo, const float* __restrict__ bo,
              float* __restrict__ out) {
    gemm_f16_body<float>(g_ctx, Wo, bo, out);
}

// ---------------------------------------------------------------------------
// fp16 tensor-core flash attention (unchanged from round 5).
// ---------------------------------------------------------------------------
#define QP 72

__global__ __launch_bounds__(256)
void attn_kernel(const int* __restrict__ mask, const int* __restrict__ cdrs) {
    extern __shared__ __align__(16) __half sh[];
    __half* qs = sh;                 // [128][QP]
    __half* ks = sh + 128 * QP;      // [64][QP]
    __half* vs = ks + 64 * QP;       // [64][QP]

    __shared__ __align__(16) float kneg[64];

    const int q0   = blockIdx.x * 128;
    const int h    = blockIdx.y;
    const int b    = blockIdx.z;
    const int tid  = threadIdx.x;
    const int warp = tid >> 5;
    const int lane = tid & 31;
    const int g    = lane >> 2;
    const int tig  = lane & 3;
    const int mf   = lane >> 3;
    const int rr   = lane & 7;

    const bool iscdr = (h < CDRH) && (g_allm[b] == 0);

    const __half* qbase = g_qh + (size_t)(b * Tt + q0) * Cc + h * Dd;
    for (int i = tid; i < 128 * 8; i += 256) {
        int r = i >> 3, c8 = i & 7;
        *(uint4*)&qs[r * QP + c8 * 8] = *(const uint4*)(qbase + r * Cc + c8 * 8);
    }
    __syncthreads();

    const uint32_t qs_u = (uint32_t)__cvta_generic_to_shared(qs);
    const uint32_t ks_u = (uint32_t)__cvta_generic_to_shared(ks);
    const uint32_t vs_u = (uint32_t)__cvta_generic_to_shared(vs);

    uint32_t qa[4][4];
#pragma unroll
    for (int kc = 0; kc < 4; kc++) {
        int row = warp * 16 + rr + (mf & 1) * 8;
        int col = kc * 16 + (mf >> 1) * 8;
        ldsm_x4(qa[kc], qs_u + (row * QP + col) * 2);
    }

    float m_run[2] = {NEG_INF, NEG_INF};
    float l_run[2] = {0.f, 0.f};
    float o[8][4] = {};

    for (int kt = 0; kt < Tt / 64; kt++) {
        const int k0 = kt * 64;
        __syncthreads();

        const __half* kbase = g_kh + (size_t)(b * Tt + k0) * Cc + h * Dd;
        const __half* vbase = g_vh + (size_t)(b * Tt + k0) * Cc + h * Dd;
        for (int i = tid; i < 64 * 8; i += 256) {
            int r = i >> 3, c8 = i & 7;
            *(uint4*)&ks[r * QP + c8 * 8] = *(const uint4*)(kbase + r * Cc + c8 * 8);
            *(uint4*)&vs[r * QP + c8 * 8] = *(const uint4*)(vbase + r * Cc + c8 * 8);
        }
        if (tid < 64) {
            int kg = k0 + tid;
            bool bad = (mask[b * Tt + kg] == 0) ||
                       (iscdr && (cdrs[b * Tt + kg] == 0));
            kneg[tid] = bad ? NEG_INF : 0.f;
        }
        __syncthreads();

        float s[8][4] = {};
#pragma unroll
        for (int kc = 0; kc < 4; kc++) {
#pragma unroll
            for (int p = 0; p < 4; p++) {
                int key = (2 * p + (mf >> 1)) * 8 + rr;
                int d   = kc * 16 + (mf & 1) * 8;
                uint32_t bk[4];
                ldsm_x4(bk, ks_u + (key * QP + d) * 2);
                mma_f16(s[2 * p],     qa[kc], bk[0], bk[1]);
                mma_f16(s[2 * p + 1], qa[kc], bk[2], bk[3]);
            }
        }

#pragma unroll
        for (int nt = 0; nt < 8; nt++) {
            float k0b = kneg[nt * 8 + 2 * tig];
            float k1b = kneg[nt * 8 + 2 * tig + 1];
            s[nt][0] = s[nt][0] * 0.125f + k0b;
            s[nt][1] = s[nt][1] * 0.125f + k1b;
            s[nt][2] = s[nt][2] * 0.125f + k0b;
            s[nt][3] = s[nt][3] * 0.125f + k1b;
        }

        float mt0 = NEG_INF, mt1 = NEG_INF;
#pragma unroll
        for (int nt = 0; nt < 8; nt++) {
            mt0 = fmaxf(mt0, fmaxf(s[nt][0], s[nt][1]));
            mt1 = fmaxf(mt1, fmaxf(s[nt][2], s[nt][3]));
        }
#pragma unroll
        for (int off = 1; off < 4; off <<= 1) {
            mt0 = fmaxf(mt0, __shfl_xor_sync(0xffffffffu, mt0, off));
            mt1 = fmaxf(mt1, __shfl_xor_sync(0xffffffffu, mt1, off));
        }
        float mn0 = fmaxf(m_run[0], mt0);
        float mn1 = fmaxf(m_run[1], mt1);
        float alpha0, alpha1, sum0 = 0.f, sum1 = 0.f;
        if (mn0 == NEG_INF) {
            alpha0 = 1.f;
#pragma unroll
            for (int nt = 0; nt < 8; nt++) { s[nt][0] = 0.f; s[nt][1] = 0.f; }
        } else {
            alpha0 = __expf(m_run[0] - mn0);
#pragma unroll
            for (int nt = 0; nt < 8; nt++) {
                float p0 = __expf(s[nt][0] - mn0);
                float p1 = __expf(s[nt][1] - mn0);
                s[nt][0] = p0; s[nt][1] = p1;
                sum0 += p0 + p1;
            }
        }
        if (mn1 == NEG_INF) {
            alpha1 = 1.f;
#pragma unroll
            for (int nt = 0; nt < 8; nt++) { s[nt][2] = 0.f; s[nt][3] = 0.f; }
        } else {
            alpha1 = __expf(m_run[1] - mn1);
#pragma unroll
            for (int nt = 0; nt < 8; nt++) {
                float p0 = __expf(s[nt][2] - mn1);
                float p1 = __expf(s[nt][3] - mn1);
                s[nt][2] = p0; s[nt][3] = p1;
                sum1 += p0 + p1;
            }
        }
#pragma unroll
        for (int off = 1; off < 4; off <<= 1) {
            sum0 += __shfl_xor_sync(0xffffffffu, sum0, off);
            sum1 += __shfl_xor_sync(0xffffffffu, sum1, off);
        }
        m_run[0] = mn0;  l_run[0] = l_run[0] * alpha0 + sum0;
        m_run[1] = mn1;  l_run[1] = l_run[1] * alpha1 + sum1;

#pragma unroll
        for (int nt = 0; nt < 8; nt++) {
            o[nt][0] *= alpha0; o[nt][1] *= alpha0;
            o[nt][2] *= alpha1; o[nt][3] *= alpha1;
        }

#pragma unroll
        for (int kc = 0; kc < 4; kc++) {
            uint32_t pa[4];
            pa[0] = h2u(__floats2half2_rn(s[2 * kc][0],     s[2 * kc][1]));
            pa[1] = h2u(__floats2half2_rn(s[2 * kc][2],     s[2 * kc][3]));
            pa[2] = h2u(__floats2half2_rn(s[2 * kc + 1][0], s[2 * kc + 1][1]));
            pa[3] = h2u(__floats2half2_rn(s[2 * kc + 1][2], s[2 * kc + 1][3]));
#pragma unroll
            for (int p = 0; p < 4; p++) {
                int key = kc * 16 + (mf & 1) * 8 + rr;
                int d   = (2 * p + (mf >> 1)) * 8;
                uint32_t bv[4];
                ldsm_x4_t(bv, vs_u + (key * QP + d) * 2);
                mma_f16(o[2 * p],     pa, bv[0], bv[1]);
                mma_f16(o[2 * p + 1], pa, bv[2], bv[3]);
            }
        }
    }

    const int r0 = warp * 16 + g;
    const int r1 = r0 + 8;
    float inv0 = 1.f / l_run[0];
    float inv1 = 1.f / l_run[1];
    float* ob0 = g_ctx + (size_t)(b * Tt + q0 + r0) * Cc + h * Dd;
    float* ob1 = g_ctx + (size_t)(b * Tt + q0 + r1) * Cc + h * Dd;
#pragma unroll
    for (int nt = 0; nt < 8; nt++) {
        float2 w0 = {o[nt][0] * inv0, o[nt][1] * inv0};
        float2 w1 = {o[nt][2] * inv1, o[nt][3] * inv1};
        *(float2*)&ob0[nt * 8 + 2 * tig] = w0;
        *(float2*)&ob1[nt * 8 + 2 * tig] = w1;
    }
}

// ---------------------------------------------------------------------------
// Launch
// ---------------------------------------------------------------------------
extern "C" void kernel_launch(void* const* d_in, const int* in_sizes, int n_in,
                              void* d_out, int out_size) {
    const float* x    = (const float*)d_in[0];
    const int*   mask = (const int*)d_in[1];
    const int*   cdrs = (const int*)d_in[2];
    const float* Wq   = (const float*)d_in[3];
    const float* bq   = (const float*)d_in[4];
    const float* Wk   = (const float*)d_in[5];
    const float* bk   = (const float*)d_in[6];
    const float* Wv   = (const float*)d_in[7];
    const float* bv   = (const float*)d_in[8];
    const float* Wo   = (const float*)d_in[9];
    const float* bo   = (const float*)d_in[10];
    float* out = (float*)d_out;

    allm_kernel<<<Bb, 256>>>(cdrs);

    dim3 gqkv(Bb * Tt / 128, Cc / 128, 3);
    gemm_qkv<<<gqkv, 256>>>(x, Wq, bq, Wk, bk, Wv, bv);

    size_t shbytes = (size_t)(128 + 64 + 64) * QP * sizeof(__half);  // 36864
    cudaFuncSetAttribute(attn_kernel, cudaFuncAttributeMaxDynamicSharedMemorySize,
                         (int)shbytes);
    dim3 gatt(Tt / 128, Hh, Bb);
    attn_kernel<<<gatt, 256, shbytes>>>(mask, cdrs);

    dim3 gout(Bb * Tt / 128, Cc / 128, 1);
    gemm_out<<<gout, 256>>>(Wo, bo, out);
}

// round 7
// speedup vs baseline: 9.2729x; 1.1123x over previous
#include <cuda_runtime.h>
#include <cuda_fp16.h>
#include <cstdint>

// Problem constants
#define Bb   4
#define Tt   2048
#define Cc   512
#define Hh   8
#define Dd   64
#define CDRH 2

#define NEG_INF __int_as_float(0xff800000)

// Scratch (allocation-free: module-static device globals)
__device__ __half g_xh[Bb * Tt * Cc];
__device__ __half g_wh[4][Cc * Cc];    // Wq, Wk, Wv, Wo in half
__device__ __half g_qh[Bb * Tt * Cc];
__device__ __half g_kh[Bb * Tt * Cc];
__device__ __half g_vh[Bb * Tt * Cc];
__device__ __half g_ctxh[Bb * Tt * Cc];
__device__ int    g_allm[Bb];

// ---------------------------------------------------------------------------
// helpers
// ---------------------------------------------------------------------------
__device__ __forceinline__ void mma_f16(float c[4], const uint32_t a[4],
                                        uint32_t b0, uint32_t b1) {
    asm volatile(
        "mma.sync.aligned.m16n8k16.row.col.f32.f16.f16.f32 "
        "{%0,%1,%2,%3}, {%4,%5,%6,%7}, {%8,%9}, {%0,%1,%2,%3};"
        : "+f"(c[0]), "+f"(c[1]), "+f"(c[2]), "+f"(c[3])
        : "r"(a[0]), "r"(a[1]), "r"(a[2]), "r"(a[3]), "r"(b0), "r"(b1));
}

__device__ __forceinline__ void ldsm_x4(uint32_t r[4], uint32_t addr) {
    asm volatile("ldmatrix.sync.aligned.m8n8.x4.shared.b16 {%0,%1,%2,%3}, [%4];"
                 : "=r"(r[0]), "=r"(r[1]), "=r"(r[2]), "=r"(r[3]) : "r"(addr));
}

__device__ __forceinline__ void ldsm_x4_t(uint32_t r[4], uint32_t addr) {
    asm volatile("ldmatrix.sync.aligned.m8n8.x4.trans.shared.b16 {%0,%1,%2,%3}, [%4];"
                 : "=r"(r[0]), "=r"(r[1]), "=r"(r[2]), "=r"(r[3]) : "r"(addr));
}

__device__ __forceinline__ uint32_t h2u(__half2 h) {
    return *reinterpret_cast<uint32_t*>(&h);
}

__device__ __forceinline__ void cp16(uint32_t dst, const void* src) {
    asm volatile("cp.async.cg.shared.global [%0], [%1], 16;" :: "r"(dst), "l"(src));
}
__device__ __forceinline__ void cp_commit() {
    asm volatile("cp.async.commit_group;");
}
template <int N>
__device__ __forceinline__ void cp_wait() {
    asm volatile("cp.async.wait_group %0;" :: "n"(N));
}

// ---------------------------------------------------------------------------
// Prep: fp32 -> half conversions (x and the 4 weight matrices)
// ---------------------------------------------------------------------------
__global__ void tohalf_kernel(const float* __restrict__ src, int which, int n4) {
    __half* dst;
    if (which == 0) dst = g_xh;
    else            dst = g_wh[which - 1];
    int i = blockIdx.x * blockDim.x + threadIdx.x;
    if (i < n4) {
        float4 v = ((const float4*)src)[i];
        uint2 w;
        w.x = h2u(__floats2half2_rn(v.x, v.y));
        w.y = h2u(__floats2half2_rn(v.z, v.w));
        ((uint2*)dst)[i] = w;
    }
}

// ---------------------------------------------------------------------------
// Per-batch "all CDR tokens masked" flag
// ---------------------------------------------------------------------------
__global__ void allm_kernel(const int* __restrict__ cdrs) {
    __shared__ int any;
    int b = blockIdx.x;
    if (threadIdx.x == 0) any = 0;
    __syncthreads();
    int local = 0;
    for (int t = threadIdx.x; t < Tt; t += blockDim.x)
        local |= (cdrs[b * Tt + t] != 0);
    if (local) any = 1;
    __syncthreads();
    if (threadIdx.x == 0) g_allm[b] = (any == 0) ? 1 : 0;
}

// ---------------------------------------------------------------------------
// fp16 tensor-core GEMM with cp.async double buffering.
// out[M,512] = A[M,512] @ W[512,512] + bias.  A, W in half.
// BM=BN=128, BK=32; 8 warps (2m x 4n); warp tile 64x32 via m16n8k16 + LDSM.
// ---------------------------------------------------------------------------
#define APIT 40    // As pitch in halves (80 B)
#define BPIT 136   // Bs pitch in halves (272 B)
#define AS_BYTES (128 * APIT * 2)
#define BS_BYTES (32 * BPIT * 2)

template <typename OutT>
__device__ __forceinline__ void gemm_f16_body(const __half* __restrict__ A,
                                              const __half* __restrict__ W,
                                              const float* __restrict__ bias,
                                              OutT* __restrict__ out) {
    __shared__ __align__(16) __half As[2][128][APIT];   // [buf][m][k]
    __shared__ __align__(16) __half Bs[2][32][BPIT];    // [buf][k][n]
    const int tid  = threadIdx.x;
    const int warp = tid >> 5;
    const int lane = tid & 31;
    const int g    = lane >> 2;
    const int tig  = lane & 3;
    const int mf   = lane >> 3;
    const int rr   = lane & 7;
    const int wm   = warp >> 2;
    const int wn   = warp & 3;
    const int m0 = blockIdx.x * 128, n0 = blockIdx.y * 128;

    const uint32_t as_u = (uint32_t)__cvta_generic_to_shared(&As[0][0][0]);
    const uint32_t bs_u = (uint32_t)__cvta_generic_to_shared(&Bs[0][0][0]);

    // A-tile loader coords (2 chunks of 16B per thread): 128 rows x 4 chunks
    const int ar = tid >> 1;               // handled below per p
    (void)ar;

    auto issue_tiles = [&](int k0, int buf) {
#pragma unroll
        for (int p = 0; p < 2; p++) {
            int li = p * 256 + tid;        // 0..511
            int r  = li >> 2;
            int c  = (li & 3) * 8;
            cp16(as_u + buf * AS_BYTES + (r * APIT + c) * 2,
                 A + (size_t)(m0 + r) * Cc + k0 + c);
        }
#pragma unroll
        for (int p = 0; p < 2; p++) {
            int li = p * 256 + tid;
            int r  = li >> 4;
            int c  = (li & 15) * 8;
            cp16(bs_u + buf * BS_BYTES + (r * BPIT + c) * 2,
                 W + (size_t)(k0 + r) * Cc + n0 + c);
        }
    };

    float acc[4][4][4] = {};

    issue_tiles(0, 0);
    cp_commit();

    for (int kt = 0; kt < 16; kt++) {
        const int cur = kt & 1;
        if (kt + 1 < 16) {
            issue_tiles((kt + 1) * 32, cur ^ 1);
            cp_commit();
            cp_wait<1>();
        } else {
            cp_wait<0>();
        }
        __syncthreads();

        const uint32_t abase = as_u + cur * AS_BYTES;
        const uint32_t bbase = bs_u + cur * BS_BYTES;
#pragma unroll
        for (int kc = 0; kc < 2; kc++) {
            uint32_t af[4][4];
#pragma unroll
            for (int mt = 0; mt < 4; mt++) {
                int row = wm * 64 + mt * 16 + rr + (mf & 1) * 8;
                int col = kc * 16 + (mf >> 1) * 8;
                ldsm_x4(af[mt], abase + (row * APIT + col) * 2);
            }
            uint32_t bf[2][4];
#pragma unroll
            for (int p = 0; p < 2; p++) {
                int krow = kc * 16 + (mf & 1) * 8 + rr;
                int ncol = wn * 32 + (2 * p + (mf >> 1)) * 8;
                ldsm_x4_t(bf[p], bbase + (krow * BPIT + ncol) * 2);
            }
#pragma unroll
            for (int mt = 0; mt < 4; mt++)
#pragma unroll
                for (int p = 0; p < 2; p++) {
                    mma_f16(acc[mt][2 * p],     af[mt], bf[p][0], bf[p][1]);
                    mma_f16(acc[mt][2 * p + 1], af[mt], bf[p][2], bf[p][3]);
                }
        }
        __syncthreads();
    }

    // epilogue: add bias, store
#pragma unroll
    for (int mt = 0; mt < 4; mt++) {
        int r0g = m0 + wm * 64 + mt * 16 + g;
        int r1g = r0g + 8;
#pragma unroll
        for (int nt = 0; nt < 4; nt++) {
            int n = n0 + wn * 32 + nt * 8 + 2 * tig;
            float b0 = bias[n], b1 = bias[n + 1];
            float v00 = acc[mt][nt][0] + b0, v01 = acc[mt][nt][1] + b1;
            float v10 = acc[mt][nt][2] + b0, v11 = acc[mt][nt][3] + b1;
            if constexpr (sizeof(OutT) == 2) {
                *(uint32_t*)&out[(size_t)r0g * Cc + n] = h2u(__floats2half2_rn(v00, v01));
                *(uint32_t*)&out[(size_t)r1g * Cc + n] = h2u(__floats2half2_rn(v10, v11));
            } else {
                float2 w0 = {v00, v01};
                float2 w1 = {v10, v11};
                *(float2*)&out[(size_t)r0g * Cc + n] = w0;
                *(float2*)&out[(size_t)r1g * Cc + n] = w1;
            }
        }
    }
}

__global__ __launch_bounds__(256, 2)
void gemm_qkv(const float* __restrict__ bq, const float* __restrict__ bk,
              const float* __restrict__ bv) {
    const __half* W; const float* bi; __half* out;
    if (blockIdx.z == 0)      { W = g_wh[0]; bi = bq; out = g_qh; }
    else if (blockIdx.z == 1) { W = g_wh[1]; bi = bk; out = g_kh; }
    else                      { W = g_wh[2]; bi = bv; out = g_vh; }
    gemm_f16_body<__half>(g_xh, W, bi, out);
}

__global__ __launch_bounds__(256, 2)
void gemm_out(const float* __restrict__ bo, float* __restrict__ out) {
    gemm_f16_body<float>(g_ctxh, g_wh[3], bo, out);
}

// ---------------------------------------------------------------------------
// fp16 tensor-core flash attention, cp.async double-buffered K/V tiles.
// ---------------------------------------------------------------------------
#define QP 72
#define KS_BYTES (64 * QP * 2)

__global__ __launch_bounds__(256)
void attn_kernel(const int* __restrict__ mask, const int* __restrict__ cdrs) {
    extern __shared__ __align__(16) __half sh[];
    __half* qs = sh;                       // [128][QP]
    __half* ks = sh + 128 * QP;            // [2][64][QP]
    __half* vs = ks + 2 * 64 * QP;         // [2][64][QP]

    __shared__ __align__(16) float kneg[64];

    const int q0   = blockIdx.x * 128;
    const int h    = blockIdx.y;
    const int b    = blockIdx.z;
    const int tid  = threadIdx.x;
    const int warp = tid >> 5;
    const int lane = tid & 31;
    const int g    = lane >> 2;
    const int tig  = lane & 3;
    const int mf   = lane >> 3;
    const int rr   = lane & 7;

    const bool iscdr = (h < CDRH) && (g_allm[b] == 0);

    const uint32_t qs_u = (uint32_t)__cvta_generic_to_shared(qs);
    const uint32_t ks_u = (uint32_t)__cvta_generic_to_shared(ks);
    const uint32_t vs_u = (uint32_t)__cvta_generic_to_shared(vs);

    const __half* kall = g_kh + (size_t)b * Tt * Cc + h * Dd;
    const __half* vall = g_vh + (size_t)b * Tt * Cc + h * Dd;

    auto issue_kv = [&](int kt, int buf) {
        const __half* kbase = kall + (size_t)kt * 64 * Cc;
        const __half* vbase = vall + (size_t)kt * 64 * Cc;
#pragma unroll
        for (int p = 0; p < 2; p++) {
            int li = p * 256 + tid;       // 0..511 ; 64 rows x 8 chunks
            int r  = li >> 3;
            int c  = (li & 7) * 8;
            cp16(ks_u + buf * KS_BYTES + (r * QP + c) * 2, kbase + (size_t)r * Cc + c);
        }
#pragma unroll
        for (int p = 0; p < 2; p++) {
            int li = p * 256 + tid;
            int r  = li >> 3;
            int c  = (li & 7) * 8;
            cp16(vs_u + buf * KS_BYTES + (r * QP + c) * 2, vbase + (size_t)r * Cc + c);
        }
    };

    // ---- stage Q tile + prologue K/V issue ----
    const __half* qbase = g_qh + (size_t)(b * Tt + q0) * Cc + h * Dd;
    for (int i = tid; i < 128 * 8; i += 256) {
        int r = i >> 3, c8 = i & 7;
        *(uint4*)&qs[r * QP + c8 * 8] = *(const uint4*)(qbase + (size_t)r * Cc + c8 * 8);
    }
    issue_kv(0, 0);
    cp_commit();
    __syncthreads();

    // ---- hoist Q A-fragments ----
    uint32_t qa[4][4];
#pragma unroll
    for (int kc = 0; kc < 4; kc++) {
        int row = warp * 16 + rr + (mf & 1) * 8;
        int col = kc * 16 + (mf >> 1) * 8;
        ldsm_x4(qa[kc], qs_u + (row * QP + col) * 2);
    }

    float m_run[2] = {NEG_INF, NEG_INF};
    float l_run[2] = {0.f, 0.f};
    float o[8][4] = {};

    for (int kt = 0; kt < Tt / 64; kt++) {
        const int cur = kt & 1;

        // mask bias for this tile (safe: prev compute ended with __syncthreads)
        if (tid < 64) {
            int kg = kt * 64 + tid;
            bool bad = (mask[b * Tt + kg] == 0) ||
                       (iscdr && (cdrs[b * Tt + kg] == 0));
            kneg[tid] = bad ? NEG_INF : 0.f;
        }

        if (kt + 1 < Tt / 64) {
            issue_kv(kt + 1, cur ^ 1);
            cp_commit();
            cp_wait<1>();
        } else {
            cp_wait<0>();
        }
        __syncthreads();

        const uint32_t kb = ks_u + cur * KS_BYTES;
        const uint32_t vb = vs_u + cur * KS_BYTES;

        // ---- S = Q K^T ----
        float s[8][4] = {};
#pragma unroll
        for (int kc = 0; kc < 4; kc++) {
#pragma unroll
            for (int p = 0; p < 4; p++) {
                int key = (2 * p + (mf >> 1)) * 8 + rr;
                int d   = kc * 16 + (mf & 1) * 8;
                uint32_t bk[4];
                ldsm_x4(bk, kb + (key * QP + d) * 2);
                mma_f16(s[2 * p],     qa[kc], bk[0], bk[1]);
                mma_f16(s[2 * p + 1], qa[kc], bk[2], bk[3]);
            }
        }

        // ---- scale + key-mask bias ----
#pragma unroll
        for (int nt = 0; nt < 8; nt++) {
            float k0b = kneg[nt * 8 + 2 * tig];
            float k1b = kneg[nt * 8 + 2 * tig + 1];
            s[nt][0] = s[nt][0] * 0.125f + k0b;
            s[nt][1] = s[nt][1] * 0.125f + k1b;
            s[nt][2] = s[nt][2] * 0.125f + k0b;
            s[nt][3] = s[nt][3] * 0.125f + k1b;
        }

        // ---- online softmax ----
        float mt0 = NEG_INF, mt1 = NEG_INF;
#pragma unroll
        for (int nt = 0; nt < 8; nt++) {
            mt0 = fmaxf(mt0, fmaxf(s[nt][0], s[nt][1]));
            mt1 = fmaxf(mt1, fmaxf(s[nt][2], s[nt][3]));
        }
#pragma unroll
        for (int off = 1; off < 4; off <<= 1) {
            mt0 = fmaxf(mt0, __shfl_xor_sync(0xffffffffu, mt0, off));
            mt1 = fmaxf(mt1, __shfl_xor_sync(0xffffffffu, mt1, off));
        }
        float mn0 = fmaxf(m_run[0], mt0);
        float mn1 = fmaxf(m_run[1], mt1);
        float alpha0, alpha1, sum0 = 0.f, sum1 = 0.f;
        if (mn0 == NEG_INF) {
            alpha0 = 1.f;
#pragma unroll
            for (int nt = 0; nt < 8; nt++) { s[nt][0] = 0.f; s[nt][1] = 0.f; }
        } else {
            alpha0 = __expf(m_run[0] - mn0);
#pragma unroll
            for (int nt = 0; nt < 8; nt++) {
                float p0 = __expf(s[nt][0] - mn0);
                float p1 = __expf(s[nt][1] - mn0);
                s[nt][0] = p0; s[nt][1] = p1;
                sum0 += p0 + p1;
            }
        }
        if (mn1 == NEG_INF) {
            alpha1 = 1.f;
#pragma unroll
            for (int nt = 0; nt < 8; nt++) { s[nt][2] = 0.f; s[nt][3] = 0.f; }
        } else {
            alpha1 = __expf(m_run[1] - mn1);
#pragma unroll
            for (int nt = 0; nt < 8; nt++) {
                float p0 = __expf(s[nt][2] - mn1);
                float p1 = __expf(s[nt][3] - mn1);
                s[nt][2] = p0; s[nt][3] = p1;
                sum1 += p0 + p1;
            }
        }
#pragma unroll
        for (int off = 1; off < 4; off <<= 1) {
            sum0 += __shfl_xor_sync(0xffffffffu, sum0, off);
            sum1 += __shfl_xor_sync(0xffffffffu, sum1, off);
        }
        m_run[0] = mn0;  l_run[0] = l_run[0] * alpha0 + sum0;
        m_run[1] = mn1;  l_run[1] = l_run[1] * alpha1 + sum1;

#pragma unroll
        for (int nt = 0; nt < 8; nt++) {
            o[nt][0] *= alpha0; o[nt][1] *= alpha0;
            o[nt][2] *= alpha1; o[nt][3] *= alpha1;
        }

        // ---- O += P @ V (P in registers) ----
#pragma unroll
        for (int kc = 0; kc < 4; kc++) {
            uint32_t pa[4];
            pa[0] = h2u(__floats2half2_rn(s[2 * kc][0],     s[2 * kc][1]));
            pa[1] = h2u(__floats2half2_rn(s[2 * kc][2],     s[2 * kc][3]));
            pa[2] = h2u(__floats2half2_rn(s[2 * kc + 1][0], s[2 * kc + 1][1]));
            pa[3] = h2u(__floats2half2_rn(s[2 * kc + 1][2], s[2 * kc + 1][3]));
#pragma unroll
            for (int p = 0; p < 4; p++) {
                int key = kc * 16 + (mf & 1) * 8 + rr;
                int d   = (2 * p + (mf >> 1)) * 8;
                uint32_t bv[4];
                ldsm_x4_t(bv, vb + (key * QP + d) * 2);
                mma_f16(o[2 * p],     pa, bv[0], bv[1]);
                mma_f16(o[2 * p + 1], pa, bv[2], bv[3]);
            }
        }
        __syncthreads();
    }

    // ---- epilogue: normalize, write ctx (half) ----
    const int r0 = warp * 16 + g;
    const int r1 = r0 + 8;
    float inv0 = 1.f / l_run[0];
    float inv1 = 1.f / l_run[1];
    __half* ob0 = g_ctxh + (size_t)(b * Tt + q0 + r0) * Cc + h * Dd;
    __half* ob1 = g_ctxh + (size_t)(b * Tt + q0 + r1) * Cc + h * Dd;
#pragma unroll
    for (int nt = 0; nt < 8; nt++) {
        *(uint32_t*)&ob0[nt * 8 + 2 * tig] =
            h2u(__floats2half2_rn(o[nt][0] * inv0, o[nt][1] * inv0));
        *(uint32_t*)&ob1[nt * 8 + 2 * tig] =
            h2u(__floats2half2_rn(o[nt][2] * inv1, o[nt][3] * inv1));
    }
}

// ---------------------------------------------------------------------------
// Launch
// ---------------------------------------------------------------------------
extern "C" void kernel_launch(void* const* d_in, const int* in_sizes, int n_in,
                              void* d_out, int out_size) {
    const float* x    = (const float*)d_in[0];
    const int*   mask = (const int*)d_in[1];
    const int*   cdrs = (const int*)d_in[2];
    const float* Wq   = (const float*)d_in[3];
    const float* bq   = (const float*)d_in[4];
    const float* Wk   = (const float*)d_in[5];
    const float* bk   = (const float*)d_in[6];
    const float* Wv   = (const float*)d_in[7];
    const float* bv   = (const float*)d_in[8];
    const float* Wo   = (const float*)d_in[9];
    const float* bo   = (const float*)d_in[10];
    float* out = (float*)d_out;

    allm_kernel<<<Bb, 256>>>(cdrs);

    // fp32 -> half prep
    tohalf_kernel<<<(Bb * Tt * Cc / 4 + 255) / 256, 256>>>(x,  0, Bb * Tt * Cc / 4);
    tohalf_kernel<<<(Cc * Cc / 4 + 255) / 256, 256>>>(Wq, 1, Cc * Cc / 4);
    tohalf_kernel<<<(Cc * Cc / 4 + 255) / 256, 256>>>(Wk, 2, Cc * Cc / 4);
    tohalf_kernel<<<(Cc * Cc / 4 + 255) / 256, 256>>>(Wv, 3, Cc * Cc / 4);
    tohalf_kernel<<<(Cc * Cc / 4 + 255) / 256, 256>>>(Wo, 4, Cc * Cc / 4);

    dim3 gqkv(Bb * Tt / 128, Cc / 128, 3);
    gemm_qkv<<<gqkv, 256>>>(bq, bk, bv);

    size_t shbytes = (size_t)(128 + 2 * 64 + 2 * 64) * QP * sizeof(__half);  // 55296
    cudaFuncSetAttribute(attn_kernel, cudaFuncAttributeMaxDynamicSharedMemorySize,
                         (int)shbytes);
    dim3 gatt(Tt / 128, Hh, Bb);
    attn_kernel<<<gatt, 256, shbytes>>>(mask, cdrs);

    dim3 gout(Bb * Tt / 128, Cc / 128, 1);
    gemm_out<<<gout, 256>>>(bo, out);
}

// round 8
// speedup vs baseline: 10.1243x; 1.0918x over previous
#include <cuda_runtime.h>
#include <cuda_fp16.h>
#include <cstdint>

// Problem constants
#define Bb   4
#define Tt   2048
#define Cc   512
#define Hh   8
#define Dd   64
#define CDRH 2

#define NEG_INF __int_as_float(0xff800000)
#define SCALE2 0.18033688011112042f   // 0.125 * log2(e)

// Scratch (allocation-free: module-static device globals)
__device__ __half g_xh[Bb * Tt * Cc];
__device__ __half g_wh[4][Cc * Cc];    // Wq, Wk, Wv, Wo in half
__device__ __half g_qh[Bb * Tt * Cc];
__device__ __half g_kh[Bb * Tt * Cc];
__device__ __half g_vh[Bb * Tt * Cc];
__device__ __half g_ctxh[Bb * Tt * Cc];
__device__ int    g_allm[Bb];

// ---------------------------------------------------------------------------
// helpers
// ---------------------------------------------------------------------------
__device__ __forceinline__ void mma_f16(float c[4], const uint32_t a[4],
                                        uint32_t b0, uint32_t b1) {
    asm volatile(
        "mma.sync.aligned.m16n8k16.row.col.f32.f16.f16.f32 "
        "{%0,%1,%2,%3}, {%4,%5,%6,%7}, {%8,%9}, {%0,%1,%2,%3};"
        : "+f"(c[0]), "+f"(c[1]), "+f"(c[2]), "+f"(c[3])
        : "r"(a[0]), "r"(a[1]), "r"(a[2]), "r"(a[3]), "r"(b0), "r"(b1));
}

__device__ __forceinline__ void ldsm_x4(uint32_t r[4], uint32_t addr) {
    asm volatile("ldmatrix.sync.aligned.m8n8.x4.shared.b16 {%0,%1,%2,%3}, [%4];"
                 : "=r"(r[0]), "=r"(r[1]), "=r"(r[2]), "=r"(r[3]) : "r"(addr));
}

__device__ __forceinline__ void ldsm_x4_t(uint32_t r[4], uint32_t addr) {
    asm volatile("ldmatrix.sync.aligned.m8n8.x4.trans.shared.b16 {%0,%1,%2,%3}, [%4];"
                 : "=r"(r[0]), "=r"(r[1]), "=r"(r[2]), "=r"(r[3]) : "r"(addr));
}

__device__ __forceinline__ uint32_t h2u(__half2 h) {
    return *reinterpret_cast<uint32_t*>(&h);
}

__device__ __forceinline__ float ex2(float x) {
    float y;
    asm("ex2.approx.f32 %0, %1;" : "=f"(y) : "f"(x));
    return y;
}

__device__ __forceinline__ void cp16(uint32_t dst, const void* src) {
    asm volatile("cp.async.cg.shared.global [%0], [%1], 16;" :: "r"(dst), "l"(src));
}
__device__ __forceinline__ void cp_commit() {
    asm volatile("cp.async.commit_group;");
}
template <int N>
__device__ __forceinline__ void cp_wait() {
    asm volatile("cp.async.wait_group %0;" :: "n"(N));
}

// ---------------------------------------------------------------------------
// Fused prep: fp32->half for x + 4 weights (grid.y 0..4), allm flag (y==5)
// ---------------------------------------------------------------------------
__global__ void prep_kernel(const float* __restrict__ x,
                            const float* __restrict__ Wq,
                            const float* __restrict__ Wk,
                            const float* __restrict__ Wv,
                            const float* __restrict__ Wo,
                            const int* __restrict__ cdrs) {
    const int y = blockIdx.y;
    if (y == 5) {
        // per-batch all-masked flag
        int b = blockIdx.x;
        if (b >= Bb) return;
        __shared__ int any;
        if (threadIdx.x == 0) any = 0;
        __syncthreads();
        int local = 0;
        for (int t = threadIdx.x; t < Tt; t += blockDim.x)
            local |= (cdrs[b * Tt + t] != 0);
        if (local) any = 1;
        __syncthreads();
        if (threadIdx.x == 0) g_allm[b] = (any == 0) ? 1 : 0;
        return;
    }
    const float* src; __half* dst; int n4;
    switch (y) {
        case 0: src = x;  dst = g_xh;    n4 = Bb * Tt * Cc / 4; break;
        case 1: src = Wq; dst = g_wh[0]; n4 = Cc * Cc / 4; break;
        case 2: src = Wk; dst = g_wh[1]; n4 = Cc * Cc / 4; break;
        case 3: src = Wv; dst = g_wh[2]; n4 = Cc * Cc / 4; break;
        default: src = Wo; dst = g_wh[3]; n4 = Cc * Cc / 4; break;
    }
    int i = blockIdx.x * blockDim.x + threadIdx.x;
    if (i < n4) {
        float4 v = ((const float4*)src)[i];
        uint2 w;
        w.x = h2u(__floats2half2_rn(v.x, v.y));
        w.y = h2u(__floats2half2_rn(v.z, v.w));
        ((uint2*)dst)[i] = w;
    }
}

// ---------------------------------------------------------------------------
// fp16 tensor-core GEMM, 3-stage cp.async pipeline, ONE sync per k-tile.
// out[M,512] = A[M,512] @ W[512,512] + bias.  A, W in half.
// BM=BN=128, BK=32; 8 warps (2m x 4n); warp tile 64x32 via m16n8k16 + LDSM.
// ---------------------------------------------------------------------------
#define APIT 40    // As pitch in halves (80 B)
#define BPIT 136   // Bs pitch in halves (272 B)
#define AS_BYTES (128 * APIT * 2)
#define BS_BYTES (32 * BPIT * 2)
#define GEMM_SMEM (3 * (AS_BYTES + BS_BYTES))

template <typename OutT>
__device__ __forceinline__ void gemm_f16_body(const __half* __restrict__ A,
                                              const __half* __restrict__ W,
                                              const float* __restrict__ bias,
                                              OutT* __restrict__ out) {
    extern __shared__ __align__(16) __half gsh[];
    __half* As = gsh;                          // [3][128][APIT]
    __half* Bs = gsh + 3 * 128 * APIT;         // [3][32][BPIT]
    const int tid  = threadIdx.x;
    const int warp = tid >> 5;
    const int lane = tid & 31;
    const int g    = lane >> 2;
    const int tig  = lane & 3;
    const int mf   = lane >> 3;
    const int rr   = lane & 7;
    const int wm   = warp >> 2;
    const int wn   = warp & 3;
    const int m0 = blockIdx.x * 128, n0 = blockIdx.y * 128;

    const uint32_t as_u = (uint32_t)__cvta_generic_to_shared(As);
    const uint32_t bs_u = (uint32_t)__cvta_generic_to_shared(Bs);

    auto issue_tiles = [&](int k0, int buf) {
#pragma unroll
        for (int p = 0; p < 2; p++) {
            int li = p * 256 + tid;        // 128 rows x 4 chunks
            int r  = li >> 2;
            int c  = (li & 3) * 8;
            cp16(as_u + buf * AS_BYTES + (r * APIT + c) * 2,
                 A + (size_t)(m0 + r) * Cc + k0 + c);
        }
#pragma unroll
        for (int p = 0; p < 2; p++) {
            int li = p * 256 + tid;        // 32 rows x 16 chunks
            int r  = li >> 4;
            int c  = (li & 15) * 8;
            cp16(bs_u + buf * BS_BYTES + (r * BPIT + c) * 2,
                 W + (size_t)(k0 + r) * Cc + n0 + c);
        }
    };

    float acc[4][4][4] = {};

    issue_tiles(0, 0);  cp_commit();
    issue_tiles(32, 1); cp_commit();

    for (int kt = 0; kt < 16; kt++) {
        const int cur = kt % 3;
        cp_wait<1>();
        __syncthreads();
        if (kt + 2 < 16) issue_tiles((kt + 2) * 32, (kt + 2) % 3);
        cp_commit();

        const uint32_t abase = as_u + cur * AS_BYTES;
        const uint32_t bbase = bs_u + cur * BS_BYTES;
#pragma unroll
        for (int kc = 0; kc < 2; kc++) {
            uint32_t af[4][4];
#pragma unroll
            for (int mt = 0; mt < 4; mt++) {
                int row = wm * 64 + mt * 16 + rr + (mf & 1) * 8;
                int col = kc * 16 + (mf >> 1) * 8;
                ldsm_x4(af[mt], abase + (row * APIT + col) * 2);
            }
            uint32_t bf[2][4];
#pragma unroll
            for (int p = 0; p < 2; p++) {
                int krow = kc * 16 + (mf & 1) * 8 + rr;
                int ncol = wn * 32 + (2 * p + (mf >> 1)) * 8;
                ldsm_x4_t(bf[p], bbase + (krow * BPIT + ncol) * 2);
            }
#pragma unroll
            for (int mt = 0; mt < 4; mt++)
#pragma unroll
                for (int p = 0; p < 2; p++) {
                    mma_f16(acc[mt][2 * p],     af[mt], bf[p][0], bf[p][1]);
                    mma_f16(acc[mt][2 * p + 1], af[mt], bf[p][2], bf[p][3]);
                }
        }
    }

    // epilogue: add bias, store
#pragma unroll
    for (int mt = 0; mt < 4; mt++) {
        int r0g = m0 + wm * 64 + mt * 16 + g;
        int r1g = r0g + 8;
#pragma unroll
        for (int nt = 0; nt < 4; nt++) {
            int n = n0 + wn * 32 + nt * 8 + 2 * tig;
            float b0 = bias[n], b1 = bias[n + 1];
            float v00 = acc[mt][nt][0] + b0, v01 = acc[mt][nt][1] + b1;
            float v10 = acc[mt][nt][2] + b0, v11 = acc[mt][nt][3] + b1;
            if constexpr (sizeof(OutT) == 2) {
                *(uint32_t*)&out[(size_t)r0g * Cc + n] = h2u(__floats2half2_rn(v00, v01));
                *(uint32_t*)&out[(size_t)r1g * Cc + n] = h2u(__floats2half2_rn(v10, v11));
            } else {
                float2 w0 = {v00, v01};
                float2 w1 = {v10, v11};
                *(float2*)&out[(size_t)r0g * Cc + n] = w0;
                *(float2*)&out[(size_t)r1g * Cc + n] = w1;
            }
        }
    }
}

__global__ __launch_bounds__(256, 2)
void gemm_qkv(const float* __restrict__ bq, const float* __restrict__ bk,
              const float* __restrict__ bv) {
    const __half* W; const float* bi; __half* out;
    if (blockIdx.z == 0)      { W = g_wh[0]; bi = bq; out = g_qh; }
    else if (blockIdx.z == 1) { W = g_wh[1]; bi = bk; out = g_kh; }
    else                      { W = g_wh[2]; bi = bv; out = g_vh; }
    gemm_f16_body<__half>(g_xh, W, bi, out);
}

__global__ __launch_bounds__(256, 2)
void gemm_out(const float* __restrict__ bo, float* __restrict__ out) {
    gemm_f16_body<float>(g_ctxh, g_wh[3], bo, out);
}

// ---------------------------------------------------------------------------
// fp16 tensor-core flash attention, 3-stage cp.async, ONE sync per key tile.
// log2-domain online softmax (scale folded into SCALE2, raw ex2).
// ---------------------------------------------------------------------------
#define QP 72
#define KS_BYTES (64 * QP * 2)

__global__ __launch_bounds__(256)
void attn_kernel(const int* __restrict__ mask, const int* __restrict__ cdrs) {
    extern __shared__ __align__(16) __half sh[];
    __half* qs = sh;                       // [128][QP]
    __half* ks = sh + 128 * QP;            // [3][64][QP]
    __half* vs = ks + 3 * 64 * QP;         // [3][64][QP]

    __shared__ __align__(16) float kneg[2][64];

    const int q0   = blockIdx.x * 128;
    const int h    = blockIdx.y;
    const int b    = blockIdx.z;
    const int tid  = threadIdx.x;
    const int warp = tid >> 5;
    const int lane = tid & 31;
    const int g    = lane >> 2;
    const int tig  = lane & 3;
    const int mf   = lane >> 3;
    const int rr   = lane & 7;

    const bool iscdr = (h < CDRH) && (g_allm[b] == 0);

    const uint32_t qs_u = (uint32_t)__cvta_generic_to_shared(qs);
    const uint32_t ks_u = (uint32_t)__cvta_generic_to_shared(ks);
    const uint32_t vs_u = (uint32_t)__cvta_generic_to_shared(vs);

    const __half* kall = g_kh + (size_t)b * Tt * Cc + h * Dd;
    const __half* vall = g_vh + (size_t)b * Tt * Cc + h * Dd;

    auto issue_kv = [&](int kt, int buf) {
        const __half* kbase = kall + (size_t)kt * 64 * Cc;
        const __half* vbase = vall + (size_t)kt * 64 * Cc;
#pragma unroll
        for (int p = 0; p < 2; p++) {
            int li = p * 256 + tid;       // 64 rows x 8 chunks
            int r  = li >> 3;
            int c  = (li & 7) * 8;
            cp16(ks_u + buf * KS_BYTES + (r * QP + c) * 2, kbase + (size_t)r * Cc + c);
        }
#pragma unroll
        for (int p = 0; p < 2; p++) {
            int li = p * 256 + tid;
            int r  = li >> 3;
            int c  = (li & 7) * 8;
            cp16(vs_u + buf * KS_BYTES + (r * QP + c) * 2, vbase + (size_t)r * Cc + c);
        }
    };

    auto mask_bias = [&](int kt, int buf) {
        if (tid < 64) {
            int kg = kt * 64 + tid;
            bool bad = (mask[b * Tt + kg] == 0) ||
                       (iscdr && (cdrs[b * Tt + kg] == 0));
            kneg[buf][tid] = bad ? NEG_INF : 0.f;
        }
    };

    // ---- prologue: Q via cp.async, then K/V tiles 0 and 1, kneg for tile 0
    const __half* qbase = g_qh + (size_t)(b * Tt + q0) * Cc + h * Dd;
#pragma unroll
    for (int p = 0; p < 4; p++) {
        int li = p * 256 + tid;            // 128 rows x 8 chunks
        int r  = li >> 3;
        int c  = (li & 7) * 8;
        cp16(qs_u + (r * QP + c) * 2, qbase + (size_t)r * Cc + c);
    }
    cp_commit();
    issue_kv(0, 0); cp_commit();
    issue_kv(1, 1); cp_commit();
    mask_bias(0, 0);

    cp_wait<2>();      // Q complete
    __syncthreads();   // Q + kneg[0] visible

    // ---- hoist Q A-fragments ----
    uint32_t qa[4][4];
#pragma unroll
    for (int kc = 0; kc < 4; kc++) {
        int row = warp * 16 + rr + (mf & 1) * 8;
        int col = kc * 16 + (mf >> 1) * 8;
        ldsm_x4(qa[kc], qs_u + (row * QP + col) * 2);
    }

    float m_run[2] = {NEG_INF, NEG_INF};   // log2 domain
    float l_run[2] = {0.f, 0.f};
    float o[8][4] = {};

    for (int kt = 0; kt < Tt / 64; kt++) {
        const int cur = kt % 3;
        cp_wait<1>();      // tile kt's group complete
        __syncthreads();   // visibility + buffer (kt+2)%3 drained + kneg handoff
        if (kt + 2 < Tt / 64) issue_kv(kt + 2, (kt + 2) % 3);
        cp_commit();
        if (kt + 1 < Tt / 64) mask_bias(kt + 1, (kt + 1) & 1);

        const uint32_t kb = ks_u + cur * KS_BYTES;
        const uint32_t vb = vs_u + cur * KS_BYTES;
        const float* kn = kneg[kt & 1];

        // ---- S = Q K^T ----
        float s[8][4] = {};
#pragma unroll
        for (int kc = 0; kc < 4; kc++) {
#pragma unroll
            for (int p = 0; p < 4; p++) {
                int key = (2 * p + (mf >> 1)) * 8 + rr;
                int d   = kc * 16 + (mf & 1) * 8;
                uint32_t bk[4];
                ldsm_x4(bk, kb + (key * QP + d) * 2);
                mma_f16(s[2 * p],     qa[kc], bk[0], bk[1]);
                mma_f16(s[2 * p + 1], qa[kc], bk[2], bk[3]);
            }
        }

        // ---- scale (log2 domain) + key-mask bias ----
#pragma unroll
        for (int nt = 0; nt < 8; nt++) {
            float k0b = kn[nt * 8 + 2 * tig];
            float k1b = kn[nt * 8 + 2 * tig + 1];
            s[nt][0] = s[nt][0] * SCALE2 + k0b;
            s[nt][1] = s[nt][1] * SCALE2 + k1b;
            s[nt][2] = s[nt][2] * SCALE2 + k0b;
            s[nt][3] = s[nt][3] * SCALE2 + k1b;
        }

        // ---- online softmax (base-2) ----
        float mt0 = NEG_INF, mt1 = NEG_INF;
#pragma unroll
        for (int nt = 0; nt < 8; nt++) {
            mt0 = fmaxf(mt0, fmaxf(s[nt][0], s[nt][1]));
            mt1 = fmaxf(mt1, fmaxf(s[nt][2], s[nt][3]));
        }
#pragma unroll
        for (int off = 1; off < 4; off <<= 1) {
            mt0 = fmaxf(mt0, __shfl_xor_sync(0xffffffffu, mt0, off));
            mt1 = fmaxf(mt1, __shfl_xor_sync(0xffffffffu, mt1, off));
        }
        float mn0 = fmaxf(m_run[0], mt0);
        float mn1 = fmaxf(m_run[1], mt1);
        float alpha0, alpha1, sum0 = 0.f, sum1 = 0.f;
        if (mn0 == NEG_INF) {
            alpha0 = 1.f;
#pragma unroll
            for (int nt = 0; nt < 8; nt++) { s[nt][0] = 0.f; s[nt][1] = 0.f; }
        } else {
            alpha0 = ex2(m_run[0] - mn0);
#pragma unroll
            for (int nt = 0; nt < 8; nt++) {
                float p0 = ex2(s[nt][0] - mn0);
                float p1 = ex2(s[nt][1] - mn0);
                s[nt][0] = p0; s[nt][1] = p1;
                sum0 += p0 + p1;
            }
        }
        if (mn1 == NEG_INF) {
            alpha1 = 1.f;
#pragma unroll
            for (int nt = 0; nt < 8; nt++) { s[nt][2] = 0.f; s[nt][3] = 0.f; }
        } else {
            alpha1 = ex2(m_run[1] - mn1);
#pragma unroll
            for (int nt = 0; nt < 8; nt++) {
                float p0 = ex2(s[nt][2] - mn1);
                float p1 = ex2(s[nt][3] - mn1);
                s[nt][2] = p0; s[nt][3] = p1;
                sum1 += p0 + p1;
            }
        }
#pragma unroll
        for (int off = 1; off < 4; off <<= 1) {
            sum0 += __shfl_xor_sync(0xffffffffu, sum0, off);
            sum1 += __shfl_xor_sync(0xffffffffu, sum1, off);
        }
        m_run[0] = mn0;  l_run[0] = l_run[0] * alpha0 + sum0;
        m_run[1] = mn1;  l_run[1] = l_run[1] * alpha1 + sum1;

#pragma unroll
        for (int nt = 0; nt < 8; nt++) {
            o[nt][0] *= alpha0; o[nt][1] *= alpha0;
            o[nt][2] *= alpha1; o[nt][3] *= alpha1;
        }

        // ---- O += P @ V (P in registers) ----
#pragma unroll
        for (int kc = 0; kc < 4; kc++) {
            uint32_t pa[4];
            pa[0] = h2u(__floats2half2_rn(s[2 * kc][0],     s[2 * kc][1]));
            pa[1] = h2u(__floats2half2_rn(s[2 * kc][2],     s[2 * kc][3]));
            pa[2] = h2u(__floats2half2_rn(s[2 * kc + 1][0], s[2 * kc + 1][1]));
            pa[3] = h2u(__floats2half2_rn(s[2 * kc + 1][2], s[2 * kc + 1][3]));
#pragma unroll
            for (int p = 0; p < 4; p++) {
                int key = kc * 16 + (mf & 1) * 8 + rr;
                int d   = (2 * p + (mf >> 1)) * 8;
                uint32_t bv[4];
                ldsm_x4_t(bv, vb + (key * QP + d) * 2);
                mma_f16(o[2 * p],     pa, bv[0], bv[1]);
                mma_f16(o[2 * p + 1], pa, bv[2], bv[3]);
            }
        }
    }

    // ---- epilogue: normalize, write ctx (half) ----
    const int r0 = warp * 16 + g;
    const int r1 = r0 + 8;
    float inv0 = 1.f / l_run[0];
    float inv1 = 1.f / l_run[1];
    __half* ob0 = g_ctxh + (size_t)(b * Tt + q0 + r0) * Cc + h * Dd;
    __half* ob1 = g_ctxh + (size_t)(b * Tt + q0 + r1) * Cc + h * Dd;
#pragma unroll
    for (int nt = 0; nt < 8; nt++) {
        *(uint32_t*)&ob0[nt * 8 + 2 * tig] =
            h2u(__floats2half2_rn(o[nt][0] * inv0, o[nt][1] * inv0));
        *(uint32_t*)&ob1[nt * 8 + 2 * tig] =
            h2u(__floats2half2_rn(o[nt][2] * inv1, o[nt][3] * inv1));
    }
}

// ---------------------------------------------------------------------------
// Launch
// ---------------------------------------------------------------------------
extern "C" void kernel_launch(void* const* d_in, const int* in_sizes, int n_in,
                              void* d_out, int out_size) {
    const float* x    = (const float*)d_in[0];
    const int*   mask = (const int*)d_in[1];
    const int*   cdrs = (const int*)d_in[2];
    const float* Wq   = (const float*)d_in[3];
    const float* bq   = (const float*)d_in[4];
    const float* Wk   = (const float*)d_in[5];
    const float* bk   = (const float*)d_in[6];
    const float* Wv   = (const float*)d_in[7];
    const float* bv   = (const float*)d_in[8];
    const float* Wo   = (const float*)d_in[9];
    const float* bo   = (const float*)d_in[10];
    float* out = (float*)d_out;

    // fused prep: x/W conversions + allm flag
    dim3 gprep((Bb * Tt * Cc / 4 + 255) / 256, 6);
    prep_kernel<<<gprep, 256>>>(x, Wq, Wk, Wv, Wo, cdrs);

    cudaFuncSetAttribute(gemm_qkv, cudaFuncAttributeMaxDynamicSharedMemorySize,
                         GEMM_SMEM);
    cudaFuncSetAttribute(gemm_out, cudaFuncAttributeMaxDynamicSharedMemorySize,
                         GEMM_SMEM);

    dim3 gqkv(Bb * Tt / 128, Cc / 128, 3);
    gemm_qkv<<<gqkv, 256, GEMM_SMEM>>>(bq, bk, bv);

    size_t shbytes = (size_t)(128 + 3 * 64 + 3 * 64) * QP * sizeof(__half);  // 73728
    cudaFuncSetAttribute(attn_kernel, cudaFuncAttributeMaxDynamicSharedMemorySize,
                         (int)shbytes);
    dim3 gatt(Tt / 128, Hh, Bb);
    attn_kernel<<<gatt, 256, shbytes>>>(mask, cdrs);

    dim3 gout(Bb * Tt / 128, Cc / 128, 1);
    gemm_out<<<gout, 256, GEMM_SMEM>>>(bo, out);
}

// round 10
// speedup vs baseline: 10.1302x; 1.0006x over previous
#include <cuda_runtime.h>
#include <cuda_fp16.h>
#include <cstdint>

// Problem constants
#define Bb   4
#define Tt   2048
#define Cc   512
#define Hh   8
#define Dd   64
#define CDRH 2

#define NEG_INF  __int_as_float(0xff800000)
#define M_INIT   -1.0e30f
#define SCALE2 0.18033688011112042f   // 0.125 * log2(e)

// Scratch (allocation-free: module-static device globals)
__device__ __half g_xh[Bb * Tt * Cc];
__device__ __half g_wh[4][Cc * Cc];    // Wq, Wk, Wv, Wo in half
__device__ __half g_qh[Bb * Tt * Cc];
__device__ __half g_kh[Bb * Tt * Cc];
__device__ __half g_vh[Bb * Tt * Cc];
__device__ __half g_ctxh[Bb * Tt * Cc];
__device__ int    g_allm[Bb];

// ---------------------------------------------------------------------------
// helpers
// ---------------------------------------------------------------------------
__device__ __forceinline__ void mma_f16(float c[4], const uint32_t a[4],
                                        uint32_t b0, uint32_t b1) {
    asm volatile(
        "mma.sync.aligned.m16n8k16.row.col.f32.f16.f16.f32 "
        "{%0,%1,%2,%3}, {%4,%5,%6,%7}, {%8,%9}, {%0,%1,%2,%3};"
        : "+f"(c[0]), "+f"(c[1]), "+f"(c[2]), "+f"(c[3])
        : "r"(a[0]), "r"(a[1]), "r"(a[2]), "r"(a[3]), "r"(b0), "r"(b1));
}

__device__ __forceinline__ void ldsm_x4(uint32_t r[4], uint32_t addr) {
    asm volatile("ldmatrix.sync.aligned.m8n8.x4.shared.b16 {%0,%1,%2,%3}, [%4];"
                 : "=r"(r[0]), "=r"(r[1]), "=r"(r[2]), "=r"(r[3]) : "r"(addr));
}

__device__ __forceinline__ void ldsm_x4_t(uint32_t r[4], uint32_t addr) {
    asm volatile("ldmatrix.sync.aligned.m8n8.x4.trans.shared.b16 {%0,%1,%2,%3}, [%4];"
                 : "=r"(r[0]), "=r"(r[1]), "=r"(r[2]), "=r"(r[3]) : "r"(addr));
}

__device__ __forceinline__ uint32_t h2u(__half2 h) {
    return *reinterpret_cast<uint32_t*>(&h);
}

__device__ __forceinline__ float ex2(float x) {
    float y;
    asm("ex2.approx.f32 %0, %1;" : "=f"(y) : "f"(x));
    return y;
}

__device__ __forceinline__ void cp16(uint32_t dst, const void* src) {
    asm volatile("cp.async.cg.shared.global [%0], [%1], 16;" :: "r"(dst), "l"(src));
}
__device__ __forceinline__ void cp_commit() {
    asm volatile("cp.async.commit_group;");
}
template <int N>
__device__ __forceinline__ void cp_wait() {
    asm volatile("cp.async.wait_group %0;" :: "n"(N));
}

// ---------------------------------------------------------------------------
// Fused prep: fp32->half for x + 4 weights (grid.y 0..4), allm flag (y==5)
// ---------------------------------------------------------------------------
__global__ void prep_kernel(const float* __restrict__ x,
                            const float* __restrict__ Wq,
                            const float* __restrict__ Wk,
                            const float* __restrict__ Wv,
                            const float* __restrict__ Wo,
                            const int* __restrict__ cdrs) {
    const int y = blockIdx.y;
    if (y == 5) {
        int b = blockIdx.x;
        if (b >= Bb) return;
        __shared__ int any;
        if (threadIdx.x == 0) any = 0;
        __syncthreads();
        int local = 0;
        for (int t = threadIdx.x; t < Tt; t += blockDim.x)
            local |= (cdrs[b * Tt + t] != 0);
        if (local) any = 1;
        __syncthreads();
        if (threadIdx.x == 0) g_allm[b] = (any == 0) ? 1 : 0;
        return;
    }
    const float* src; __half* dst; int n4;
    switch (y) {
        case 0: src = x;  dst = g_xh;    n4 = Bb * Tt * Cc / 4; break;
        case 1: src = Wq; dst = g_wh[0]; n4 = Cc * Cc / 4; break;
        case 2: src = Wk; dst = g_wh[1]; n4 = Cc * Cc / 4; break;
        case 3: src = Wv; dst = g_wh[2]; n4 = Cc * Cc / 4; break;
        default: src = Wo; dst = g_wh[3]; n4 = Cc * Cc / 4; break;
    }
    int i = blockIdx.x * blockDim.x + threadIdx.x;
    if (i < n4) {
        float4 v = ((const float4*)src)[i];
        uint2 w;
        w.x = h2u(__floats2half2_rn(v.x, v.y));
        w.y = h2u(__floats2half2_rn(v.z, v.w));
        ((uint2*)dst)[i] = w;
    }
}

// ---------------------------------------------------------------------------
// fp16 tensor-core GEMM, 4-stage cp.async pipeline, ONE sync per k-tile.
// out[M,512] = A[M,512] @ W[512,512] + bias.  A, W in half.
// BM=BN=128, BK=32; 8 warps (2m x 4n); warp tile 64x32 via m16n8k16 + LDSM.
// ---------------------------------------------------------------------------
#define APIT 40    // As pitch in halves (80 B)
#define BPIT 136   // Bs pitch in halves (272 B)
#define AS_BYTES (128 * APIT * 2)
#define BS_BYTES (32 * BPIT * 2)
#define GEMM_SMEM (4 * (AS_BYTES + BS_BYTES))

template <typename OutT>
__device__ __forceinline__ void gemm_f16_body(const __half* __restrict__ A,
                                              const __half* __restrict__ W,
                                              const float* __restrict__ bias,
                                              OutT* __restrict__ out) {
    extern __shared__ __align__(16) __half gsh[];
    __half* As = gsh;                          // [4][128][APIT]
    __half* Bs = gsh + 4 * 128 * APIT;         // [4][32][BPIT]
    const int tid  = threadIdx.x;
    const int warp = tid >> 5;
    const int lane = tid & 31;
    const int g    = lane >> 2;
    const int tig  = lane & 3;
    const int mf   = lane >> 3;
    const int rr   = lane & 7;
    const int wm   = warp >> 2;
    const int wn   = warp & 3;
    const int m0 = blockIdx.x * 128, n0 = blockIdx.y * 128;

    const uint32_t as_u = (uint32_t)__cvta_generic_to_shared(As);
    const uint32_t bs_u = (uint32_t)__cvta_generic_to_shared(Bs);

    auto issue_tiles = [&](int k0, int buf) {
#pragma unroll
        for (int p = 0; p < 2; p++) {
            int li = p * 256 + tid;        // 128 rows x 4 chunks
            int r  = li >> 2;
            int c  = (li & 3) * 8;
            cp16(as_u + buf * AS_BYTES + (r * APIT + c) * 2,
                 A + (size_t)(m0 + r) * Cc + k0 + c);
        }
#pragma unroll
        for (int p = 0; p < 2; p++) {
            int li = p * 256 + tid;        // 32 rows x 16 chunks
            int r  = li >> 4;
            int c  = (li & 15) * 8;
            cp16(bs_u + buf * BS_BYTES + (r * BPIT + c) * 2,
                 W + (size_t)(k0 + r) * Cc + n0 + c);
        }
    };

    float acc[4][4][4] = {};

    issue_tiles(0, 0);  cp_commit();
    issue_tiles(32, 1); cp_commit();
    issue_tiles(64, 2); cp_commit();

    for (int kt = 0; kt < 16; kt++) {
        const int cur = kt & 3;
        cp_wait<2>();
        __syncthreads();
        if (kt + 3 < 16) issue_tiles((kt + 3) * 32, (kt + 3) & 3);
        cp_commit();

        const uint32_t abase = as_u + cur * AS_BYTES;
        const uint32_t bbase = bs_u + cur * BS_BYTES;
#pragma unroll
        for (int kc = 0; kc < 2; kc++) {
            uint32_t af[4][4];
#pragma unroll
            for (int mt = 0; mt < 4; mt++) {
                int row = wm * 64 + mt * 16 + rr + (mf & 1) * 8;
                int col = kc * 16 + (mf >> 1) * 8;
                ldsm_x4(af[mt], abase + (row * APIT + col) * 2);
            }
            uint32_t bf[2][4];
#pragma unroll
            for (int p = 0; p < 2; p++) {
                int krow = kc * 16 + (mf & 1) * 8 + rr;
                int ncol = wn * 32 + (2 * p + (mf >> 1)) * 8;
                ldsm_x4_t(bf[p], bbase + (krow * BPIT + ncol) * 2);
            }
#pragma unroll
            for (int mt = 0; mt < 4; mt++)
#pragma unroll
                for (int p = 0; p < 2; p++) {
                    mma_f16(acc[mt][2 * p],     af[mt], bf[p][0], bf[p][1]);
                    mma_f16(acc[mt][2 * p + 1], af[mt], bf[p][2], bf[p][3]);
                }
        }
    }

    // epilogue: add bias, store
#pragma unroll
    for (int mt = 0; mt < 4; mt++) {
        int r0g = m0 + wm * 64 + mt * 16 + g;
        int r1g = r0g + 8;
#pragma unroll
        for (int nt = 0; nt < 4; nt++) {
            int n = n0 + wn * 32 + nt * 8 + 2 * tig;
            float b0 = bias[n], b1 = bias[n + 1];
            float v00 = acc[mt][nt][0] + b0, v01 = acc[mt][nt][1] + b1;
            float v10 = acc[mt][nt][2] + b0, v11 = acc[mt][nt][3] + b1;
            if constexpr (sizeof(OutT) == 2) {
                *(uint32_t*)&out[(size_t)r0g * Cc + n] = h2u(__floats2half2_rn(v00, v01));
                *(uint32_t*)&out[(size_t)r1g * Cc + n] = h2u(__floats2half2_rn(v10, v11));
            } else {
                float2 w0 = {v00, v01};
                float2 w1 = {v10, v11};
                *(float2*)&out[(size_t)r0g * Cc + n] = w0;
                *(float2*)&out[(size_t)r1g * Cc + n] = w1;
            }
        }
    }
}

__global__ __launch_bounds__(256, 2)
void gemm_qkv(const float* __restrict__ bq, const float* __restrict__ bk,
              const float* __restrict__ bv) {
    const __half* W; const float* bi; __half* out;
    if (blockIdx.z == 0)      { W = g_wh[0]; bi = bq; out = g_qh; }
    else if (blockIdx.z == 1) { W = g_wh[1]; bi = bk; out = g_kh; }
    else                      { W = g_wh[2]; bi = bv; out = g_vh; }
    gemm_f16_body<__half>(g_xh, W, bi, out);
}

__global__ __launch_bounds__(256, 2)
void gemm_out(const float* __restrict__ bo, float* __restrict__ out) {
    gemm_f16_body<float>(g_ctxh, g_wh[3], bo, out);
}

// ---------------------------------------------------------------------------
// fp16 tensor-core flash attention: 4-stage cp.async, one sync per tile,
// whole key-mask bias precomputed once into smem, branchless log2 softmax.
// ---------------------------------------------------------------------------
#define QP 72
#define KS_BYTES (64 * QP * 2)
// dynamic smem: Q(128*QP) + 4*K + 4*V (halves) + kneg (2048 floats)
#define ATTN_SMEM ((128 * QP + 8 * 64 * QP) * 2 + Tt * 4)

__global__ __launch_bounds__(256)
void attn_kernel(const int* __restrict__ mask, const int* __restrict__ cdrs) {
    extern __shared__ __align__(16) __half sh[];
    __half* qs = sh;                       // [128][QP]
    __half* ks = sh + 128 * QP;            // [4][64][QP]
    __half* vs = ks + 4 * 64 * QP;         // [4][64][QP]
    float*  kneg = (float*)(vs + 4 * 64 * QP);   // [2048]

    const int q0   = blockIdx.x * 128;
    const int h    = blockIdx.y;
    const int b    = blockIdx.z;
    const int tid  = threadIdx.x;
    const int warp = tid >> 5;
    const int lane = tid & 31;
    const int g    = lane >> 2;
    const int tig  = lane & 3;
    const int mf   = lane >> 3;
    const int rr   = lane & 7;

    const bool iscdr = (h < CDRH) && (g_allm[b] == 0);

    const uint32_t qs_u = (uint32_t)__cvta_generic_to_shared(qs);
    const uint32_t ks_u = (uint32_t)__cvta_generic_to_shared(ks);
    const uint32_t vs_u = (uint32_t)__cvta_generic_to_shared(vs);

    const __half* kall = g_kh + (size_t)b * Tt * Cc + h * Dd;
    const __half* vall = g_vh + (size_t)b * Tt * Cc + h * Dd;

    auto issue_kv = [&](int kt, int buf) {
        const __half* kbase = kall + (size_t)kt * 64 * Cc;
        const __half* vbase = vall + (size_t)kt * 64 * Cc;
#pragma unroll
        for (int p = 0; p < 2; p++) {
            int li = p * 256 + tid;       // 64 rows x 8 chunks
            int r  = li >> 3;
            int c  = (li & 7) * 8;
            cp16(ks_u + buf * KS_BYTES + (r * QP + c) * 2, kbase + (size_t)r * Cc + c);
        }
#pragma unroll
        for (int p = 0; p < 2; p++) {
            int li = p * 256 + tid;
            int r  = li >> 3;
            int c  = (li & 7) * 8;
            cp16(vs_u + buf * KS_BYTES + (r * QP + c) * 2, vbase + (size_t)r * Cc + c);
        }
    };

    // ---- prologue: Q + first 3 K/V tiles via cp.async; mask bias for all keys
    const __half* qbase = g_qh + (size_t)(b * Tt + q0) * Cc + h * Dd;
#pragma unroll
    for (int p = 0; p < 4; p++) {
        int li = p * 256 + tid;
        int r  = li >> 3;
        int c  = (li & 7) * 8;
        cp16(qs_u + (r * QP + c) * 2, qbase + (size_t)r * Cc + c);
    }
    cp_commit();
    issue_kv(0, 0); cp_commit();
    issue_kv(1, 1); cp_commit();
    issue_kv(2, 2); cp_commit();

    // full key-mask bias (one pass, reused for all 32 tiles)
#pragma unroll
    for (int p = 0; p < Tt / 256; p++) {
        int kg = p * 256 + tid;
        bool bad = (mask[b * Tt + kg] == 0) ||
                   (iscdr && (cdrs[b * Tt + kg] == 0));
        kneg[kg] = bad ? NEG_INF : 0.f;
    }

    cp_wait<3>();      // Q complete
    __syncthreads();   // Q + kneg visible

    // ---- hoist Q A-fragments ----
    uint32_t qa[4][4];
#pragma unroll
    for (int kc = 0; kc < 4; kc++) {
        int row = warp * 16 + rr + (mf & 1) * 8;
        int col = kc * 16 + (mf >> 1) * 8;
        ldsm_x4(qa[kc], qs_u + (row * QP + col) * 2);
    }

    float m_run[2] = {M_INIT, M_INIT};     // log2 domain, finite sentinel
    float l_run[2] = {0.f, 0.f};
    float o[8][4] = {};

    for (int kt = 0; kt < Tt / 64; kt++) {
        const int cur = kt & 3;
        cp_wait<2>();      // tile kt complete (kt+1, kt+2 may be in flight)
        __syncthreads();   // visibility + buffer (kt+3)&3 drained (iter kt-1)
        if (kt + 3 < Tt / 64) issue_kv(kt + 3, (kt + 3) & 3);
        cp_commit();

        const uint32_t kb = ks_u + cur * KS_BYTES;
        const uint32_t vb = vs_u + cur * KS_BYTES;
        const float* kn = kneg + kt * 64;

        // ---- S = Q K^T ----
        float s[8][4] = {};
#pragma unroll
        for (int kc = 0; kc < 4; kc++) {
#pragma unroll
            for (int p = 0; p < 4; p++) {
                int key = (2 * p + (mf >> 1)) * 8 + rr;
                int d   = kc * 16 + (mf & 1) * 8;
                uint32_t bk[4];
                ldsm_x4(bk, kb + (key * QP + d) * 2);
                mma_f16(s[2 * p],     qa[kc], bk[0], bk[1]);
                mma_f16(s[2 * p + 1], qa[kc], bk[2], bk[3]);
            }
        }

        // ---- scale (log2 domain) + key-mask bias ----
#pragma unroll
        for (int nt = 0; nt < 8; nt++) {
            float k0b = kn[nt * 8 + 2 * tig];
            float k1b = kn[nt * 8 + 2 * tig + 1];
            s[nt][0] = s[nt][0] * SCALE2 + k0b;
            s[nt][1] = s[nt][1] * SCALE2 + k1b;
            s[nt][2] = s[nt][2] * SCALE2 + k0b;
            s[nt][3] = s[nt][3] * SCALE2 + k1b;
        }

        // ---- branchless online softmax (base-2) ----
        float mt0 = NEG_INF, mt1 = NEG_INF;
#pragma unroll
        for (int nt = 0; nt < 8; nt++) {
            mt0 = fmaxf(mt0, fmaxf(s[nt][0], s[nt][1]));
            mt1 = fmaxf(mt1, fmaxf(s[nt][2], s[nt][3]));
        }
#pragma unroll
        for (int off = 1; off < 4; off <<= 1) {
            mt0 = fmaxf(mt0, __shfl_xor_sync(0xffffffffu, mt0, off));
            mt1 = fmaxf(mt1, __shfl_xor_sync(0xffffffffu, mt1, off));
        }
        float mn0 = fmaxf(m_run[0], mt0);   // >= -1e30, always finite
        float mn1 = fmaxf(m_run[1], mt1);
        float alpha0 = ex2(m_run[0] - mn0);
        float alpha1 = ex2(m_run[1] - mn1);
        float sum0 = 0.f, sum1 = 0.f;
#pragma unroll
        for (int nt = 0; nt < 8; nt++) {
            float p0 = ex2(s[nt][0] - mn0);   // s=-inf -> 0
            float p1 = ex2(s[nt][1] - mn0);
            float p2 = ex2(s[nt][2] - mn1);
            float p3 = ex2(s[nt][3] - mn1);
            s[nt][0] = p0; s[nt][1] = p1; s[nt][2] = p2; s[nt][3] = p3;
            sum0 += p0 + p1;
            sum1 += p2 + p3;
        }
#pragma unroll
        for (int off = 1; off < 4; off <<= 1) {
            sum0 += __shfl_xor_sync(0xffffffffu, sum0, off);
            sum1 += __shfl_xor_sync(0xffffffffu, sum1, off);
        }
        m_run[0] = mn0;  l_run[0] = l_run[0] * alpha0 + sum0;
        m_run[1] = mn1;  l_run[1] = l_run[1] * alpha1 + sum1;

#pragma unroll
        for (int nt = 0; nt < 8; nt++) {
            o[nt][0] *= alpha0; o[nt][1] *= alpha0;
            o[nt][2] *= alpha1; o[nt][3] *= alpha1;
        }

        // ---- O += P @ V (P in registers) ----
#pragma unroll
        for (int kc = 0; kc < 4; kc++) {
            uint32_t pa[4];
            pa[0] = h2u(__floats2half2_rn(s[2 * kc][0],     s[2 * kc][1]));
            pa[1] = h2u(__floats2half2_rn(s[2 * kc][2],     s[2 * kc][3]));
            pa[2] = h2u(__floats2half2_rn(s[2 * kc + 1][0], s[2 * kc + 1][1]));
            pa[3] = h2u(__floats2half2_rn(s[2 * kc + 1][2], s[2 * kc + 1][3]));
#pragma unroll
            for (int p = 0; p < 4; p++) {
                int key = kc * 16 + (mf & 1) * 8 + rr;
                int d   = (2 * p + (mf >> 1)) * 8;
                uint32_t bv[4];
                ldsm_x4_t(bv, vb + (key * QP + d) * 2);
                mma_f16(o[2 * p],     pa, bv[0], bv[1]);
                mma_f16(o[2 * p + 1], pa, bv[2], bv[3]);
            }
        }
    }

    // ---- epilogue: normalize, write ctx (half) ----
    const int r0 = warp * 16 + g;
    const int r1 = r0 + 8;
    float inv0 = 1.f / l_run[0];
    float inv1 = 1.f / l_run[1];
    __half* ob0 = g_ctxh + (size_t)(b * Tt + q0 + r0) * Cc + h * Dd;
    __half* ob1 = g_ctxh + (size_t)(b * Tt + q0 + r1) * Cc + h * Dd;
#pragma unroll
    for (int nt = 0; nt < 8; nt++) {
        *(uint32_t*)&ob0[nt * 8 + 2 * tig] =
            h2u(__floats2half2_rn(o[nt][0] * inv0, o[nt][1] * inv0));
        *(uint32_t*)&ob1[nt * 8 + 2 * tig] =
            h2u(__floats2half2_rn(o[nt][2] * inv1, o[nt][3] * inv1));
    }
}

// ---------------------------------------------------------------------------
// Launch
// ---------------------------------------------------------------------------
extern "C" void kernel_launch(void* const* d_in, const int* in_sizes, int n_in,
                              void* d_out, int out_size) {
    const float* x    = (const float*)d_in[0];
    const int*   mask = (const int*)d_in[1];
    const int*   cdrs = (const int*)d_in[2];
    const float* Wq   = (const float*)d_in[3];
    const float* bq   = (const float*)d_in[4];
    const float* Wk   = (const float*)d_in[5];
    const float* bk   = (const float*)d_in[6];
    const float* Wv   = (const float*)d_in[7];
    const float* bv   = (const float*)d_in[8];
    const float* Wo   = (const float*)d_in[9];
    const float* bo   = (const float*)d_in[10];
    float* out = (float*)d_out;

    // fused prep: x/W conversions + allm flag
    dim3 gprep((Bb * Tt * Cc / 4 + 255) / 256, 6);
    prep_kernel<<<gprep, 256>>>(x, Wq, Wk, Wv, Wo, cdrs);

    cudaFuncSetAttribute(gemm_qkv, cudaFuncAttributeMaxDynamicSharedMemorySize,
                         GEMM_SMEM);
    cudaFuncSetAttribute(gemm_out, cudaFuncAttributeMaxDynamicSharedMemorySize,
                         GEMM_SMEM);

    dim3 gqkv(Bb * Tt / 128, Cc / 128, 3);
    gemm_qkv<<<gqkv, 256, GEMM_SMEM>>>(bq, bk, bv);

    cudaFuncSetAttribute(attn_kernel, cudaFuncAttributeMaxDynamicSharedMemorySize,
                         ATTN_SMEM);
    dim3 gatt(Tt / 128, Hh, Bb);
    attn_kernel<<<gatt, 256, ATTN_SMEM>>>(mask, cdrs);

    dim3 gout(Bb * Tt / 128, Cc / 128, 1);
    gemm_out<<<gout, 256, GEMM_SMEM>>>(bo, out);
}

// round 11
// speedup vs baseline: 10.7806x; 1.0642x over previous
#include <cuda_runtime.h>
#include <cuda_fp16.h>
#include <cstdint>

// Problem constants
#define Bb   4
#define Tt   2048
#define Cc   512
#define Hh   8
#define Dd   64
#define CDRH 2

#define NEG_INF  __int_as_float(0xff800000)
#define M_INIT   -1.0e30f
#define SCALE2 0.18033688011112042f   // 0.125 * log2(e)

// Scratch (allocation-free: module-static device globals)
__device__ __half g_xh[Bb * Tt * Cc];
__device__ __half g_wh[4][Cc * Cc];    // Wq, Wk, Wv, Wo in half
__device__ __half g_qh[Bb * Tt * Cc];
__device__ __half g_kh[Bb * Tt * Cc];
__device__ __half g_vh[Bb * Tt * Cc];
__device__ __half g_ctxh[Bb * Tt * Cc];
__device__ int    g_allm[Bb];

// ---------------------------------------------------------------------------
// helpers
// ---------------------------------------------------------------------------
__device__ __forceinline__ void mma_f16(float c[4], const uint32_t a[4],
                                        uint32_t b0, uint32_t b1) {
    asm volatile(
        "mma.sync.aligned.m16n8k16.row.col.f32.f16.f16.f32 "
        "{%0,%1,%2,%3}, {%4,%5,%6,%7}, {%8,%9}, {%0,%1,%2,%3};"
        : "+f"(c[0]), "+f"(c[1]), "+f"(c[2]), "+f"(c[3])
        : "r"(a[0]), "r"(a[1]), "r"(a[2]), "r"(a[3]), "r"(b0), "r"(b1));
}

__device__ __forceinline__ void ldsm_x4(uint32_t r[4], uint32_t addr) {
    asm volatile("ldmatrix.sync.aligned.m8n8.x4.shared.b16 {%0,%1,%2,%3}, [%4];"
                 : "=r"(r[0]), "=r"(r[1]), "=r"(r[2]), "=r"(r[3]) : "r"(addr));
}

__device__ __forceinline__ void ldsm_x4_t(uint32_t r[4], uint32_t addr) {
    asm volatile("ldmatrix.sync.aligned.m8n8.x4.trans.shared.b16 {%0,%1,%2,%3}, [%4];"
                 : "=r"(r[0]), "=r"(r[1]), "=r"(r[2]), "=r"(r[3]) : "r"(addr));
}

__device__ __forceinline__ uint32_t h2u(__half2 h) {
    return *reinterpret_cast<uint32_t*>(&h);
}

__device__ __forceinline__ float ex2(float x) {
    float y;
    asm("ex2.approx.f32 %0, %1;" : "=f"(y) : "f"(x));
    return y;
}

__device__ __forceinline__ void cp16(uint32_t dst, const void* src) {
    asm volatile("cp.async.cg.shared.global [%0], [%1], 16;" :: "r"(dst), "l"(src));
}
__device__ __forceinline__ void cp_commit() {
    asm volatile("cp.async.commit_group;");
}
template <int N>
__device__ __forceinline__ void cp_wait() {
    asm volatile("cp.async.wait_group %0;" :: "n"(N));
}

// ---------------------------------------------------------------------------
// Fused prep: fp32->half for x + 4 weights (grid.y 0..4), allm flag (y==5)
// ---------------------------------------------------------------------------
__global__ void prep_kernel(const float* __restrict__ x,
                            const float* __restrict__ Wq,
                            const float* __restrict__ Wk,
                            const float* __restrict__ Wv,
                            const float* __restrict__ Wo,
                            const int* __restrict__ cdrs) {
    const int y = blockIdx.y;
    if (y == 5) {
        int b = blockIdx.x;
        if (b >= Bb) return;
        __shared__ int any;
        if (threadIdx.x == 0) any = 0;
        __syncthreads();
        int local = 0;
        for (int t = threadIdx.x; t < Tt; t += blockDim.x)
            local |= (cdrs[b * Tt + t] != 0);
        if (local) any = 1;
        __syncthreads();
        if (threadIdx.x == 0) g_allm[b] = (any == 0) ? 1 : 0;
        return;
    }
    const float* src; __half* dst; int n4;
    switch (y) {
        case 0: src = x;  dst = g_xh;    n4 = Bb * Tt * Cc / 4; break;
        case 1: src = Wq; dst = g_wh[0]; n4 = Cc * Cc / 4; break;
        case 2: src = Wk; dst = g_wh[1]; n4 = Cc * Cc / 4; break;
        case 3: src = Wv; dst = g_wh[2]; n4 = Cc * Cc / 4; break;
        default: src = Wo; dst = g_wh[3]; n4 = Cc * Cc / 4; break;
    }
    int i = blockIdx.x * blockDim.x + threadIdx.x;
    if (i < n4) {
        float4 v = ((const float4*)src)[i];
        uint2 w;
        w.x = h2u(__floats2half2_rn(v.x, v.y));
        w.y = h2u(__floats2half2_rn(v.z, v.w));
        ((uint2*)dst)[i] = w;
    }
}

// ---------------------------------------------------------------------------
// fp16 tensor-core GEMM, 3-stage cp.async pipeline, ONE sync per k-tile.
// out[M,512] = A[M,512] @ W[512,512] + bias.  A, W in half.
// BM=BN=128, BK=32; 8 warps (2m x 4n); warp tile 64x32 via m16n8k16 + LDSM.
// ---------------------------------------------------------------------------
#define APIT 40    // As pitch in halves (80 B)
#define BPIT 136   // Bs pitch in halves (272 B)
#define AS_BYTES (128 * APIT * 2)
#define BS_BYTES (32 * BPIT * 2)
#define GEMM_SMEM (3 * (AS_BYTES + BS_BYTES))

template <typename OutT>
__device__ __forceinline__ void gemm_f16_body(const __half* __restrict__ A,
                                              const __half* __restrict__ W,
                                              const float* __restrict__ bias,
                                              OutT* __restrict__ out) {
    extern __shared__ __align__(16) __half gsh[];
    __half* As = gsh;                          // [3][128][APIT]
    __half* Bs = gsh + 3 * 128 * APIT;         // [3][32][BPIT]
    const int tid  = threadIdx.x;
    const int warp = tid >> 5;
    const int lane = tid & 31;
    const int g    = lane >> 2;
    const int tig  = lane & 3;
    const int mf   = lane >> 3;
    const int rr   = lane & 7;
    const int wm   = warp >> 2;
    const int wn   = warp & 3;
    const int m0 = blockIdx.x * 128, n0 = blockIdx.y * 128;

    const uint32_t as_u = (uint32_t)__cvta_generic_to_shared(As);
    const uint32_t bs_u = (uint32_t)__cvta_generic_to_shared(Bs);

    auto issue_tiles = [&](int k0, int buf) {
#pragma unroll
        for (int p = 0; p < 2; p++) {
            int li = p * 256 + tid;        // 128 rows x 4 chunks
            int r  = li >> 2;
            int c  = (li & 3) * 8;
            cp16(as_u + buf * AS_BYTES + (r * APIT + c) * 2,
                 A + (size_t)(m0 + r) * Cc + k0 + c);
        }
#pragma unroll
        for (int p = 0; p < 2; p++) {
            int li = p * 256 + tid;        // 32 rows x 16 chunks
            int r  = li >> 4;
            int c  = (li & 15) * 8;
            cp16(bs_u + buf * BS_BYTES + (r * BPIT + c) * 2,
                 W + (size_t)(k0 + r) * Cc + n0 + c);
        }
    };

    float acc[4][4][4] = {};

    issue_tiles(0, 0);  cp_commit();
    issue_tiles(32, 1); cp_commit();

    for (int kt = 0; kt < 16; kt++) {
        const int cur = kt % 3;
        cp_wait<1>();
        __syncthreads();
        if (kt + 2 < 16) issue_tiles((kt + 2) * 32, (kt + 2) % 3);
        cp_commit();

        const uint32_t abase = as_u + cur * AS_BYTES;
        const uint32_t bbase = bs_u + cur * BS_BYTES;
#pragma unroll
        for (int kc = 0; kc < 2; kc++) {
            uint32_t af[4][4];
#pragma unroll
            for (int mt = 0; mt < 4; mt++) {
                int row = wm * 64 + mt * 16 + rr + (mf & 1) * 8;
                int col = kc * 16 + (mf >> 1) * 8;
                ldsm_x4(af[mt], abase + (row * APIT + col) * 2);
            }
            uint32_t bf[2][4];
#pragma unroll
            for (int p = 0; p < 2; p++) {
                int krow = kc * 16 + (mf & 1) * 8 + rr;
                int ncol = wn * 32 + (2 * p + (mf >> 1)) * 8;
                ldsm_x4_t(bf[p], bbase + (krow * BPIT + ncol) * 2);
            }
#pragma unroll
            for (int mt = 0; mt < 4; mt++)
#pragma unroll
                for (int p = 0; p < 2; p++) {
                    mma_f16(acc[mt][2 * p],     af[mt], bf[p][0], bf[p][1]);
                    mma_f16(acc[mt][2 * p + 1], af[mt], bf[p][2], bf[p][3]);
                }
        }
    }

    // epilogue: add bias, store
#pragma unroll
    for (int mt = 0; mt < 4; mt++) {
        int r0g = m0 + wm * 64 + mt * 16 + g;
        int r1g = r0g + 8;
#pragma unroll
        for (int nt = 0; nt < 4; nt++) {
            int n = n0 + wn * 32 + nt * 8 + 2 * tig;
            float b0 = bias[n], b1 = bias[n + 1];
            float v00 = acc[mt][nt][0] + b0, v01 = acc[mt][nt][1] + b1;
            float v10 = acc[mt][nt][2] + b0, v11 = acc[mt][nt][3] + b1;
            if constexpr (sizeof(OutT) == 2) {
                *(uint32_t*)&out[(size_t)r0g * Cc + n] = h2u(__floats2half2_rn(v00, v01));
                *(uint32_t*)&out[(size_t)r1g * Cc + n] = h2u(__floats2half2_rn(v10, v11));
            } else {
                float2 w0 = {v00, v01};
                float2 w1 = {v10, v11};
                *(float2*)&out[(size_t)r0g * Cc + n] = w0;
                *(float2*)&out[(size_t)r1g * Cc + n] = w1;
            }
        }
    }
}

__global__ __launch_bounds__(256, 2)
void gemm_qkv(const float* __restrict__ bq, const float* __restrict__ bk,
              const float* __restrict__ bv) {
    const __half* W; const float* bi; __half* out;
    if (blockIdx.z == 0)      { W = g_wh[0]; bi = bq; out = g_qh; }
    else if (blockIdx.z == 1) { W = g_wh[1]; bi = bk; out = g_kh; }
    else                      { W = g_wh[2]; bi = bv; out = g_vh; }
    gemm_f16_body<__half>(g_xh, W, bi, out);
}

__global__ __launch_bounds__(256, 2)
void gemm_out(const float* __restrict__ bo, float* __restrict__ out) {
    gemm_f16_body<float>(g_ctxh, g_wh[3], bo, out);
}

// ---------------------------------------------------------------------------
// fp16 tensor-core flash attention: 3-stage cp.async, one sync per tile,
// whole key-mask bias precomputed once, branchless log2 softmax.
// smem = 80 KB -> 2 CTAs/SM (16 warps) so one CTA's softmax overlaps the
// other CTA's MMA/LDSM phase.
// ---------------------------------------------------------------------------
#define QP 72
#define KS_BYTES (64 * QP * 2)
// dynamic smem: Q(128*QP) + 3*K + 3*V (halves) + kneg (2048 floats) = 81920 B
#define ATTN_SMEM ((128 * QP + 6 * 64 * QP) * 2 + Tt * 4)

__global__ __launch_bounds__(256, 2)
void attn_kernel(const int* __restrict__ mask, const int* __restrict__ cdrs) {
    extern __shared__ __align__(16) __half sh[];
    __half* qs = sh;                       // [128][QP]
    __half* ks = sh + 128 * QP;            // [3][64][QP]
    __half* vs = ks + 3 * 64 * QP;         // [3][64][QP]
    float*  kneg = (float*)(vs + 3 * 64 * QP);   // [2048]

    const int q0   = blockIdx.x * 128;
    const int h    = blockIdx.y;
    const int b    = blockIdx.z;
    const int tid  = threadIdx.x;
    const int warp = tid >> 5;
    const int lane = tid & 31;
    const int g    = lane >> 2;
    const int tig  = lane & 3;
    const int mf   = lane >> 3;
    const int rr   = lane & 7;

    const bool iscdr = (h < CDRH) && (g_allm[b] == 0);

    const uint32_t qs_u = (uint32_t)__cvta_generic_to_shared(qs);
    const uint32_t ks_u = (uint32_t)__cvta_generic_to_shared(ks);
    const uint32_t vs_u = (uint32_t)__cvta_generic_to_shared(vs);

    const __half* kall = g_kh + (size_t)b * Tt * Cc + h * Dd;
    const __half* vall = g_vh + (size_t)b * Tt * Cc + h * Dd;

    auto issue_kv = [&](int kt, int buf) {
        const __half* kbase = kall + (size_t)kt * 64 * Cc;
        const __half* vbase = vall + (size_t)kt * 64 * Cc;
#pragma unroll
        for (int p = 0; p < 2; p++) {
            int li = p * 256 + tid;       // 64 rows x 8 chunks
            int r  = li >> 3;
            int c  = (li & 7) * 8;
            cp16(ks_u + buf * KS_BYTES + (r * QP + c) * 2, kbase + (size_t)r * Cc + c);
        }
#pragma unroll
        for (int p = 0; p < 2; p++) {
            int li = p * 256 + tid;
            int r  = li >> 3;
            int c  = (li & 7) * 8;
            cp16(vs_u + buf * KS_BYTES + (r * QP + c) * 2, vbase + (size_t)r * Cc + c);
        }
    };

    // ---- prologue: Q + first 2 K/V tiles via cp.async; mask bias for all keys
    const __half* qbase = g_qh + (size_t)(b * Tt + q0) * Cc + h * Dd;
#pragma unroll
    for (int p = 0; p < 4; p++) {
        int li = p * 256 + tid;
        int r  = li >> 3;
        int c  = (li & 7) * 8;
        cp16(qs_u + (r * QP + c) * 2, qbase + (size_t)r * Cc + c);
    }
    cp_commit();
    issue_kv(0, 0); cp_commit();
    issue_kv(1, 1); cp_commit();

    // full key-mask bias (one pass, reused for all 32 tiles)
#pragma unroll
    for (int p = 0; p < Tt / 256; p++) {
        int kg = p * 256 + tid;
        bool bad = (mask[b * Tt + kg] == 0) ||
                   (iscdr && (cdrs[b * Tt + kg] == 0));
        kneg[kg] = bad ? NEG_INF : 0.f;
    }

    cp_wait<2>();      // Q complete
    __syncthreads();   // Q + kneg visible

    // ---- hoist Q A-fragments ----
    uint32_t qa[4][4];
#pragma unroll
    for (int kc = 0; kc < 4; kc++) {
        int row = warp * 16 + rr + (mf & 1) * 8;
        int col = kc * 16 + (mf >> 1) * 8;
        ldsm_x4(qa[kc], qs_u + (row * QP + col) * 2);
    }

    float m_run[2] = {M_INIT, M_INIT};     // log2 domain, finite sentinel
    float l_run[2] = {0.f, 0.f};
    float o[8][4] = {};

    for (int kt = 0; kt < Tt / 64; kt++) {
        const int cur = kt % 3;
        cp_wait<1>();      // tile kt complete (kt+1 may be in flight)
        __syncthreads();   // visibility + buffer (kt+2)%3 drained (iter kt-1)
        if (kt + 2 < Tt / 64) issue_kv(kt + 2, (kt + 2) % 3);
        cp_commit();

        const uint32_t kb = ks_u + cur * KS_BYTES;
        const uint32_t vb = vs_u + cur * KS_BYTES;
        const float* kn = kneg + kt * 64;

        // ---- S = Q K^T ----
        float s[8][4] = {};
#pragma unroll
        for (int kc = 0; kc < 4; kc++) {
#pragma unroll
            for (int p = 0; p < 4; p++) {
                int key = (2 * p + (mf >> 1)) * 8 + rr;
                int d   = kc * 16 + (mf & 1) * 8;
                uint32_t bk[4];
                ldsm_x4(bk, kb + (key * QP + d) * 2);
                mma_f16(s[2 * p],     qa[kc], bk[0], bk[1]);
                mma_f16(s[2 * p + 1], qa[kc], bk[2], bk[3]);
            }
        }

        // ---- scale (log2 domain) + key-mask bias ----
#pragma unroll
        for (int nt = 0; nt < 8; nt++) {
            float k0b = kn[nt * 8 + 2 * tig];
            float k1b = kn[nt * 8 + 2 * tig + 1];
            s[nt][0] = s[nt][0] * SCALE2 + k0b;
            s[nt][1] = s[nt][1] * SCALE2 + k1b;
            s[nt][2] = s[nt][2] * SCALE2 + k0b;
            s[nt][3] = s[nt][3] * SCALE2 + k1b;
        }

        // ---- branchless online softmax (base-2) ----
        float mt0 = NEG_INF, mt1 = NEG_INF;
#pragma unroll
        for (int nt = 0; nt < 8; nt++) {
            mt0 = fmaxf(mt0, fmaxf(s[nt][0], s[nt][1]));
            mt1 = fmaxf(mt1, fmaxf(s[nt][2], s[nt][3]));
        }
#pragma unroll
        for (int off = 1; off < 4; off <<= 1) {
            mt0 = fmaxf(mt0, __shfl_xor_sync(0xffffffffu, mt0, off));
            mt1 = fmaxf(mt1, __shfl_xor_sync(0xffffffffu, mt1, off));
        }
        float mn0 = fmaxf(m_run[0], mt0);   // >= -1e30, always finite
        float mn1 = fmaxf(m_run[1], mt1);
        float alpha0 = ex2(m_run[0] - mn0);
        float alpha1 = ex2(m_run[1] - mn1);
        float sum0 = 0.f, sum1 = 0.f;
#pragma unroll
        for (int nt = 0; nt < 8; nt++) {
            float p0 = ex2(s[nt][0] - mn0);   // s=-inf -> 0
            float p1 = ex2(s[nt][1] - mn0);
            float p2 = ex2(s[nt][2] - mn1);
            float p3 = ex2(s[nt][3] - mn1);
            s[nt][0] = p0; s[nt][1] = p1; s[nt][2] = p2; s[nt][3] = p3;
            sum0 += p0 + p1;
            sum1 += p2 + p3;
        }
#pragma unroll
        for (int off = 1; off < 4; off <<= 1) {
            sum0 += __shfl_xor_sync(0xffffffffu, sum0, off);
            sum1 += __shfl_xor_sync(0xffffffffu, sum1, off);
        }
        m_run[0] = mn0;  l_run[0] = l_run[0] * alpha0 + sum0;
        m_run[1] = mn1;  l_run[1] = l_run[1] * alpha1 + sum1;

#pragma unroll
        for (int nt = 0; nt < 8; nt++) {
            o[nt][0] *= alpha0; o[nt][1] *= alpha0;
            o[nt][2] *= alpha1; o[nt][3] *= alpha1;
        }

        // ---- O += P @ V (P in registers) ----
#pragma unroll
        for (int kc = 0; kc < 4; kc++) {
            uint32_t pa[4];
            pa[0] = h2u(__floats2half2_rn(s[2 * kc][0],     s[2 * kc][1]));
            pa[1] = h2u(__floats2half2_rn(s[2 * kc][2],     s[2 * kc][3]));
            pa[2] = h2u(__floats2half2_rn(s[2 * kc + 1][0], s[2 * kc + 1][1]));
            pa[3] = h2u(__floats2half2_rn(s[2 * kc + 1][2], s[2 * kc + 1][3]));
#pragma unroll
            for (int p = 0; p < 4; p++) {
                int key = kc * 16 + (mf & 1) * 8 + rr;
                int d   = (2 * p + (mf >> 1)) * 8;
                uint32_t bv[4];
                ldsm_x4_t(bv, vb + (key * QP + d) * 2);
                mma_f16(o[2 * p],     pa, bv[0], bv[1]);
                mma_f16(o[2 * p + 1], pa, bv[2], bv[3]);
            }
        }
    }

    // ---- epilogue: normalize, write ctx (half) ----
    const int r0 = warp * 16 + g;
    const int r1 = r0 + 8;
    float inv0 = 1.f / l_run[0];
    float inv1 = 1.f / l_run[1];
    __half* ob0 = g_ctxh + (size_t)(b * Tt + q0 + r0) * Cc + h * Dd;
    __half* ob1 = g_ctxh + (size_t)(b * Tt + q0 + r1) * Cc + h * Dd;
#pragma unroll
    for (int nt = 0; nt < 8; nt++) {
        *(uint32_t*)&ob0[nt * 8 + 2 * tig] =
            h2u(__floats2half2_rn(o[nt][0] * inv0, o[nt][1] * inv0));
        *(uint32_t*)&ob1[nt * 8 + 2 * tig] =
            h2u(__floats2half2_rn(o[nt][2] * inv1, o[nt][3] * inv1));
    }
}

// ---------------------------------------------------------------------------
// Launch
// ---------------------------------------------------------------------------
extern "C" void kernel_launch(void* const* d_in, const int* in_sizes, int n_in,
                              void* d_out, int out_size) {
    const float* x    = (const float*)d_in[0];
    const int*   mask = (const int*)d_in[1];
    const int*   cdrs = (const int*)d_in[2];
    const float* Wq   = (const float*)d_in[3];
    const float* bq   = (const float*)d_in[4];
    const float* Wk   = (const float*)d_in[5];
    const float* bk   = (const float*)d_in[6];
    const float* Wv   = (const float*)d_in[7];
    const float* bv   = (const float*)d_in[8];
    const float* Wo   = (const float*)d_in[9];
    const float* bo   = (const float*)d_in[10];
    float* out = (float*)d_out;

    // fused prep: x/W conversions + allm flag
    dim3 gprep((Bb * Tt * Cc / 4 + 255) / 256, 6);
    prep_kernel<<<gprep, 256>>>(x, Wq, Wk, Wv, Wo, cdrs);

    cudaFuncSetAttribute(gemm_qkv, cudaFuncAttributeMaxDynamicSharedMemorySize,
                         GEMM_SMEM);
    cudaFuncSetAttribute(gemm_out, cudaFuncAttributeMaxDynamicSharedMemorySize,
                         GEMM_SMEM);

    dim3 gqkv(Bb * Tt / 128, Cc / 128, 3);
    gemm_qkv<<<gqkv, 256, GEMM_SMEM>>>(bq, bk, bv);

    cudaFuncSetAttribute(attn_kernel, cudaFuncAttributeMaxDynamicSharedMemorySize,
                         ATTN_SMEM);
    dim3 gatt(Tt / 128, Hh, Bb);
    attn_kernel<<<gatt, 256, ATTN_SMEM>>>(mask, cdrs);

    dim3 gout(Bb * Tt / 128, Cc / 128, 1);
    gemm_out<<<gout, 256, GEMM_SMEM>>>(bo, out);
}

// round 12
// speedup vs baseline: 11.5089x; 1.0676x over previous
#include <cuda_runtime.h>
#include <cuda_fp16.h>
#include <cstdint>

// Problem constants
#define Bb   4
#define Tt   2048
#define Cc   512
#define Hh   8
#define Dd   64
#define CDRH 2

#define NEG_INF  __int_as_float(0xff800000)
#define M_INIT   -1.0e30f
#define SCALE2 0.18033688011112042f   // 0.125 * log2(e)
#define ONES_H2 0x3C003C00u           // half2(1.0, 1.0)

// Scratch (allocation-free: module-static device globals)
__device__ __half g_xh[Bb * Tt * Cc];
__device__ __half g_wh[4][Cc * Cc];    // Wq, Wk, Wv, Wo in half
__device__ __half g_qh[Bb * Tt * Cc];
__device__ __half g_kh[Bb * Tt * Cc];
__device__ __half g_vh[Bb * Tt * Cc];
__device__ __half g_ctxh[Bb * Tt * Cc];
__device__ int    g_allm[Bb];

// ---------------------------------------------------------------------------
// helpers
// ---------------------------------------------------------------------------
__device__ __forceinline__ void mma_f16(float c[4], const uint32_t a[4],
                                        uint32_t b0, uint32_t b1) {
    asm volatile(
        "mma.sync.aligned.m16n8k16.row.col.f32.f16.f16.f32 "
        "{%0,%1,%2,%3}, {%4,%5,%6,%7}, {%8,%9}, {%0,%1,%2,%3};"
        : "+f"(c[0]), "+f"(c[1]), "+f"(c[2]), "+f"(c[3])
        : "r"(a[0]), "r"(a[1]), "r"(a[2]), "r"(a[3]), "r"(b0), "r"(b1));
}

__device__ __forceinline__ void ldsm_x4(uint32_t r[4], uint32_t addr) {
    asm volatile("ldmatrix.sync.aligned.m8n8.x4.shared.b16 {%0,%1,%2,%3}, [%4];"
                 : "=r"(r[0]), "=r"(r[1]), "=r"(r[2]), "=r"(r[3]) : "r"(addr));
}

__device__ __forceinline__ void ldsm_x4_t(uint32_t r[4], uint32_t addr) {
    asm volatile("ldmatrix.sync.aligned.m8n8.x4.trans.shared.b16 {%0,%1,%2,%3}, [%4];"
                 : "=r"(r[0]), "=r"(r[1]), "=r"(r[2]), "=r"(r[3]) : "r"(addr));
}

__device__ __forceinline__ uint32_t h2u(__half2 h) {
    return *reinterpret_cast<uint32_t*>(&h);
}

__device__ __forceinline__ float ex2(float x) {
    float y;
    asm("ex2.approx.f32 %0, %1;" : "=f"(y) : "f"(x));
    return y;
}

// half2 exp2 of a packed pair
__device__ __forceinline__ uint32_t ex2h2(uint32_t x) {
    uint32_t y;
    asm("ex2.approx.f16x2 %0, %1;" : "=r"(y) : "r"(x));
    return y;
}

__device__ __forceinline__ void cp16(uint32_t dst, const void* src) {
    asm volatile("cp.async.cg.shared.global [%0], [%1], 16;" :: "r"(dst), "l"(src));
}
__device__ __forceinline__ void cp_commit() {
    asm volatile("cp.async.commit_group;");
}
template <int N>
__device__ __forceinline__ void cp_wait() {
    asm volatile("cp.async.wait_group %0;" :: "n"(N));
}

// ---------------------------------------------------------------------------
// Fused prep: fp32->half for x + 4 weights (grid.y 0..4), allm flag (y==5)
// ---------------------------------------------------------------------------
__global__ void prep_kernel(const float* __restrict__ x,
                            const float* __restrict__ Wq,
                            const float* __restrict__ Wk,
                            const float* __restrict__ Wv,
                            const float* __restrict__ Wo,
                            const int* __restrict__ cdrs) {
    const int y = blockIdx.y;
    if (y == 5) {
        int b = blockIdx.x;
        if (b >= Bb) return;
        __shared__ int any;
        if (threadIdx.x == 0) any = 0;
        __syncthreads();
        int local = 0;
        for (int t = threadIdx.x; t < Tt; t += blockDim.x)
            local |= (cdrs[b * Tt + t] != 0);
        if (local) any = 1;
        __syncthreads();
        if (threadIdx.x == 0) g_allm[b] = (any == 0) ? 1 : 0;
        return;
    }
    const float* src; __half* dst; int n4;
    switch (y) {
        case 0: src = x;  dst = g_xh;    n4 = Bb * Tt * Cc / 4; break;
        case 1: src = Wq; dst = g_wh[0]; n4 = Cc * Cc / 4; break;
        case 2: src = Wk; dst = g_wh[1]; n4 = Cc * Cc / 4; break;
        case 3: src = Wv; dst = g_wh[2]; n4 = Cc * Cc / 4; break;
        default: src = Wo; dst = g_wh[3]; n4 = Cc * Cc / 4; break;
    }
    int i = blockIdx.x * blockDim.x + threadIdx.x;
    if (i < n4) {
        float4 v = ((const float4*)src)[i];
        uint2 w;
        w.x = h2u(__floats2half2_rn(v.x, v.y));
        w.y = h2u(__floats2half2_rn(v.z, v.w));
        ((uint2*)dst)[i] = w;
    }
}

// ---------------------------------------------------------------------------
// fp16 tensor-core GEMM, 3-stage cp.async pipeline, ONE sync per k-tile.
// ---------------------------------------------------------------------------
#define APIT 40    // As pitch in halves (80 B)
#define BPIT 136   // Bs pitch in halves (272 B)
#define AS_BYTES (128 * APIT * 2)
#define BS_BYTES (32 * BPIT * 2)
#define GEMM_SMEM (3 * (AS_BYTES + BS_BYTES))

template <typename OutT>
__device__ __forceinline__ void gemm_f16_body(const __half* __restrict__ A,
                                              const __half* __restrict__ W,
                                              const float* __restrict__ bias,
                                              OutT* __restrict__ out) {
    extern __shared__ __align__(16) __half gsh[];
    __half* As = gsh;                          // [3][128][APIT]
    __half* Bs = gsh + 3 * 128 * APIT;         // [3][32][BPIT]
    const int tid  = threadIdx.x;
    const int warp = tid >> 5;
    const int lane = tid & 31;
    const int g    = lane >> 2;
    const int tig  = lane & 3;
    const int mf   = lane >> 3;
    const int rr   = lane & 7;
    const int wm   = warp >> 2;
    const int wn   = warp & 3;
    const int m0 = blockIdx.x * 128, n0 = blockIdx.y * 128;

    const uint32_t as_u = (uint32_t)__cvta_generic_to_shared(As);
    const uint32_t bs_u = (uint32_t)__cvta_generic_to_shared(Bs);

    auto issue_tiles = [&](int k0, int buf) {
#pragma unroll
        for (int p = 0; p < 2; p++) {
            int li = p * 256 + tid;        // 128 rows x 4 chunks
            int r  = li >> 2;
            int c  = (li & 3) * 8;
            cp16(as_u + buf * AS_BYTES + (r * APIT + c) * 2,
                 A + (size_t)(m0 + r) * Cc + k0 + c);
        }
#pragma unroll
        for (int p = 0; p < 2; p++) {
            int li = p * 256 + tid;        // 32 rows x 16 chunks
            int r  = li >> 4;
            int c  = (li & 15) * 8;
            cp16(bs_u + buf * BS_BYTES + (r * BPIT + c) * 2,
                 W + (size_t)(k0 + r) * Cc + n0 + c);
        }
    };

    float acc[4][4][4] = {};

    issue_tiles(0, 0);  cp_commit();
    issue_tiles(32, 1); cp_commit();

    for (int kt = 0; kt < 16; kt++) {
        const int cur = kt % 3;
        cp_wait<1>();
        __syncthreads();
        if (kt + 2 < 16) issue_tiles((kt + 2) * 32, (kt + 2) % 3);
        cp_commit();

        const uint32_t abase = as_u + cur * AS_BYTES;
        const uint32_t bbase = bs_u + cur * BS_BYTES;
#pragma unroll
        for (int kc = 0; kc < 2; kc++) {
            uint32_t af[4][4];
#pragma unroll
            for (int mt = 0; mt < 4; mt++) {
                int row = wm * 64 + mt * 16 + rr + (mf & 1) * 8;
                int col = kc * 16 + (mf >> 1) * 8;
                ldsm_x4(af[mt], abase + (row * APIT + col) * 2);
            }
            uint32_t bf[2][4];
#pragma unroll
            for (int p = 0; p < 2; p++) {
                int krow = kc * 16 + (mf & 1) * 8 + rr;
                int ncol = wn * 32 + (2 * p + (mf >> 1)) * 8;
                ldsm_x4_t(bf[p], bbase + (krow * BPIT + ncol) * 2);
            }
#pragma unroll
            for (int mt = 0; mt < 4; mt++)
#pragma unroll
                for (int p = 0; p < 2; p++) {
                    mma_f16(acc[mt][2 * p],     af[mt], bf[p][0], bf[p][1]);
                    mma_f16(acc[mt][2 * p + 1], af[mt], bf[p][2], bf[p][3]);
                }
        }
    }

    // epilogue: add bias, store
#pragma unroll
    for (int mt = 0; mt < 4; mt++) {
        int r0g = m0 + wm * 64 + mt * 16 + g;
        int r1g = r0g + 8;
#pragma unroll
        for (int nt = 0; nt < 4; nt++) {
            int n = n0 + wn * 32 + nt * 8 + 2 * tig;
            float b0 = bias[n], b1 = bias[n + 1];
            float v00 = acc[mt][nt][0] + b0, v01 = acc[mt][nt][1] + b1;
            float v10 = acc[mt][nt][2] + b0, v11 = acc[mt][nt][3] + b1;
            if constexpr (sizeof(OutT) == 2) {
                *(uint32_t*)&out[(size_t)r0g * Cc + n] = h2u(__floats2half2_rn(v00, v01));
                *(uint32_t*)&out[(size_t)r1g * Cc + n] = h2u(__floats2half2_rn(v10, v11));
            } else {
                float2 w0 = {v00, v01};
                float2 w1 = {v10, v11};
                *(float2*)&out[(size_t)r0g * Cc + n] = w0;
                *(float2*)&out[(size_t)r1g * Cc + n] = w1;
            }
        }
    }
}

__global__ __launch_bounds__(256, 2)
void gemm_qkv(const float* __restrict__ bq, const float* __restrict__ bk,
              const float* __restrict__ bv) {
    const __half* W; const float* bi; __half* out;
    if (blockIdx.z == 0)      { W = g_wh[0]; bi = bq; out = g_qh; }
    else if (blockIdx.z == 1) { W = g_wh[1]; bi = bk; out = g_kh; }
    else                      { W = g_wh[2]; bi = bv; out = g_vh; }
    gemm_f16_body<__half>(g_xh, W, bi, out);
}

__global__ __launch_bounds__(256, 2)
void gemm_out(const float* __restrict__ bo, float* __restrict__ out) {
    gemm_f16_body<float>(g_ctxh, g_wh[3], bo, out);
}

// ---------------------------------------------------------------------------
// fp16 tensor-core flash attention: 3-stage cp.async, 2 CTAs/SM,
// half2-ex2 softmax, row sums via ones-MMA (no sum shfl, no f32 exp).
// ---------------------------------------------------------------------------
#define QP 72
#define KS_BYTES (64 * QP * 2)
#define ATTN_SMEM ((128 * QP + 6 * 64 * QP) * 2 + Tt * 4)

__global__ __launch_bounds__(256, 2)
void attn_kernel(const int* __restrict__ mask, const int* __restrict__ cdrs) {
    extern __shared__ __align__(16) __half sh[];
    __half* qs = sh;                       // [128][QP]
    __half* ks = sh + 128 * QP;            // [3][64][QP]
    __half* vs = ks + 3 * 64 * QP;         // [3][64][QP]
    float*  kneg = (float*)(vs + 3 * 64 * QP);   // [2048]

    const int q0   = blockIdx.x * 128;
    const int h    = blockIdx.y;
    const int b    = blockIdx.z;
    const int tid  = threadIdx.x;
    const int warp = tid >> 5;
    const int lane = tid & 31;
    const int g    = lane >> 2;
    const int tig  = lane & 3;
    const int mf   = lane >> 3;
    const int rr   = lane & 7;

    const bool iscdr = (h < CDRH) && (g_allm[b] == 0);

    const uint32_t qs_u = (uint32_t)__cvta_generic_to_shared(qs);
    const uint32_t ks_u = (uint32_t)__cvta_generic_to_shared(ks);
    const uint32_t vs_u = (uint32_t)__cvta_generic_to_shared(vs);

    const __half* kall = g_kh + (size_t)b * Tt * Cc + h * Dd;
    const __half* vall = g_vh + (size_t)b * Tt * Cc + h * Dd;

    auto issue_kv = [&](int kt, int buf) {
        const __half* kbase = kall + (size_t)kt * 64 * Cc;
        const __half* vbase = vall + (size_t)kt * 64 * Cc;
#pragma unroll
        for (int p = 0; p < 2; p++) {
            int li = p * 256 + tid;       // 64 rows x 8 chunks
            int r  = li >> 3;
            int c  = (li & 7) * 8;
            cp16(ks_u + buf * KS_BYTES + (r * QP + c) * 2, kbase + (size_t)r * Cc + c);
        }
#pragma unroll
        for (int p = 0; p < 2; p++) {
            int li = p * 256 + tid;
            int r  = li >> 3;
            int c  = (li & 7) * 8;
            cp16(vs_u + buf * KS_BYTES + (r * QP + c) * 2, vbase + (size_t)r * Cc + c);
        }
    };

    // ---- prologue ----
    const __half* qbase = g_qh + (size_t)(b * Tt + q0) * Cc + h * Dd;
#pragma unroll
    for (int p = 0; p < 4; p++) {
        int li = p * 256 + tid;
        int r  = li >> 3;
        int c  = (li & 7) * 8;
        cp16(qs_u + (r * QP + c) * 2, qbase + (size_t)r * Cc + c);
    }
    cp_commit();
    issue_kv(0, 0); cp_commit();
    issue_kv(1, 1); cp_commit();

#pragma unroll
    for (int p = 0; p < Tt / 256; p++) {
        int kg = p * 256 + tid;
        bool bad = (mask[b * Tt + kg] == 0) ||
                   (iscdr && (cdrs[b * Tt + kg] == 0));
        kneg[kg] = bad ? NEG_INF : 0.f;
    }

    cp_wait<2>();
    __syncthreads();

    // ---- hoist Q A-fragments ----
    uint32_t qa[4][4];
#pragma unroll
    for (int kc = 0; kc < 4; kc++) {
        int row = warp * 16 + rr + (mf & 1) * 8;
        int col = kc * 16 + (mf >> 1) * 8;
        ldsm_x4(qa[kc], qs_u + (row * QP + col) * 2);
    }

    float m_run[2] = {M_INIT, M_INIT};
    float l_run[2] = {0.f, 0.f};
    float o[8][4] = {};

    for (int kt = 0; kt < Tt / 64; kt++) {
        const int cur = kt % 3;
        cp_wait<1>();
        __syncthreads();
        if (kt + 2 < Tt / 64) issue_kv(kt + 2, (kt + 2) % 3);
        cp_commit();

        const uint32_t kb = ks_u + cur * KS_BYTES;
        const uint32_t vb = vs_u + cur * KS_BYTES;
        const float* kn = kneg + kt * 64;

        // ---- S = Q K^T ----
        float s[8][4] = {};
#pragma unroll
        for (int kc = 0; kc < 4; kc++) {
#pragma unroll
            for (int p = 0; p < 4; p++) {
                int key = (2 * p + (mf >> 1)) * 8 + rr;
                int d   = kc * 16 + (mf & 1) * 8;
                uint32_t bk[4];
                ldsm_x4(bk, kb + (key * QP + d) * 2);
                mma_f16(s[2 * p],     qa[kc], bk[0], bk[1]);
                mma_f16(s[2 * p + 1], qa[kc], bk[2], bk[3]);
            }
        }

        // ---- scale (log2 domain) + key-mask bias ----
#pragma unroll
        for (int nt = 0; nt < 8; nt++) {
            float k0b = kn[nt * 8 + 2 * tig];
            float k1b = kn[nt * 8 + 2 * tig + 1];
            s[nt][0] = s[nt][0] * SCALE2 + k0b;
            s[nt][1] = s[nt][1] * SCALE2 + k1b;
            s[nt][2] = s[nt][2] * SCALE2 + k0b;
            s[nt][3] = s[nt][3] * SCALE2 + k1b;
        }

        // ---- row max (quad reduce) ----
        float mt0 = NEG_INF, mt1 = NEG_INF;
#pragma unroll
        for (int nt = 0; nt < 8; nt++) {
            mt0 = fmaxf(mt0, fmaxf(s[nt][0], s[nt][1]));
            mt1 = fmaxf(mt1, fmaxf(s[nt][2], s[nt][3]));
        }
#pragma unroll
        for (int off = 1; off < 4; off <<= 1) {
            mt0 = fmaxf(mt0, __shfl_xor_sync(0xffffffffu, mt0, off));
            mt1 = fmaxf(mt1, __shfl_xor_sync(0xffffffffu, mt1, off));
        }
        float mn0 = fmaxf(m_run[0], mt0);   // finite (>= -1e30)
        float mn1 = fmaxf(m_run[1], mt1);
        float alpha0 = ex2(m_run[0] - mn0);
        float alpha1 = ex2(m_run[1] - mn1);
        m_run[0] = mn0;
        m_run[1] = mn1;

        // rescale O before PV accumulation
#pragma unroll
        for (int nt = 0; nt < 8; nt++) {
            o[nt][0] *= alpha0; o[nt][1] *= alpha0;
            o[nt][2] *= alpha1; o[nt][3] *= alpha1;
        }

        // ---- P = exp2(s - m) in half2; row sums via ones-MMA; O += P@V ----
        float sc[4] = {0.f, 0.f, 0.f, 0.f};   // row-sum accumulator (C layout)
#pragma unroll
        for (int kc = 0; kc < 4; kc++) {
            const int e = 2 * kc, od = 2 * kc + 1;
            uint32_t pa[4];
            pa[0] = ex2h2(h2u(__floats2half2_rn(s[e][0] - mn0,  s[e][1] - mn0)));
            pa[1] = ex2h2(h2u(__floats2half2_rn(s[e][2] - mn1,  s[e][3] - mn1)));
            pa[2] = ex2h2(h2u(__floats2half2_rn(s[od][0] - mn0, s[od][1] - mn0)));
            pa[3] = ex2h2(h2u(__floats2half2_rn(s[od][2] - mn1, s[od][3] - mn1)));

            // row sums: B = ones -> sc[0]=sum(row r0), sc[2]=sum(row r1)
            mma_f16(sc, pa, ONES_H2, ONES_H2);

#pragma unroll
            for (int p = 0; p < 4; p++) {
                int key = kc * 16 + (mf & 1) * 8 + rr;
                int d   = (2 * p + (mf >> 1)) * 8;
                uint32_t bv[4];
                ldsm_x4_t(bv, vb + (key * QP + d) * 2);
                mma_f16(o[2 * p],     pa, bv[0], bv[1]);
                mma_f16(o[2 * p + 1], pa, bv[2], bv[3]);
            }
        }
        l_run[0] = l_run[0] * alpha0 + sc[0];
        l_run[1] = l_run[1] * alpha1 + sc[2];
    }

    // ---- epilogue: normalize, write ctx (half) ----
    const int r0 = warp * 16 + g;
    const int r1 = r0 + 8;
    float inv0 = 1.f / l_run[0];
    float inv1 = 1.f / l_run[1];
    __half* ob0 = g_ctxh + (size_t)(b * Tt + q0 + r0) * Cc + h * Dd;
    __half* ob1 = g_ctxh + (size_t)(b * Tt + q0 + r1) * Cc + h * Dd;
#pragma unroll
    for (int nt = 0; nt < 8; nt++) {
        *(uint32_t*)&ob0[nt * 8 + 2 * tig] =
            h2u(__floats2half2_rn(o[nt][0] * inv0, o[nt][1] * inv0));
        *(uint32_t*)&ob1[nt * 8 + 2 * tig] =
            h2u(__floats2half2_rn(o[nt][2] * inv1, o[nt][3] * inv1));
    }
}

// ---------------------------------------------------------------------------
// Launch
// ---------------------------------------------------------------------------
extern "C" void kernel_launch(void* const* d_in, const int* in_sizes, int n_in,
                              void* d_out, int out_size) {
    const float* x    = (const float*)d_in[0];
    const int*   mask = (const int*)d_in[1];
    const int*   cdrs = (const int*)d_in[2];
    const float* Wq   = (const float*)d_in[3];
    const float* bq   = (const float*)d_in[4];
    const float* Wk   = (const float*)d_in[5];
    const float* bk   = (const float*)d_in[6];
    const float* Wv   = (const float*)d_in[7];
    const float* bv   = (const float*)d_in[8];
    const float* Wo   = (const float*)d_in[9];
    const float* bo   = (const float*)d_in[10];
    float* out = (float*)d_out;

    dim3 gprep((Bb * Tt * Cc / 4 + 255) / 256, 6);
    prep_kernel<<<gprep, 256>>>(x, Wq, Wk, Wv, Wo, cdrs);

    cudaFuncSetAttribute(gemm_qkv, cudaFuncAttributeMaxDynamicSharedMemorySize,
                         GEMM_SMEM);
    cudaFuncSetAttribute(gemm_out, cudaFuncAttributeMaxDynamicSharedMemorySize,
                         GEMM_SMEM);

    dim3 gqkv(Bb * Tt / 128, Cc / 128, 3);
    gemm_qkv<<<gqkv, 256, GEMM_SMEM>>>(bq, bk, bv);

    cudaFuncSetAttribute(attn_kernel, cudaFuncAttributeMaxDynamicSharedMemorySize,
                         ATTN_SMEM);
    dim3 gatt(Tt / 128, Hh, Bb);
    attn_kernel<<<gatt, 256, ATTN_SMEM>>>(mask, cdrs);

    dim3 gout(Bb * Tt / 128, Cc / 128, 1);
    gemm_out<<<gout, 256, GEMM_SMEM>>>(bo, out);
}